// round 1
// baseline (speedup 1.0000x reference)
#include <cuda_runtime.h>

#define Bt  2
#define Ss  2048
#define Dd  1024
#define Hh  16
#define HDd 64
#define Tt  (Bt * Ss)      // 4096 tokens
#define DFF (4 * Dd)       // 4096

// ---------------- scratch (device globals; no allocation allowed) ----------------
__device__ float g_q[Tt * Dd];
__device__ float g_k[Tt * Dd];
__device__ float g_v[Tt * Dd];
__device__ float g_mid[Tt * Dd];
__device__ float g_proj[Tt * Dd];
__device__ float g_x1[Tt * Dd];
__device__ float g_up[(size_t)Tt * DFF];

// ---------------- SGEMM: C[M,N] = A[M,K] @ B[K,N] + bias, optional ReLU ----------
// 128x128 tile, K-chunk 16, 256 threads, 8x8 per-thread microtile.
template <int RELU>
__global__ __launch_bounds__(256, 2)
void sgemm_bias(const float* __restrict__ A, const float* __restrict__ Bm,
                const float* __restrict__ bias, float* __restrict__ C,
                int M, int N, int K)
{
    __shared__ float As[16][128];
    __shared__ float Bs[16][128];

    const int tid = threadIdx.x;
    const int tx = tid & 15, ty = tid >> 4;
    const int m0 = blockIdx.y << 7, n0 = blockIdx.x << 7;

    float acc[8][8];
#pragma unroll
    for (int i = 0; i < 8; i++)
#pragma unroll
        for (int j = 0; j < 8; j++) acc[i][j] = 0.f;

    for (int k0 = 0; k0 < K; k0 += 16) {
        // A tile: 128 rows x 16 k. Each thread: row tid>>1, 8 consecutive k.
        {
            const int m  = tid >> 1;
            const int kk = (tid & 1) * 8;
            const float* ap = &A[(size_t)(m0 + m) * K + k0 + kk];
            float4 a0 = *(const float4*)ap;
            float4 a1 = *(const float4*)(ap + 4);
            As[kk + 0][m] = a0.x; As[kk + 1][m] = a0.y;
            As[kk + 2][m] = a0.z; As[kk + 3][m] = a0.w;
            As[kk + 4][m] = a1.x; As[kk + 5][m] = a1.y;
            As[kk + 6][m] = a1.z; As[kk + 7][m] = a1.w;
        }
        // B tile: 16 k x 128 n. Each thread: k = tid>>4, 8 consecutive n.
        {
            const int kk = tid >> 4;
            const int n  = (tid & 15) * 8;
            const float* bp = &Bm[(size_t)(k0 + kk) * N + n0 + n];
            *(float4*)&Bs[kk][n]     = *(const float4*)bp;
            *(float4*)&Bs[kk][n + 4] = *(const float4*)(bp + 4);
        }
        __syncthreads();

#pragma unroll
        for (int kk = 0; kk < 16; kk++) {
            float a[8], b[8];
            *(float4*)&a[0] = *(const float4*)&As[kk][ty * 8];
            *(float4*)&a[4] = *(const float4*)&As[kk][ty * 8 + 4];
            *(float4*)&b[0] = *(const float4*)&Bs[kk][tx * 8];
            *(float4*)&b[4] = *(const float4*)&Bs[kk][tx * 8 + 4];
#pragma unroll
            for (int i = 0; i < 8; i++)
#pragma unroll
                for (int j = 0; j < 8; j++)
                    acc[i][j] += a[i] * b[j];
        }
        __syncthreads();
    }

#pragma unroll
    for (int i = 0; i < 8; i++) {
        float* cp = &C[(size_t)(m0 + ty * 8 + i) * N + n0 + tx * 8];
#pragma unroll
        for (int j = 0; j < 8; j++) {
            float v = acc[i][j] + bias[n0 + tx * 8 + j];
            if (RELU) v = fmaxf(v, 0.f);
            cp[j] = v;
        }
    }
}

// ---------------- causal flash attention ----------------
// grid: (S/64 query blocks, B*H). block: 256 threads (16x16).
// BM=64 queries, BN=32 keys per tile, Hd=64. Online softmax, stats kept
// redundantly in all 16 lanes of each half-warp via butterfly shuffles.
__global__ __launch_bounds__(256)
void attn_kernel(const float* __restrict__ Q, const float* __restrict__ Kg,
                 const float* __restrict__ Vg, float* __restrict__ Og)
{
    __shared__ float Qs[64][65];
    __shared__ float Ks[32][65];
    __shared__ float Vs[32][65];
    __shared__ float Ps[64][33];

    const int tid = threadIdx.x;
    const int tx = tid & 15, ty = tid >> 4;
    const int qb = blockIdx.x;
    const int bh = blockIdx.y;
    const int b = bh >> 4, h = bh & 15;

    const float* Qb = Q  + (size_t)b * Ss * Dd + h * HDd;
    const float* Kb = Kg + (size_t)b * Ss * Dd + h * HDd;
    const float* Vb = Vg + (size_t)b * Ss * Dd + h * HDd;

    // load Q tile (pre-scaled by 1/sqrt(64))
    for (int i = tid; i < 64 * 64; i += 256) {
        int r = i >> 6, d = i & 63;
        Qs[r][d] = Qb[(size_t)(qb * 64 + r) * Dd + d] * 0.125f;
    }

    float m_i[4], l_i[4], O[4][4];
#pragma unroll
    for (int i = 0; i < 4; i++) {
        m_i[i] = -1e30f; l_i[i] = 0.f;
#pragma unroll
        for (int j = 0; j < 4; j++) O[i][j] = 0.f;
    }

    const int nkt = qb * 2 + 2;   // key tiles up through the diagonal
    for (int kt = 0; kt < nkt; kt++) {
        __syncthreads();   // protect Ks/Vs from readers of previous iteration
        for (int i = tid; i < 32 * 64; i += 256) {
            int r = i >> 6, d = i & 63;
            Ks[r][d] = Kb[(size_t)(kt * 32 + r) * Dd + d];
            Vs[r][d] = Vb[(size_t)(kt * 32 + r) * Dd + d];
        }
        __syncthreads();

        // scores: rows ty*4..+3, cols tx*2..+1
        float s[4][2];
#pragma unroll
        for (int i = 0; i < 4; i++) { s[i][0] = 0.f; s[i][1] = 0.f; }
#pragma unroll 8
        for (int kk = 0; kk < 64; kk++) {
            float a0 = Qs[ty * 4 + 0][kk];
            float a1 = Qs[ty * 4 + 1][kk];
            float a2 = Qs[ty * 4 + 2][kk];
            float a3 = Qs[ty * 4 + 3][kk];
            float b0 = Ks[tx * 2 + 0][kk];
            float b1 = Ks[tx * 2 + 1][kk];
            s[0][0] += a0 * b0; s[0][1] += a0 * b1;
            s[1][0] += a1 * b0; s[1][1] += a1 * b1;
            s[2][0] += a2 * b0; s[2][1] += a2 * b1;
            s[3][0] += a3 * b0; s[3][1] += a3 * b1;
        }

        // causal mask + online softmax (reductions within 16-lane half-warp)
#pragma unroll
        for (int i = 0; i < 4; i++) {
            const int qg = qb * 64 + ty * 4 + i;
#pragma unroll
            for (int j = 0; j < 2; j++) {
                const int kg = kt * 32 + tx * 2 + j;
                if (kg > qg) s[i][j] = -1e30f;
            }
            float v = fmaxf(s[i][0], s[i][1]);
#pragma unroll
            for (int o = 1; o < 16; o <<= 1)
                v = fmaxf(v, __shfl_xor_sync(0xffffffffu, v, o, 16));
            const float mnew = fmaxf(m_i[i], v);
            const float fac  = __expf(m_i[i] - mnew);
            const float p0 = __expf(s[i][0] - mnew);
            const float p1 = __expf(s[i][1] - mnew);
            Ps[ty * 4 + i][tx * 2 + 0] = p0;
            Ps[ty * 4 + i][tx * 2 + 1] = p1;
            float rs = p0 + p1;
#pragma unroll
            for (int o = 1; o < 16; o <<= 1)
                rs += __shfl_xor_sync(0xffffffffu, rs, o, 16);
            l_i[i] = l_i[i] * fac + rs;
            m_i[i] = mnew;
#pragma unroll
            for (int j = 0; j < 4; j++) O[i][j] *= fac;
        }
        __syncwarp();  // Ps rows are produced & consumed within one warp

        // O += P @ V : dims tx*4..+3
#pragma unroll 4
        for (int k = 0; k < 32; k++) {
            float pr0 = Ps[ty * 4 + 0][k];
            float pr1 = Ps[ty * 4 + 1][k];
            float pr2 = Ps[ty * 4 + 2][k];
            float pr3 = Ps[ty * 4 + 3][k];
            float v0 = Vs[k][tx * 4 + 0];
            float v1 = Vs[k][tx * 4 + 1];
            float v2 = Vs[k][tx * 4 + 2];
            float v3 = Vs[k][tx * 4 + 3];
            O[0][0] += pr0 * v0; O[0][1] += pr0 * v1; O[0][2] += pr0 * v2; O[0][3] += pr0 * v3;
            O[1][0] += pr1 * v0; O[1][1] += pr1 * v1; O[1][2] += pr1 * v2; O[1][3] += pr1 * v3;
            O[2][0] += pr2 * v0; O[2][1] += pr2 * v1; O[2][2] += pr2 * v2; O[2][3] += pr2 * v3;
            O[3][0] += pr3 * v0; O[3][1] += pr3 * v1; O[3][2] += pr3 * v2; O[3][3] += pr3 * v3;
        }
    }

#pragma unroll
    for (int i = 0; i < 4; i++) {
        const float inv = 1.f / l_i[i];
        float* op = Og + (size_t)(b * Ss + qb * 64 + ty * 4 + i) * Dd + h * HDd + tx * 4;
#pragma unroll
        for (int j = 0; j < 4; j++) op[j] = O[i][j] * inv;
    }
}

// ---------------- residual add + LayerNorm (one block per token) -----------------
__global__ __launch_bounds__(256)
void add_ln_kernel(const float* __restrict__ a, const float* __restrict__ r,
                   const float* __restrict__ gamma, const float* __restrict__ beta,
                   float* __restrict__ out)
{
    const int t = blockIdx.x;
    const int tid = threadIdx.x;
    __shared__ float buf[Dd];
    __shared__ float red[20];

    float s = 0.f, sq = 0.f;
    for (int i = tid; i < Dd; i += 256) {
        float v = a[(size_t)t * Dd + i] + r[(size_t)t * Dd + i];
        buf[i] = v;
        s += v; sq += v * v;
    }
#pragma unroll
    for (int o = 16; o; o >>= 1) {
        s  += __shfl_xor_sync(0xffffffffu, s, o);
        sq += __shfl_xor_sync(0xffffffffu, sq, o);
    }
    if ((tid & 31) == 0) { red[tid >> 5] = s; red[8 + (tid >> 5)] = sq; }
    __syncthreads();
    if (tid == 0) {
        float ts = 0.f, tq = 0.f;
        for (int i = 0; i < 8; i++) { ts += red[i]; tq += red[8 + i]; }
        const float mu  = ts * (1.0f / Dd);
        const float var = tq * (1.0f / Dd) - mu * mu;
        red[16] = mu;
        red[17] = rsqrtf(var + 1e-6f);
    }
    __syncthreads();
    const float mu = red[16], rstd = red[17];
    for (int i = tid; i < Dd; i += 256)
        out[(size_t)t * Dd + i] = (buf[i] - mu) * rstd * gamma[i] + beta[i];
}

// ---------------- launch ----------------
extern "C" void kernel_launch(void* const* d_in, const int* in_sizes, int n_in,
                              void* d_out, int out_size)
{
    const float* x   = (const float*)d_in[0];
    const float* Wq  = (const float*)d_in[1];
    const float* bq  = (const float*)d_in[2];
    const float* Wk  = (const float*)d_in[3];
    const float* bk  = (const float*)d_in[4];
    const float* Wv  = (const float*)d_in[5];
    const float* bv  = (const float*)d_in[6];
    const float* Wo  = (const float*)d_in[7];
    const float* bo  = (const float*)d_in[8];
    const float* g1  = (const float*)d_in[9];
    const float* b1  = (const float*)d_in[10];
    const float* Wup = (const float*)d_in[11];
    const float* bup = (const float*)d_in[12];
    const float* Wdn = (const float*)d_in[13];
    const float* bdn = (const float*)d_in[14];
    const float* g2  = (const float*)d_in[15];
    const float* b2  = (const float*)d_in[16];
    float* out = (float*)d_out;

    float *q, *k, *v, *mid, *proj, *x1, *up;
    cudaGetSymbolAddress((void**)&q,    g_q);
    cudaGetSymbolAddress((void**)&k,    g_k);
    cudaGetSymbolAddress((void**)&v,    g_v);
    cudaGetSymbolAddress((void**)&mid,  g_mid);
    cudaGetSymbolAddress((void**)&proj, g_proj);
    cudaGetSymbolAddress((void**)&x1,   g_x1);
    cudaGetSymbolAddress((void**)&up,   g_up);

    const dim3 blk(256);
    const dim3 gridD(Dd / 128, Tt / 128);     // N=1024 GEMMs
    const dim3 gridF(DFF / 128, Tt / 128);    // N=4096 GEMM

    // QKV projections
    sgemm_bias<0><<<gridD, blk>>>(x, Wq, bq, q, Tt, Dd, Dd);
    sgemm_bias<0><<<gridD, blk>>>(x, Wk, bk, k, Tt, Dd, Dd);
    sgemm_bias<0><<<gridD, blk>>>(x, Wv, bv, v, Tt, Dd, Dd);

    // causal attention
    attn_kernel<<<dim3(Ss / 64, Bt * Hh), blk>>>(q, k, v, mid);

    // output projection + residual LN1
    sgemm_bias<0><<<gridD, blk>>>(mid, Wo, bo, proj, Tt, Dd, Dd);
    add_ln_kernel<<<Tt, blk>>>(x, proj, g1, b1, x1);

    // FFN
    sgemm_bias<1><<<gridF, blk>>>(x1, Wup, bup, up, Tt, DFF, Dd);
    sgemm_bias<0><<<gridD, blk>>>(up, Wdn, bdn, proj, Tt, Dd, DFF);
    add_ln_kernel<<<Tt, blk>>>(x1, proj, g2, b2, out);
}

// round 3
// speedup vs baseline: 2.0630x; 2.0630x over previous
#include <cuda_runtime.h>
#include <cstdint>

#define Bt  2
#define Ss  2048
#define Dd  1024
#define Hh  16
#define HDd 64
#define Tt  (Bt * Ss)      // 4096 tokens
#define DFF (4 * Dd)       // 4096

// ---------------- scratch (device globals; no allocation allowed) ----------------
__device__ float g_q[Tt * Dd];
__device__ float g_k[Tt * Dd];
__device__ float g_v[Tt * Dd];
__device__ float g_mid[Tt * Dd];
__device__ float g_proj[Tt * Dd];
__device__ float g_x1[Tt * Dd];
__device__ float g_up[(size_t)Tt * DFF];

// ---------------- helpers ----------------
__device__ __forceinline__ uint32_t f2tf32(float f) {
    uint32_t o;
    asm("cvt.rna.tf32.f32 %0, %1;" : "=r"(o) : "f"(f));
    return o;
}
__device__ __forceinline__ void mma_tf32(float* d, const uint32_t* a, const uint32_t* b) {
    asm volatile(
        "mma.sync.aligned.m16n8k8.row.col.f32.tf32.tf32.f32 "
        "{%0,%1,%2,%3}, {%4,%5,%6,%7}, {%8,%9}, {%0,%1,%2,%3};"
        : "+f"(d[0]), "+f"(d[1]), "+f"(d[2]), "+f"(d[3])
        : "r"(a[0]), "r"(a[1]), "r"(a[2]), "r"(a[3]), "r"(b[0]), "r"(b[1]));
}

// ---------------- TF32 tensor-core GEMM ----------------
// C[M,N] = A[M,K] @ W[K,N] + bias (+ ReLU).
// Block tile 128x128, K-chunk 32, 256 threads = 8 warps in 2(m) x 4(n) grid.
// Each warp: 64x32 output = 4x4 m16n8k8 tiles.
template <int RELU>
__global__ __launch_bounds__(256)
void gemm_tc(const float* __restrict__ A, const float* __restrict__ W,
             const float* __restrict__ bias, float* __restrict__ C,
             int M, int N, int K)
{
    __shared__ float As[128][36];   // m-major, tf32-rounded
    __shared__ float Bs[32][136];   // k-major, tf32-rounded

    const int tid  = threadIdx.x;
    const int lane = tid & 31;
    const int wid  = tid >> 5;
    const int wm   = (wid & 1) * 64;   // warp m offset
    const int wn   = (wid >> 1) * 32;  // warp n offset
    const int m0   = blockIdx.y << 7;
    const int n0   = blockIdx.x << 7;

    const int row = lane >> 2;   // 0..7
    const int col = lane & 3;    // 0..3

    float acc[4][4][4];
#pragma unroll
    for (int mi = 0; mi < 4; mi++)
#pragma unroll
        for (int ni = 0; ni < 4; ni++)
#pragma unroll
            for (int j = 0; j < 4; j++) acc[mi][ni][j] = 0.f;

    // fill indices
    const int fa_r = tid >> 3;         // 0..31 (A rows, step 32)
    const int fa_q = (tid & 7) * 4;    // A k-cols
    const int fb_r = tid >> 5;         // 0..7  (B k-rows, step 8)
    const int fb_c = (tid & 31) * 4;   // B n-cols

    for (int k0 = 0; k0 < K; k0 += 32) {
        // A tile: 128 x 32
#pragma unroll
        for (int rr = fa_r; rr < 128; rr += 32) {
            float4 v = *(const float4*)&A[(size_t)(m0 + rr) * K + k0 + fa_q];
            As[rr][fa_q + 0] = __uint_as_float(f2tf32(v.x));
            As[rr][fa_q + 1] = __uint_as_float(f2tf32(v.y));
            As[rr][fa_q + 2] = __uint_as_float(f2tf32(v.z));
            As[rr][fa_q + 3] = __uint_as_float(f2tf32(v.w));
        }
        // B tile: 32 x 128 straight from W[K,N]
#pragma unroll
        for (int rr = fb_r; rr < 32; rr += 8) {
            float4 v = *(const float4*)&W[(size_t)(k0 + rr) * N + n0 + fb_c];
            Bs[rr][fb_c + 0] = __uint_as_float(f2tf32(v.x));
            Bs[rr][fb_c + 1] = __uint_as_float(f2tf32(v.y));
            Bs[rr][fb_c + 2] = __uint_as_float(f2tf32(v.z));
            Bs[rr][fb_c + 3] = __uint_as_float(f2tf32(v.w));
        }
        __syncthreads();

#pragma unroll
        for (int ks = 0; ks < 4; ks++) {
            const int kb = ks * 8;
            uint32_t a[4][4], b[4][2];
#pragma unroll
            for (int mi = 0; mi < 4; mi++) {
                const int r = wm + mi * 16 + row;
                a[mi][0] = __float_as_uint(As[r][kb + col]);
                a[mi][1] = __float_as_uint(As[r + 8][kb + col]);
                a[mi][2] = __float_as_uint(As[r][kb + col + 4]);
                a[mi][3] = __float_as_uint(As[r + 8][kb + col + 4]);
            }
#pragma unroll
            for (int ni = 0; ni < 4; ni++) {
                const int c = wn + ni * 8 + row;
                b[ni][0] = __float_as_uint(Bs[kb + col][c]);
                b[ni][1] = __float_as_uint(Bs[kb + col + 4][c]);
            }
#pragma unroll
            for (int mi = 0; mi < 4; mi++)
#pragma unroll
                for (int ni = 0; ni < 4; ni++)
                    mma_tf32(acc[mi][ni], a[mi], b[ni]);
        }
        __syncthreads();
    }

    // epilogue: direct float2 stores with bias (+ReLU)
#pragma unroll
    for (int mi = 0; mi < 4; mi++) {
        const int r0 = m0 + wm + mi * 16 + row;
#pragma unroll
        for (int ni = 0; ni < 4; ni++) {
            const int c0 = n0 + wn + ni * 8 + 2 * col;
            const float b0 = bias[c0], b1 = bias[c0 + 1];
            float2 v0, v1;
            v0.x = acc[mi][ni][0] + b0; v0.y = acc[mi][ni][1] + b1;
            v1.x = acc[mi][ni][2] + b0; v1.y = acc[mi][ni][3] + b1;
            if (RELU) {
                v0.x = fmaxf(v0.x, 0.f); v0.y = fmaxf(v0.y, 0.f);
                v1.x = fmaxf(v1.x, 0.f); v1.y = fmaxf(v1.y, 0.f);
            }
            *(float2*)&C[(size_t)r0 * N + c0]       = v0;
            *(float2*)&C[(size_t)(r0 + 8) * N + c0] = v1;
        }
    }
}

// ---------------- causal flash attention (unchanged) ----------------
__global__ __launch_bounds__(256)
void attn_kernel(const float* __restrict__ Q, const float* __restrict__ Kg,
                 const float* __restrict__ Vg, float* __restrict__ Og)
{
    __shared__ float Qs[64][65];
    __shared__ float Ks[32][65];
    __shared__ float Vs[32][65];
    __shared__ float Ps[64][33];

    const int tid = threadIdx.x;
    const int tx = tid & 15, ty = tid >> 4;
    const int qb = blockIdx.x;
    const int bh = blockIdx.y;
    const int b = bh >> 4, h = bh & 15;

    const float* Qb = Q  + (size_t)b * Ss * Dd + h * HDd;
    const float* Kb = Kg + (size_t)b * Ss * Dd + h * HDd;
    const float* Vb = Vg + (size_t)b * Ss * Dd + h * HDd;

    for (int i = tid; i < 64 * 64; i += 256) {
        int r = i >> 6, d = i & 63;
        Qs[r][d] = Qb[(size_t)(qb * 64 + r) * Dd + d] * 0.125f;
    }

    float m_i[4], l_i[4], O[4][4];
#pragma unroll
    for (int i = 0; i < 4; i++) {
        m_i[i] = -1e30f; l_i[i] = 0.f;
#pragma unroll
        for (int j = 0; j < 4; j++) O[i][j] = 0.f;
    }

    const int nkt = qb * 2 + 2;
    for (int kt = 0; kt < nkt; kt++) {
        __syncthreads();
        for (int i = tid; i < 32 * 64; i += 256) {
            int r = i >> 6, d = i & 63;
            Ks[r][d] = Kb[(size_t)(kt * 32 + r) * Dd + d];
            Vs[r][d] = Vb[(size_t)(kt * 32 + r) * Dd + d];
        }
        __syncthreads();

        float s[4][2];
#pragma unroll
        for (int i = 0; i < 4; i++) { s[i][0] = 0.f; s[i][1] = 0.f; }
#pragma unroll 8
        for (int kk = 0; kk < 64; kk++) {
            float a0 = Qs[ty * 4 + 0][kk];
            float a1 = Qs[ty * 4 + 1][kk];
            float a2 = Qs[ty * 4 + 2][kk];
            float a3 = Qs[ty * 4 + 3][kk];
            float b0 = Ks[tx * 2 + 0][kk];
            float b1 = Ks[tx * 2 + 1][kk];
            s[0][0] += a0 * b0; s[0][1] += a0 * b1;
            s[1][0] += a1 * b0; s[1][1] += a1 * b1;
            s[2][0] += a2 * b0; s[2][1] += a2 * b1;
            s[3][0] += a3 * b0; s[3][1] += a3 * b1;
        }

#pragma unroll
        for (int i = 0; i < 4; i++) {
            const int qg = qb * 64 + ty * 4 + i;
#pragma unroll
            for (int j = 0; j < 2; j++) {
                const int kg = kt * 32 + tx * 2 + j;
                if (kg > qg) s[i][j] = -1e30f;
            }
            float v = fmaxf(s[i][0], s[i][1]);
#pragma unroll
            for (int o = 1; o < 16; o <<= 1)
                v = fmaxf(v, __shfl_xor_sync(0xffffffffu, v, o, 16));
            const float mnew = fmaxf(m_i[i], v);
            const float fac  = __expf(m_i[i] - mnew);
            const float p0 = __expf(s[i][0] - mnew);
            const float p1 = __expf(s[i][1] - mnew);
            Ps[ty * 4 + i][tx * 2 + 0] = p0;
            Ps[ty * 4 + i][tx * 2 + 1] = p1;
            float rs = p0 + p1;
#pragma unroll
            for (int o = 1; o < 16; o <<= 1)
                rs += __shfl_xor_sync(0xffffffffu, rs, o, 16);
            l_i[i] = l_i[i] * fac + rs;
            m_i[i] = mnew;
#pragma unroll
            for (int j = 0; j < 4; j++) O[i][j] *= fac;
        }
        __syncwarp();

#pragma unroll 4
        for (int k = 0; k < 32; k++) {
            float pr0 = Ps[ty * 4 + 0][k];
            float pr1 = Ps[ty * 4 + 1][k];
            float pr2 = Ps[ty * 4 + 2][k];
            float pr3 = Ps[ty * 4 + 3][k];
            float v0 = Vs[k][tx * 4 + 0];
            float v1 = Vs[k][tx * 4 + 1];
            float v2 = Vs[k][tx * 4 + 2];
            float v3 = Vs[k][tx * 4 + 3];
            O[0][0] += pr0 * v0; O[0][1] += pr0 * v1; O[0][2] += pr0 * v2; O[0][3] += pr0 * v3;
            O[1][0] += pr1 * v0; O[1][1] += pr1 * v1; O[1][2] += pr1 * v2; O[1][3] += pr1 * v3;
            O[2][0] += pr2 * v0; O[2][1] += pr2 * v1; O[2][2] += pr2 * v2; O[2][3] += pr2 * v3;
            O[3][0] += pr3 * v0; O[3][1] += pr3 * v1; O[3][2] += pr3 * v2; O[3][3] += pr3 * v3;
        }
    }

#pragma unroll
    for (int i = 0; i < 4; i++) {
        const float inv = 1.f / l_i[i];
        float* op = Og + (size_t)(b * Ss + qb * 64 + ty * 4 + i) * Dd + h * HDd + tx * 4;
#pragma unroll
        for (int j = 0; j < 4; j++) op[j] = O[i][j] * inv;
    }
}

// ---------------- residual add + LayerNorm ----------------
__global__ __launch_bounds__(256)
void add_ln_kernel(const float* __restrict__ a, const float* __restrict__ r,
                   const float* __restrict__ gamma, const float* __restrict__ beta,
                   float* __restrict__ out)
{
    const int t = blockIdx.x;
    const int tid = threadIdx.x;
    __shared__ float buf[Dd];
    __shared__ float red[20];

    float s = 0.f, sq = 0.f;
    for (int i = tid; i < Dd; i += 256) {
        float v = a[(size_t)t * Dd + i] + r[(size_t)t * Dd + i];
        buf[i] = v;
        s += v; sq += v * v;
    }
#pragma unroll
    for (int o = 16; o; o >>= 1) {
        s  += __shfl_xor_sync(0xffffffffu, s, o);
        sq += __shfl_xor_sync(0xffffffffu, sq, o);
    }
    if ((tid & 31) == 0) { red[tid >> 5] = s; red[8 + (tid >> 5)] = sq; }
    __syncthreads();
    if (tid == 0) {
        float ts = 0.f, tq = 0.f;
        for (int i = 0; i < 8; i++) { ts += red[i]; tq += red[8 + i]; }
        const float mu  = ts * (1.0f / Dd);
        const float var = tq * (1.0f / Dd) - mu * mu;
        red[16] = mu;
        red[17] = rsqrtf(var + 1e-6f);
    }
    __syncthreads();
    const float mu = red[16], rstd = red[17];
    for (int i = tid; i < Dd; i += 256)
        out[(size_t)t * Dd + i] = (buf[i] - mu) * rstd * gamma[i] + beta[i];
}

// ---------------- launch ----------------
extern "C" void kernel_launch(void* const* d_in, const int* in_sizes, int n_in,
                              void* d_out, int out_size)
{
    const float* x   = (const float*)d_in[0];
    const float* Wq  = (const float*)d_in[1];
    const float* bq  = (const float*)d_in[2];
    const float* Wk  = (const float*)d_in[3];
    const float* bk  = (const float*)d_in[4];
    const float* Wv  = (const float*)d_in[5];
    const float* bv  = (const float*)d_in[6];
    const float* Wo  = (const float*)d_in[7];
    const float* bo  = (const float*)d_in[8];
    const float* g1  = (const float*)d_in[9];
    const float* b1  = (const float*)d_in[10];
    const float* Wup = (const float*)d_in[11];
    const float* bup = (const float*)d_in[12];
    const float* Wdn = (const float*)d_in[13];
    const float* bdn = (const float*)d_in[14];
    const float* g2  = (const float*)d_in[15];
    const float* b2  = (const float*)d_in[16];
    float* out = (float*)d_out;

    float *q, *k, *v, *mid, *proj, *x1, *up;
    cudaGetSymbolAddress((void**)&q,    g_q);
    cudaGetSymbolAddress((void**)&k,    g_k);
    cudaGetSymbolAddress((void**)&v,    g_v);
    cudaGetSymbolAddress((void**)&mid,  g_mid);
    cudaGetSymbolAddress((void**)&proj, g_proj);
    cudaGetSymbolAddress((void**)&x1,   g_x1);
    cudaGetSymbolAddress((void**)&up,   g_up);

    const dim3 blk(256);
    const dim3 gridD(Dd / 128, Tt / 128);    // N=1024
    const dim3 gridF(DFF / 128, Tt / 128);   // N=4096

    // QKV projections (tensor cores, TF32)
    gemm_tc<0><<<gridD, blk>>>(x, Wq, bq, q, Tt, Dd, Dd);
    gemm_tc<0><<<gridD, blk>>>(x, Wk, bk, k, Tt, Dd, Dd);
    gemm_tc<0><<<gridD, blk>>>(x, Wv, bv, v, Tt, Dd, Dd);

    // causal attention
    attn_kernel<<<dim3(Ss / 64, Bt * Hh), blk>>>(q, k, v, mid);

    // output projection + residual LN1
    gemm_tc<0><<<gridD, blk>>>(mid, Wo, bo, proj, Tt, Dd, Dd);
    add_ln_kernel<<<Tt, blk>>>(x, proj, g1, b1, x1);

    // FFN
    gemm_tc<1><<<gridF, blk>>>(x1, Wup, bup, up, Tt, DFF, Dd);
    gemm_tc<0><<<gridD, blk>>>(up, Wdn, bdn, proj, Tt, Dd, DFF);
    add_ln_kernel<<<Tt, blk>>>(x1, proj, g2, b2, out);
}

// round 4
// speedup vs baseline: 3.1026x; 1.5040x over previous
#include <cuda_runtime.h>
#include <cstdint>

#define Bt  2
#define Ss  2048
#define Dd  1024
#define Hh  16
#define HDd 64
#define Tt  (Bt * Ss)      // 4096 tokens
#define DFF (4 * Dd)       // 4096

// ---------------- scratch (device globals; no allocation allowed) ----------------
__device__ float g_q[Tt * Dd];
__device__ float g_k[Tt * Dd];
__device__ float g_v[Tt * Dd];
__device__ float g_mid[Tt * Dd];
__device__ float g_proj[Tt * Dd];
__device__ float g_x1[Tt * Dd];
__device__ float g_up[(size_t)Tt * DFF];

// ---------------- helpers ----------------
__device__ __forceinline__ uint32_t f2tf32(float f) {
    uint32_t o;
    asm("cvt.rna.tf32.f32 %0, %1;" : "=r"(o) : "f"(f));
    return o;
}
__device__ __forceinline__ float tf32f(float f) { return __uint_as_float(f2tf32(f)); }

__device__ __forceinline__ void mma_tf32(float* d, const uint32_t* a, const uint32_t* b) {
    asm volatile(
        "mma.sync.aligned.m16n8k8.row.col.f32.tf32.tf32.f32 "
        "{%0,%1,%2,%3}, {%4,%5,%6,%7}, {%8,%9}, {%0,%1,%2,%3};"
        : "+f"(d[0]), "+f"(d[1]), "+f"(d[2]), "+f"(d[3])
        : "r"(a[0]), "r"(a[1]), "r"(a[2]), "r"(a[3]), "r"(b[0]), "r"(b[1]));
}

// ---------------- TF32 tensor-core GEMM (unchanged from R3) ----------------
template <int RELU>
__global__ __launch_bounds__(256)
void gemm_tc(const float* __restrict__ A, const float* __restrict__ W,
             const float* __restrict__ bias, float* __restrict__ C,
             int M, int N, int K)
{
    __shared__ float As[128][36];
    __shared__ float Bs[32][136];

    const int tid  = threadIdx.x;
    const int lane = tid & 31;
    const int wid  = tid >> 5;
    const int wm   = (wid & 1) * 64;
    const int wn   = (wid >> 1) * 32;
    const int m0   = blockIdx.y << 7;
    const int n0   = blockIdx.x << 7;

    const int row = lane >> 2;
    const int col = lane & 3;

    float acc[4][4][4];
#pragma unroll
    for (int mi = 0; mi < 4; mi++)
#pragma unroll
        for (int ni = 0; ni < 4; ni++)
#pragma unroll
            for (int j = 0; j < 4; j++) acc[mi][ni][j] = 0.f;

    const int fa_r = tid >> 3;
    const int fa_q = (tid & 7) * 4;
    const int fb_r = tid >> 5;
    const int fb_c = (tid & 31) * 4;

    for (int k0 = 0; k0 < K; k0 += 32) {
#pragma unroll
        for (int rr = fa_r; rr < 128; rr += 32) {
            float4 v = *(const float4*)&A[(size_t)(m0 + rr) * K + k0 + fa_q];
            As[rr][fa_q + 0] = tf32f(v.x);
            As[rr][fa_q + 1] = tf32f(v.y);
            As[rr][fa_q + 2] = tf32f(v.z);
            As[rr][fa_q + 3] = tf32f(v.w);
        }
#pragma unroll
        for (int rr = fb_r; rr < 32; rr += 8) {
            float4 v = *(const float4*)&W[(size_t)(k0 + rr) * N + n0 + fb_c];
            Bs[rr][fb_c + 0] = tf32f(v.x);
            Bs[rr][fb_c + 1] = tf32f(v.y);
            Bs[rr][fb_c + 2] = tf32f(v.z);
            Bs[rr][fb_c + 3] = tf32f(v.w);
        }
        __syncthreads();

#pragma unroll
        for (int ks = 0; ks < 4; ks++) {
            const int kb = ks * 8;
            uint32_t a[4][4], b[4][2];
#pragma unroll
            for (int mi = 0; mi < 4; mi++) {
                const int r = wm + mi * 16 + row;
                a[mi][0] = __float_as_uint(As[r][kb + col]);
                a[mi][1] = __float_as_uint(As[r + 8][kb + col]);
                a[mi][2] = __float_as_uint(As[r][kb + col + 4]);
                a[mi][3] = __float_as_uint(As[r + 8][kb + col + 4]);
            }
#pragma unroll
            for (int ni = 0; ni < 4; ni++) {
                const int c = wn + ni * 8 + row;
                b[ni][0] = __float_as_uint(Bs[kb + col][c]);
                b[ni][1] = __float_as_uint(Bs[kb + col + 4][c]);
            }
#pragma unroll
            for (int mi = 0; mi < 4; mi++)
#pragma unroll
                for (int ni = 0; ni < 4; ni++)
                    mma_tf32(acc[mi][ni], a[mi], b[ni]);
        }
        __syncthreads();
    }

#pragma unroll
    for (int mi = 0; mi < 4; mi++) {
        const int r0 = m0 + wm + mi * 16 + row;
#pragma unroll
        for (int ni = 0; ni < 4; ni++) {
            const int c0 = n0 + wn + ni * 8 + 2 * col;
            const float b0 = bias[c0], b1 = bias[c0 + 1];
            float2 v0, v1;
            v0.x = acc[mi][ni][0] + b0; v0.y = acc[mi][ni][1] + b1;
            v1.x = acc[mi][ni][2] + b0; v1.y = acc[mi][ni][3] + b1;
            if (RELU) {
                v0.x = fmaxf(v0.x, 0.f); v0.y = fmaxf(v0.y, 0.f);
                v1.x = fmaxf(v1.x, 0.f); v1.y = fmaxf(v1.y, 0.f);
            }
            *(float2*)&C[(size_t)r0 * N + c0]       = v0;
            *(float2*)&C[(size_t)(r0 + 8) * N + c0] = v1;
        }
    }
}

// ---------------- tensor-core causal flash attention ----------------
// CTA: 64 queries, 4 warps (16 q-rows each), key tile 64, Hd=64.
// Q in register A-fragments; K smem tile reused as P tile; V smem doubles
// as Q staging. All smem strides 68 floats (conflict-free fragment access).
__global__ __launch_bounds__(128)
void attn_tc(const float* __restrict__ Qg, const float* __restrict__ Kg,
             const float* __restrict__ Vg, float* __restrict__ Og)
{
    __shared__ float Ks[64][68];   // K tile; overlaid with P after QK^T
    __shared__ float Vs[64][68];   // V tile; doubles as Q staging in prologue

    const int tid  = threadIdx.x;
    const int lane = tid & 31;
    const int wid  = tid >> 5;            // 0..3
    const int row  = lane >> 2;           // 0..7
    const int col  = lane & 3;            // 0..3
    const int qb   = blockIdx.x;          // 0..31
    const int bh   = blockIdx.y;
    const int b    = bh >> 4, h = bh & 15;

    const float* Qb = Qg + (size_t)b * Ss * Dd + h * HDd;
    const float* Kb = Kg + (size_t)b * Ss * Dd + h * HDd;
    const float* Vb = Vg + (size_t)b * Ss * Dd + h * HDd;

    // ---- prologue: stage Q (scaled, tf32) through Vs, build A fragments ----
    for (int i = tid; i < 64 * 16; i += 128) {
        const int r = i >> 4, c4 = (i & 15) << 2;
        float4 v = *(const float4*)&Qb[(size_t)(qb * 64 + r) * Dd + c4];
        Vs[r][c4 + 0] = tf32f(v.x * 0.125f);
        Vs[r][c4 + 1] = tf32f(v.y * 0.125f);
        Vs[r][c4 + 2] = tf32f(v.z * 0.125f);
        Vs[r][c4 + 3] = tf32f(v.w * 0.125f);
    }
    __syncthreads();

    uint32_t qf[8][4];
    {
        const int r = wid * 16 + row;
#pragma unroll
        for (int kk = 0; kk < 8; kk++) {
            qf[kk][0] = __float_as_uint(Vs[r][kk * 8 + col]);
            qf[kk][1] = __float_as_uint(Vs[r + 8][kk * 8 + col]);
            qf[kk][2] = __float_as_uint(Vs[r][kk * 8 + col + 4]);
            qf[kk][3] = __float_as_uint(Vs[r + 8][kk * 8 + col + 4]);
        }
    }

    float m0 = -1e30f, m1 = -1e30f, l0 = 0.f, l1 = 0.f;
    float O[8][4];
#pragma unroll
    for (int n = 0; n < 8; n++)
#pragma unroll
        for (int j = 0; j < 4; j++) O[n][j] = 0.f;

    const int lq0 = wid * 16 + row;   // local q row (warp-relative +16*wid)
    const int lq1 = lq0 + 8;

    const int nkt = qb + 1;
    for (int kt = 0; kt < nkt; kt++) {
        __syncthreads();   // previous iteration's P/V reads done (and Q staging)
        for (int i = tid; i < 64 * 16; i += 128) {
            const int r = i >> 4, c4 = (i & 15) << 2;
            float4 kv = *(const float4*)&Kb[(size_t)(kt * 64 + r) * Dd + c4];
            float4 vv = *(const float4*)&Vb[(size_t)(kt * 64 + r) * Dd + c4];
            Ks[r][c4 + 0] = tf32f(kv.x); Vs[r][c4 + 0] = tf32f(vv.x);
            Ks[r][c4 + 1] = tf32f(kv.y); Vs[r][c4 + 1] = tf32f(vv.y);
            Ks[r][c4 + 2] = tf32f(kv.z); Vs[r][c4 + 2] = tf32f(vv.z);
            Ks[r][c4 + 3] = tf32f(kv.w); Vs[r][c4 + 3] = tf32f(vv.w);
        }
        __syncthreads();

        // ---- S = Q @ K^T  (8 n-tiles of 8 keys) ----
        float S[8][4];
#pragma unroll
        for (int n = 0; n < 8; n++)
#pragma unroll
            for (int j = 0; j < 4; j++) S[n][j] = 0.f;

#pragma unroll
        for (int kk = 0; kk < 8; kk++) {
#pragma unroll
            for (int n = 0; n < 8; n++) {
                uint32_t bq[2];
                bq[0] = __float_as_uint(Ks[n * 8 + row][kk * 8 + col]);
                bq[1] = __float_as_uint(Ks[n * 8 + row][kk * 8 + col + 4]);
                mma_tf32(S[n], qf[kk], bq);
            }
        }
        __syncthreads();   // all warps done reading Ks before P overwrites it

        // ---- causal mask (diagonal tile only) ----
        if (kt == qb) {
#pragma unroll
            for (int n = 0; n < 8; n++) {
                const int kc = n * 8 + 2 * col;
                if (kc     > lq0) S[n][0] = -1e30f;
                if (kc + 1 > lq0) S[n][1] = -1e30f;
                if (kc     > lq1) S[n][2] = -1e30f;
                if (kc + 1 > lq1) S[n][3] = -1e30f;
            }
        }

        // ---- online softmax (rows lq0, lq1) ----
        float mx0 = -1e30f, mx1 = -1e30f;
#pragma unroll
        for (int n = 0; n < 8; n++) {
            mx0 = fmaxf(mx0, fmaxf(S[n][0], S[n][1]));
            mx1 = fmaxf(mx1, fmaxf(S[n][2], S[n][3]));
        }
        mx0 = fmaxf(mx0, __shfl_xor_sync(0xffffffffu, mx0, 1));
        mx0 = fmaxf(mx0, __shfl_xor_sync(0xffffffffu, mx0, 2));
        mx1 = fmaxf(mx1, __shfl_xor_sync(0xffffffffu, mx1, 1));
        mx1 = fmaxf(mx1, __shfl_xor_sync(0xffffffffu, mx1, 2));

        const float mn0 = fmaxf(m0, mx0), mn1 = fmaxf(m1, mx1);
        const float fac0 = __expf(m0 - mn0), fac1 = __expf(m1 - mn1);

        float s0 = 0.f, s1 = 0.f;
        const int pr = wid * 16 + row;
#pragma unroll
        for (int n = 0; n < 8; n++) {
            const float p00 = __expf(S[n][0] - mn0);
            const float p01 = __expf(S[n][1] - mn0);
            const float p10 = __expf(S[n][2] - mn1);
            const float p11 = __expf(S[n][3] - mn1);
            s0 += p00 + p01;
            s1 += p10 + p11;
            Ks[pr][n * 8 + 2 * col]         = tf32f(p00);
            Ks[pr][n * 8 + 2 * col + 1]     = tf32f(p01);
            Ks[pr + 8][n * 8 + 2 * col]     = tf32f(p10);
            Ks[pr + 8][n * 8 + 2 * col + 1] = tf32f(p11);
        }
        s0 += __shfl_xor_sync(0xffffffffu, s0, 1);
        s0 += __shfl_xor_sync(0xffffffffu, s0, 2);
        s1 += __shfl_xor_sync(0xffffffffu, s1, 1);
        s1 += __shfl_xor_sync(0xffffffffu, s1, 2);

        l0 = l0 * fac0 + s0;
        l1 = l1 * fac1 + s1;
        m0 = mn0; m1 = mn1;

#pragma unroll
        for (int n = 0; n < 8; n++) {
            O[n][0] *= fac0; O[n][1] *= fac0;
            O[n][2] *= fac1; O[n][3] *= fac1;
        }
        __syncwarp();   // warp's own P rows visible to itself

        // ---- O += P @ V ----
#pragma unroll
        for (int kk = 0; kk < 8; kk++) {
            uint32_t pa[4];
            pa[0] = __float_as_uint(Ks[pr][kk * 8 + col]);
            pa[1] = __float_as_uint(Ks[pr + 8][kk * 8 + col]);
            pa[2] = __float_as_uint(Ks[pr][kk * 8 + col + 4]);
            pa[3] = __float_as_uint(Ks[pr + 8][kk * 8 + col + 4]);
#pragma unroll
            for (int n = 0; n < 8; n++) {
                uint32_t bv[2];
                bv[0] = __float_as_uint(Vs[kk * 8 + col][n * 8 + row]);
                bv[1] = __float_as_uint(Vs[kk * 8 + col + 4][n * 8 + row]);
                mma_tf32(O[n], pa, bv);
            }
        }
    }

    // ---- epilogue ----
    const float inv0 = 1.f / l0, inv1 = 1.f / l1;
    const int q0 = qb * 64 + lq0;
    float* o0 = Og + (size_t)(b * Ss + q0) * Dd + h * HDd;
    float* o1 = o0 + 8 * Dd;
#pragma unroll
    for (int n = 0; n < 8; n++) {
        const int c0 = n * 8 + 2 * col;
        float2 v0, v1;
        v0.x = O[n][0] * inv0; v0.y = O[n][1] * inv0;
        v1.x = O[n][2] * inv1; v1.y = O[n][3] * inv1;
        *(float2*)&o0[c0] = v0;
        *(float2*)&o1[c0] = v1;
    }
}

// ---------------- residual add + LayerNorm ----------------
__global__ __launch_bounds__(256)
void add_ln_kernel(const float* __restrict__ a, const float* __restrict__ r,
                   const float* __restrict__ gamma, const float* __restrict__ beta,
                   float* __restrict__ out)
{
    const int t = blockIdx.x;
    const int tid = threadIdx.x;
    __shared__ float buf[Dd];
    __shared__ float red[20];

    float s = 0.f, sq = 0.f;
    for (int i = tid; i < Dd; i += 256) {
        float v = a[(size_t)t * Dd + i] + r[(size_t)t * Dd + i];
        buf[i] = v;
        s += v; sq += v * v;
    }
#pragma unroll
    for (int o = 16; o; o >>= 1) {
        s  += __shfl_xor_sync(0xffffffffu, s, o);
        sq += __shfl_xor_sync(0xffffffffu, sq, o);
    }
    if ((tid & 31) == 0) { red[tid >> 5] = s; red[8 + (tid >> 5)] = sq; }
    __syncthreads();
    if (tid == 0) {
        float ts = 0.f, tq = 0.f;
        for (int i = 0; i < 8; i++) { ts += red[i]; tq += red[8 + i]; }
        const float mu  = ts * (1.0f / Dd);
        const float var = tq * (1.0f / Dd) - mu * mu;
        red[16] = mu;
        red[17] = rsqrtf(var + 1e-6f);
    }
    __syncthreads();
    const float mu = red[16], rstd = red[17];
    for (int i = tid; i < Dd; i += 256)
        out[(size_t)t * Dd + i] = (buf[i] - mu) * rstd * gamma[i] + beta[i];
}

// ---------------- launch ----------------
extern "C" void kernel_launch(void* const* d_in, const int* in_sizes, int n_in,
                              void* d_out, int out_size)
{
    const float* x   = (const float*)d_in[0];
    const float* Wq  = (const float*)d_in[1];
    const float* bq  = (const float*)d_in[2];
    const float* Wk  = (const float*)d_in[3];
    const float* bk  = (const float*)d_in[4];
    const float* Wv  = (const float*)d_in[5];
    const float* bv  = (const float*)d_in[6];
    const float* Wo  = (const float*)d_in[7];
    const float* bo  = (const float*)d_in[8];
    const float* g1  = (const float*)d_in[9];
    const float* b1  = (const float*)d_in[10];
    const float* Wup = (const float*)d_in[11];
    const float* bup = (const float*)d_in[12];
    const float* Wdn = (const float*)d_in[13];
    const float* bdn = (const float*)d_in[14];
    const float* g2  = (const float*)d_in[15];
    const float* b2  = (const float*)d_in[16];
    float* out = (float*)d_out;

    float *q, *k, *v, *mid, *proj, *x1, *up;
    cudaGetSymbolAddress((void**)&q,    g_q);
    cudaGetSymbolAddress((void**)&k,    g_k);
    cudaGetSymbolAddress((void**)&v,    g_v);
    cudaGetSymbolAddress((void**)&mid,  g_mid);
    cudaGetSymbolAddress((void**)&proj, g_proj);
    cudaGetSymbolAddress((void**)&x1,   g_x1);
    cudaGetSymbolAddress((void**)&up,   g_up);

    const dim3 blk(256);
    const dim3 gridD(Dd / 128, Tt / 128);
    const dim3 gridF(DFF / 128, Tt / 128);

    gemm_tc<0><<<gridD, blk>>>(x, Wq, bq, q, Tt, Dd, Dd);
    gemm_tc<0><<<gridD, blk>>>(x, Wk, bk, k, Tt, Dd, Dd);
    gemm_tc<0><<<gridD, blk>>>(x, Wv, bv, v, Tt, Dd, Dd);

    attn_tc<<<dim3(Ss / 64, Bt * Hh), dim3(128)>>>(q, k, v, mid);

    gemm_tc<0><<<gridD, blk>>>(mid, Wo, bo, proj, Tt, Dd, Dd);
    add_ln_kernel<<<Tt, blk>>>(x, proj, g1, b1, x1);

    gemm_tc<1><<<gridF, blk>>>(x1, Wup, bup, up, Tt, DFF, Dd);
    gemm_tc<0><<<gridD, blk>>>(up, Wdn, bdn, proj, Tt, Dd, DFF);
    add_ln_kernel<<<Tt, blk>>>(x1, proj, g2, b2, out);
}

// round 5
// speedup vs baseline: 3.7571x; 1.2109x over previous
#include <cuda_runtime.h>
#include <cuda_fp16.h>
#include <cstdint>

#define Bt  2
#define Ss  2048
#define Dd  1024
#define Hh  16
#define HDd 64
#define Tt  (Bt * Ss)      // 4096 tokens
#define DFF (4 * Dd)       // 4096

// ---------------- scratch (device globals; no allocation allowed) ----------------
__device__ float g_q[Tt * Dd];
__device__ float g_k[Tt * Dd];
__device__ float g_v[Tt * Dd];
__device__ float g_mid[Tt * Dd];
__device__ float g_proj[Tt * Dd];
__device__ float g_x1[Tt * Dd];
__device__ float g_up[(size_t)Tt * DFF];

// ---------------- helpers ----------------
__device__ __forceinline__ uint32_t f2tf32(float f) {
    uint32_t o;
    asm("cvt.rna.tf32.f32 %0, %1;" : "=r"(o) : "f"(f));
    return o;
}
__device__ __forceinline__ float tf32f(float f) { return __uint_as_float(f2tf32(f)); }

__device__ __forceinline__ void mma_tf32(float* d, const uint32_t* a, const uint32_t* b) {
    asm volatile(
        "mma.sync.aligned.m16n8k8.row.col.f32.tf32.tf32.f32 "
        "{%0,%1,%2,%3}, {%4,%5,%6,%7}, {%8,%9}, {%0,%1,%2,%3};"
        : "+f"(d[0]), "+f"(d[1]), "+f"(d[2]), "+f"(d[3])
        : "r"(a[0]), "r"(a[1]), "r"(a[2]), "r"(a[3]), "r"(b[0]), "r"(b[1]));
}
__device__ __forceinline__ void mma_f16(float* d, const uint32_t* a, const uint32_t* b) {
    asm volatile(
        "mma.sync.aligned.m16n8k16.row.col.f32.f16.f16.f32 "
        "{%0,%1,%2,%3}, {%4,%5,%6,%7}, {%8,%9}, {%0,%1,%2,%3};"
        : "+f"(d[0]), "+f"(d[1]), "+f"(d[2]), "+f"(d[3])
        : "r"(a[0]), "r"(a[1]), "r"(a[2]), "r"(a[3]), "r"(b[0]), "r"(b[1]));
}
__device__ __forceinline__ uint32_t sptr(const void* p) {
    return (uint32_t)__cvta_generic_to_shared(p);
}
__device__ __forceinline__ void ldsm_x4(uint32_t* r, uint32_t addr) {
    asm volatile("ldmatrix.sync.aligned.m8n8.x4.shared.b16 {%0,%1,%2,%3}, [%4];"
                 : "=r"(r[0]), "=r"(r[1]), "=r"(r[2]), "=r"(r[3]) : "r"(addr));
}
__device__ __forceinline__ void ldsm_x2t(uint32_t* r, uint32_t addr) {
    asm volatile("ldmatrix.sync.aligned.m8n8.x2.trans.shared.b16 {%0,%1}, [%2];"
                 : "=r"(r[0]), "=r"(r[1]) : "r"(addr));
}

// ---------------- FP16 tensor-core GEMM ----------------
// C[M,N] = A[M,K] @ W[K,N] + bias (+ ReLU). fp32 accumulate.
// Block tile 128x128, K-chunk 32 (2 x k16), 256 threads = 8 warps (2m x 4n).
// Each warp: 64x32 = 4x4 m16n8k16 tiles. Fragments via ldmatrix.
template <int RELU>
__global__ __launch_bounds__(256)
void gemm_f16(const float* __restrict__ A, const float* __restrict__ W,
              const float* __restrict__ bias, float* __restrict__ C,
              int M, int N, int K)
{
    __shared__ __half As[128][40];    // row-major m x k, stride 80B (conflict-free ldsm)
    __shared__ __half Bs[32][136];    // k-major k x n, stride 272B (conflict-free ldsm.trans)

    const int tid  = threadIdx.x;
    const int lane = tid & 31;
    const int wid  = tid >> 5;
    const int wm   = (wid & 1) * 64;
    const int wn   = (wid >> 1) * 32;
    const int m0   = blockIdx.y << 7;
    const int n0   = blockIdx.x << 7;

    const int row = lane >> 2;   // 0..7
    const int col = lane & 3;    // 0..3

    float acc[4][4][4];
#pragma unroll
    for (int mi = 0; mi < 4; mi++)
#pragma unroll
        for (int ni = 0; ni < 4; ni++)
#pragma unroll
            for (int j = 0; j < 4; j++) acc[mi][ni][j] = 0.f;

    const int fa_r = tid >> 3;         // A rows, step 32
    const int fa_q = (tid & 7) * 4;    // A k offset (halves)
    const int fb_r = tid >> 5;         // B k rows, step 8
    const int fb_c = (tid & 31) * 4;   // B n offset

    const int lrow = lane & 15;        // ldmatrix row index
    const int lcol = (lane >> 4) * 8;  // ldmatrix k-half offset (A x4 only)

    for (int k0 = 0; k0 < K; k0 += 32) {
        // A tile: 128 x 32 fp16
#pragma unroll
        for (int rr = fa_r; rr < 128; rr += 32) {
            float4 v = *(const float4*)&A[(size_t)(m0 + rr) * K + k0 + fa_q];
            *(__half2*)&As[rr][fa_q]     = __floats2half2_rn(v.x, v.y);
            *(__half2*)&As[rr][fa_q + 2] = __floats2half2_rn(v.z, v.w);
        }
        // B tile: 32 x 128 fp16 straight from W[K,N]
#pragma unroll
        for (int rr = fb_r; rr < 32; rr += 8) {
            float4 v = *(const float4*)&W[(size_t)(k0 + rr) * N + n0 + fb_c];
            *(__half2*)&Bs[rr][fb_c]     = __floats2half2_rn(v.x, v.y);
            *(__half2*)&Bs[rr][fb_c + 2] = __floats2half2_rn(v.z, v.w);
        }
        __syncthreads();

#pragma unroll
        for (int ks = 0; ks < 32; ks += 16) {
            uint32_t a[4][4], b[4][2];
#pragma unroll
            for (int mi = 0; mi < 4; mi++)
                ldsm_x4(a[mi], sptr(&As[wm + mi * 16 + lrow][ks + lcol]));
#pragma unroll
            for (int ni = 0; ni < 4; ni++)
                ldsm_x2t(b[ni], sptr(&Bs[ks + lrow][wn + ni * 8]));
#pragma unroll
            for (int mi = 0; mi < 4; mi++)
#pragma unroll
                for (int ni = 0; ni < 4; ni++)
                    mma_f16(acc[mi][ni], a[mi], b[ni]);
        }
        __syncthreads();
    }

    // epilogue: direct float2 stores with bias (+ReLU)
#pragma unroll
    for (int mi = 0; mi < 4; mi++) {
        const int r0 = m0 + wm + mi * 16 + row;
#pragma unroll
        for (int ni = 0; ni < 4; ni++) {
            const int c0 = n0 + wn + ni * 8 + 2 * col;
            const float b0 = bias[c0], b1 = bias[c0 + 1];
            float2 v0, v1;
            v0.x = acc[mi][ni][0] + b0; v0.y = acc[mi][ni][1] + b1;
            v1.x = acc[mi][ni][2] + b0; v1.y = acc[mi][ni][3] + b1;
            if (RELU) {
                v0.x = fmaxf(v0.x, 0.f); v0.y = fmaxf(v0.y, 0.f);
                v1.x = fmaxf(v1.x, 0.f); v1.y = fmaxf(v1.y, 0.f);
            }
            *(float2*)&C[(size_t)r0 * N + c0]       = v0;
            *(float2*)&C[(size_t)(r0 + 8) * N + c0] = v1;
        }
    }
}

// ---------------- tensor-core causal flash attention (unchanged from R4) ----------------
__global__ __launch_bounds__(128)
void attn_tc(const float* __restrict__ Qg, const float* __restrict__ Kg,
             const float* __restrict__ Vg, float* __restrict__ Og)
{
    __shared__ float Ks[64][68];
    __shared__ float Vs[64][68];

    const int tid  = threadIdx.x;
    const int lane = tid & 31;
    const int wid  = tid >> 5;
    const int row  = lane >> 2;
    const int col  = lane & 3;
    const int qb   = blockIdx.x;
    const int bh   = blockIdx.y;
    const int b    = bh >> 4, h = bh & 15;

    const float* Qb = Qg + (size_t)b * Ss * Dd + h * HDd;
    const float* Kb = Kg + (size_t)b * Ss * Dd + h * HDd;
    const float* Vb = Vg + (size_t)b * Ss * Dd + h * HDd;

    for (int i = tid; i < 64 * 16; i += 128) {
        const int r = i >> 4, c4 = (i & 15) << 2;
        float4 v = *(const float4*)&Qb[(size_t)(qb * 64 + r) * Dd + c4];
        Vs[r][c4 + 0] = tf32f(v.x * 0.125f);
        Vs[r][c4 + 1] = tf32f(v.y * 0.125f);
        Vs[r][c4 + 2] = tf32f(v.z * 0.125f);
        Vs[r][c4 + 3] = tf32f(v.w * 0.125f);
    }
    __syncthreads();

    uint32_t qf[8][4];
    {
        const int r = wid * 16 + row;
#pragma unroll
        for (int kk = 0; kk < 8; kk++) {
            qf[kk][0] = __float_as_uint(Vs[r][kk * 8 + col]);
            qf[kk][1] = __float_as_uint(Vs[r + 8][kk * 8 + col]);
            qf[kk][2] = __float_as_uint(Vs[r][kk * 8 + col + 4]);
            qf[kk][3] = __float_as_uint(Vs[r + 8][kk * 8 + col + 4]);
        }
    }

    float m0 = -1e30f, m1 = -1e30f, l0 = 0.f, l1 = 0.f;
    float O[8][4];
#pragma unroll
    for (int n = 0; n < 8; n++)
#pragma unroll
        for (int j = 0; j < 4; j++) O[n][j] = 0.f;

    const int lq0 = wid * 16 + row;
    const int lq1 = lq0 + 8;

    const int nkt = qb + 1;
    for (int kt = 0; kt < nkt; kt++) {
        __syncthreads();
        for (int i = tid; i < 64 * 16; i += 128) {
            const int r = i >> 4, c4 = (i & 15) << 2;
            float4 kv = *(const float4*)&Kb[(size_t)(kt * 64 + r) * Dd + c4];
            float4 vv = *(const float4*)&Vb[(size_t)(kt * 64 + r) * Dd + c4];
            Ks[r][c4 + 0] = tf32f(kv.x); Vs[r][c4 + 0] = tf32f(vv.x);
            Ks[r][c4 + 1] = tf32f(kv.y); Vs[r][c4 + 1] = tf32f(vv.y);
            Ks[r][c4 + 2] = tf32f(kv.z); Vs[r][c4 + 2] = tf32f(vv.z);
            Ks[r][c4 + 3] = tf32f(kv.w); Vs[r][c4 + 3] = tf32f(vv.w);
        }
        __syncthreads();

        float S[8][4];
#pragma unroll
        for (int n = 0; n < 8; n++)
#pragma unroll
            for (int j = 0; j < 4; j++) S[n][j] = 0.f;

#pragma unroll
        for (int kk = 0; kk < 8; kk++) {
#pragma unroll
            for (int n = 0; n < 8; n++) {
                uint32_t bq[2];
                bq[0] = __float_as_uint(Ks[n * 8 + row][kk * 8 + col]);
                bq[1] = __float_as_uint(Ks[n * 8 + row][kk * 8 + col + 4]);
                mma_tf32(S[n], qf[kk], bq);
            }
        }
        __syncthreads();

        if (kt == qb) {
#pragma unroll
            for (int n = 0; n < 8; n++) {
                const int kc = n * 8 + 2 * col;
                if (kc     > lq0) S[n][0] = -1e30f;
                if (kc + 1 > lq0) S[n][1] = -1e30f;
                if (kc     > lq1) S[n][2] = -1e30f;
                if (kc + 1 > lq1) S[n][3] = -1e30f;
            }
        }

        float mx0 = -1e30f, mx1 = -1e30f;
#pragma unroll
        for (int n = 0; n < 8; n++) {
            mx0 = fmaxf(mx0, fmaxf(S[n][0], S[n][1]));
            mx1 = fmaxf(mx1, fmaxf(S[n][2], S[n][3]));
        }
        mx0 = fmaxf(mx0, __shfl_xor_sync(0xffffffffu, mx0, 1));
        mx0 = fmaxf(mx0, __shfl_xor_sync(0xffffffffu, mx0, 2));
        mx1 = fmaxf(mx1, __shfl_xor_sync(0xffffffffu, mx1, 1));
        mx1 = fmaxf(mx1, __shfl_xor_sync(0xffffffffu, mx1, 2));

        const float mn0 = fmaxf(m0, mx0), mn1 = fmaxf(m1, mx1);
        const float fac0 = __expf(m0 - mn0), fac1 = __expf(m1 - mn1);

        float s0 = 0.f, s1 = 0.f;
        const int pr = wid * 16 + row;
#pragma unroll
        for (int n = 0; n < 8; n++) {
            const float p00 = __expf(S[n][0] - mn0);
            const float p01 = __expf(S[n][1] - mn0);
            const float p10 = __expf(S[n][2] - mn1);
            const float p11 = __expf(S[n][3] - mn1);
            s0 += p00 + p01;
            s1 += p10 + p11;
            Ks[pr][n * 8 + 2 * col]         = tf32f(p00);
            Ks[pr][n * 8 + 2 * col + 1]     = tf32f(p01);
            Ks[pr + 8][n * 8 + 2 * col]     = tf32f(p10);
            Ks[pr + 8][n * 8 + 2 * col + 1] = tf32f(p11);
        }
        s0 += __shfl_xor_sync(0xffffffffu, s0, 1);
        s0 += __shfl_xor_sync(0xffffffffu, s0, 2);
        s1 += __shfl_xor_sync(0xffffffffu, s1, 1);
        s1 += __shfl_xor_sync(0xffffffffu, s1, 2);

        l0 = l0 * fac0 + s0;
        l1 = l1 * fac1 + s1;
        m0 = mn0; m1 = mn1;

#pragma unroll
        for (int n = 0; n < 8; n++) {
            O[n][0] *= fac0; O[n][1] *= fac0;
            O[n][2] *= fac1; O[n][3] *= fac1;
        }
        __syncwarp();

#pragma unroll
        for (int kk = 0; kk < 8; kk++) {
            uint32_t pa[4];
            pa[0] = __float_as_uint(Ks[pr][kk * 8 + col]);
            pa[1] = __float_as_uint(Ks[pr + 8][kk * 8 + col]);
            pa[2] = __float_as_uint(Ks[pr][kk * 8 + col + 4]);
            pa[3] = __float_as_uint(Ks[pr + 8][kk * 8 + col + 4]);
#pragma unroll
            for (int n = 0; n < 8; n++) {
                uint32_t bv[2];
                bv[0] = __float_as_uint(Vs[kk * 8 + col][n * 8 + row]);
                bv[1] = __float_as_uint(Vs[kk * 8 + col + 4][n * 8 + row]);
                mma_tf32(O[n], pa, bv);
            }
        }
    }

    const float inv0 = 1.f / l0, inv1 = 1.f / l1;
    const int q0 = qb * 64 + lq0;
    float* o0 = Og + (size_t)(b * Ss + q0) * Dd + h * HDd;
    float* o1 = o0 + 8 * Dd;
#pragma unroll
    for (int n = 0; n < 8; n++) {
        const int c0 = n * 8 + 2 * col;
        float2 v0, v1;
        v0.x = O[n][0] * inv0; v0.y = O[n][1] * inv0;
        v1.x = O[n][2] * inv1; v1.y = O[n][3] * inv1;
        *(float2*)&o0[c0] = v0;
        *(float2*)&o1[c0] = v1;
    }
}

// ---------------- residual add + LayerNorm ----------------
__global__ __launch_bounds__(256)
void add_ln_kernel(const float* __restrict__ a, const float* __restrict__ r,
                   const float* __restrict__ gamma, const float* __restrict__ beta,
                   float* __restrict__ out)
{
    const int t = blockIdx.x;
    const int tid = threadIdx.x;
    __shared__ float buf[Dd];
    __shared__ float red[20];

    float s = 0.f, sq = 0.f;
    for (int i = tid; i < Dd; i += 256) {
        float v = a[(size_t)t * Dd + i] + r[(size_t)t * Dd + i];
        buf[i] = v;
        s += v; sq += v * v;
    }
#pragma unroll
    for (int o = 16; o; o >>= 1) {
        s  += __shfl_xor_sync(0xffffffffu, s, o);
        sq += __shfl_xor_sync(0xffffffffu, sq, o);
    }
    if ((tid & 31) == 0) { red[tid >> 5] = s; red[8 + (tid >> 5)] = sq; }
    __syncthreads();
    if (tid == 0) {
        float ts = 0.f, tq = 0.f;
        for (int i = 0; i < 8; i++) { ts += red[i]; tq += red[8 + i]; }
        const float mu  = ts * (1.0f / Dd);
        const float var = tq * (1.0f / Dd) - mu * mu;
        red[16] = mu;
        red[17] = rsqrtf(var + 1e-6f);
    }
    __syncthreads();
    const float mu = red[16], rstd = red[17];
    for (int i = tid; i < Dd; i += 256)
        out[(size_t)t * Dd + i] = (buf[i] - mu) * rstd * gamma[i] + beta[i];
}

// ---------------- launch ----------------
extern "C" void kernel_launch(void* const* d_in, const int* in_sizes, int n_in,
                              void* d_out, int out_size)
{
    const float* x   = (const float*)d_in[0];
    const float* Wq  = (const float*)d_in[1];
    const float* bq  = (const float*)d_in[2];
    const float* Wk  = (const float*)d_in[3];
    const float* bk  = (const float*)d_in[4];
    const float* Wv  = (const float*)d_in[5];
    const float* bv  = (const float*)d_in[6];
    const float* Wo  = (const float*)d_in[7];
    const float* bo  = (const float*)d_in[8];
    const float* g1  = (const float*)d_in[9];
    const float* b1  = (const float*)d_in[10];
    const float* Wup = (const float*)d_in[11];
    const float* bup = (const float*)d_in[12];
    const float* Wdn = (const float*)d_in[13];
    const float* bdn = (const float*)d_in[14];
    const float* g2  = (const float*)d_in[15];
    const float* b2  = (const float*)d_in[16];
    float* out = (float*)d_out;

    float *q, *k, *v, *mid, *proj, *x1, *up;
    cudaGetSymbolAddress((void**)&q,    g_q);
    cudaGetSymbolAddress((void**)&k,    g_k);
    cudaGetSymbolAddress((void**)&v,    g_v);
    cudaGetSymbolAddress((void**)&mid,  g_mid);
    cudaGetSymbolAddress((void**)&proj, g_proj);
    cudaGetSymbolAddress((void**)&x1,   g_x1);
    cudaGetSymbolAddress((void**)&up,   g_up);

    const dim3 blk(256);
    const dim3 gridD(Dd / 128, Tt / 128);
    const dim3 gridF(DFF / 128, Tt / 128);

    gemm_f16<0><<<gridD, blk>>>(x, Wq, bq, q, Tt, Dd, Dd);
    gemm_f16<0><<<gridD, blk>>>(x, Wk, bk, k, Tt, Dd, Dd);
    gemm_f16<0><<<gridD, blk>>>(x, Wv, bv, v, Tt, Dd, Dd);

    attn_tc<<<dim3(Ss / 64, Bt * Hh), dim3(128)>>>(q, k, v, mid);

    gemm_f16<0><<<gridD, blk>>>(mid, Wo, bo, proj, Tt, Dd, Dd);
    add_ln_kernel<<<Tt, blk>>>(x, proj, g1, b1, x1);

    gemm_f16<1><<<gridF, blk>>>(x1, Wup, bup, up, Tt, DFF, Dd);
    gemm_f16<0><<<gridD, blk>>>(up, Wdn, bdn, proj, Tt, Dd, DFF);
    add_ln_kernel<<<Tt, blk>>>(x1, proj, g2, b2, out);
}

// round 6
// speedup vs baseline: 4.6850x; 1.2470x over previous
#include <cuda_runtime.h>
#include <cuda_fp16.h>
#include <cstdint>

#define Bt  2
#define Ss  2048
#define Dd  1024
#define Hh  16
#define HDd 64
#define Tt  (Bt * Ss)      // 4096 tokens
#define DFF (4 * Dd)       // 4096

// ---------------- scratch (device globals; no allocation allowed) ----------------
__device__ float g_q[Tt * Dd];
__device__ float g_k[Tt * Dd];
__device__ float g_v[Tt * Dd];
__device__ float g_mid[Tt * Dd];
__device__ float g_proj[Tt * Dd];
__device__ float g_x1[Tt * Dd];
__device__ float g_up[(size_t)Tt * DFF];

// ---------------- helpers ----------------
__device__ __forceinline__ void mma_f16(float* d, const uint32_t* a, const uint32_t* b) {
    asm volatile(
        "mma.sync.aligned.m16n8k16.row.col.f32.f16.f16.f32 "
        "{%0,%1,%2,%3}, {%4,%5,%6,%7}, {%8,%9}, {%0,%1,%2,%3};"
        : "+f"(d[0]), "+f"(d[1]), "+f"(d[2]), "+f"(d[3])
        : "r"(a[0]), "r"(a[1]), "r"(a[2]), "r"(a[3]), "r"(b[0]), "r"(b[1]));
}
__device__ __forceinline__ uint32_t sptr(const void* p) {
    return (uint32_t)__cvta_generic_to_shared(p);
}
__device__ __forceinline__ void ldsm_x4(uint32_t* r, uint32_t addr) {
    asm volatile("ldmatrix.sync.aligned.m8n8.x4.shared.b16 {%0,%1,%2,%3}, [%4];"
                 : "=r"(r[0]), "=r"(r[1]), "=r"(r[2]), "=r"(r[3]) : "r"(addr));
}
__device__ __forceinline__ void ldsm_x2t(uint32_t* r, uint32_t addr) {
    asm volatile("ldmatrix.sync.aligned.m8n8.x2.trans.shared.b16 {%0,%1}, [%2];"
                 : "=r"(r[0]), "=r"(r[1]) : "r"(addr));
}
__device__ __forceinline__ uint32_t packh2(float x, float y) {
    __half2 h = __floats2half2_rn(x, y);
    return *reinterpret_cast<uint32_t*>(&h);
}

// ---------------- FP16 tensor-core GEMM (unchanged from R5) ----------------
template <int RELU>
__global__ __launch_bounds__(256)
void gemm_f16(const float* __restrict__ A, const float* __restrict__ W,
              const float* __restrict__ bias, float* __restrict__ C,
              int M, int N, int K)
{
    __shared__ __half As[128][40];
    __shared__ __half Bs[32][136];

    const int tid  = threadIdx.x;
    const int lane = tid & 31;
    const int wid  = tid >> 5;
    const int wm   = (wid & 1) * 64;
    const int wn   = (wid >> 1) * 32;
    const int m0   = blockIdx.y << 7;
    const int n0   = blockIdx.x << 7;

    const int row = lane >> 2;
    const int col = lane & 3;

    float acc[4][4][4];
#pragma unroll
    for (int mi = 0; mi < 4; mi++)
#pragma unroll
        for (int ni = 0; ni < 4; ni++)
#pragma unroll
            for (int j = 0; j < 4; j++) acc[mi][ni][j] = 0.f;

    const int fa_r = tid >> 3;
    const int fa_q = (tid & 7) * 4;
    const int fb_r = tid >> 5;
    const int fb_c = (tid & 31) * 4;

    const int lrow = lane & 15;
    const int lcol = (lane >> 4) * 8;

    for (int k0 = 0; k0 < K; k0 += 32) {
#pragma unroll
        for (int rr = fa_r; rr < 128; rr += 32) {
            float4 v = *(const float4*)&A[(size_t)(m0 + rr) * K + k0 + fa_q];
            *(__half2*)&As[rr][fa_q]     = __floats2half2_rn(v.x, v.y);
            *(__half2*)&As[rr][fa_q + 2] = __floats2half2_rn(v.z, v.w);
        }
#pragma unroll
        for (int rr = fb_r; rr < 32; rr += 8) {
            float4 v = *(const float4*)&W[(size_t)(k0 + rr) * N + n0 + fb_c];
            *(__half2*)&Bs[rr][fb_c]     = __floats2half2_rn(v.x, v.y);
            *(__half2*)&Bs[rr][fb_c + 2] = __floats2half2_rn(v.z, v.w);
        }
        __syncthreads();

#pragma unroll
        for (int ks = 0; ks < 32; ks += 16) {
            uint32_t a[4][4], b[4][2];
#pragma unroll
            for (int mi = 0; mi < 4; mi++)
                ldsm_x4(a[mi], sptr(&As[wm + mi * 16 + lrow][ks + lcol]));
#pragma unroll
            for (int ni = 0; ni < 4; ni++)
                ldsm_x2t(b[ni], sptr(&Bs[ks + lrow][wn + ni * 8]));
#pragma unroll
            for (int mi = 0; mi < 4; mi++)
#pragma unroll
                for (int ni = 0; ni < 4; ni++)
                    mma_f16(acc[mi][ni], a[mi], b[ni]);
        }
        __syncthreads();
    }

#pragma unroll
    for (int mi = 0; mi < 4; mi++) {
        const int r0 = m0 + wm + mi * 16 + row;
#pragma unroll
        for (int ni = 0; ni < 4; ni++) {
            const int c0 = n0 + wn + ni * 8 + 2 * col;
            const float b0 = bias[c0], b1 = bias[c0 + 1];
            float2 v0, v1;
            v0.x = acc[mi][ni][0] + b0; v0.y = acc[mi][ni][1] + b1;
            v1.x = acc[mi][ni][2] + b0; v1.y = acc[mi][ni][3] + b1;
            if (RELU) {
                v0.x = fmaxf(v0.x, 0.f); v0.y = fmaxf(v0.y, 0.f);
                v1.x = fmaxf(v1.x, 0.f); v1.y = fmaxf(v1.y, 0.f);
            }
            *(float2*)&C[(size_t)r0 * N + c0]       = v0;
            *(float2*)&C[(size_t)(r0 + 8) * N + c0] = v1;
        }
    }
}

// ---------------- FP16 tensor-core causal flash attention ----------------
// CTA: 64 queries, 4 warps, key tile 64, Hd=64. m16n8k16 fp16, fp32 accum.
// P stays in registers (S C-fragments == PV A-fragments); no P smem staging.
__global__ __launch_bounds__(128)
void attn_f16(const float* __restrict__ Qg, const float* __restrict__ Kg,
              const float* __restrict__ Vg, float* __restrict__ Og)
{
    __shared__ __half Ks[64][72];   // [key][dim]; doubles as Q staging in prologue
    __shared__ __half Vs[64][72];   // [key][dim]

    const int tid  = threadIdx.x;
    const int lane = tid & 31;
    const int wid  = tid >> 5;            // 0..3
    const int g    = lane >> 2;           // 0..7
    const int t    = lane & 3;            // 0..3
    const int lrow = lane & 15;           // ldmatrix row
    const int qb   = blockIdx.x;
    const int bh   = blockIdx.y;
    const int b    = bh >> 4, h = bh & 15;

    const float* Qb = Qg + (size_t)b * Ss * Dd + h * HDd;
    const float* Kb = Kg + (size_t)b * Ss * Dd + h * HDd;
    const float* Vb = Vg + (size_t)b * Ss * Dd + h * HDd;

    // ---- prologue: stage Q (scaled, fp16) through Ks, build A fragments ----
    for (int i = tid; i < 64 * 16; i += 128) {
        const int r = i >> 4, c4 = (i & 15) << 2;
        float4 v = *(const float4*)&Qb[(size_t)(qb * 64 + r) * Dd + c4];
        *(__half2*)&Ks[r][c4]     = __floats2half2_rn(v.x * 0.125f, v.y * 0.125f);
        *(__half2*)&Ks[r][c4 + 2] = __floats2half2_rn(v.z * 0.125f, v.w * 0.125f);
    }
    __syncthreads();

    uint32_t qf[4][4];   // 4 k16 steps over Hd=64
    {
        const int qr = wid * 16 + g;
#pragma unroll
        for (int s = 0; s < 4; s++) {
            qf[s][0] = *(const uint32_t*)&Ks[qr][s * 16 + 2 * t];
            qf[s][1] = *(const uint32_t*)&Ks[qr + 8][s * 16 + 2 * t];
            qf[s][2] = *(const uint32_t*)&Ks[qr][s * 16 + 2 * t + 8];
            qf[s][3] = *(const uint32_t*)&Ks[qr + 8][s * 16 + 2 * t + 8];
        }
    }

    float m0 = -1e30f, m1 = -1e30f, l0 = 0.f, l1 = 0.f;
    float O[8][4];
#pragma unroll
    for (int n = 0; n < 8; n++)
#pragma unroll
        for (int j = 0; j < 4; j++) O[n][j] = 0.f;

    const int lq0 = wid * 16 + g;
    const int lq1 = lq0 + 8;

    const int nkt = qb + 1;
    for (int kt = 0; kt < nkt; kt++) {
        __syncthreads();   // previous iteration's Ks/Vs reads done (and Q staging)
        for (int i = tid; i < 64 * 16; i += 128) {
            const int r = i >> 4, c4 = (i & 15) << 2;
            float4 kv = *(const float4*)&Kb[(size_t)(kt * 64 + r) * Dd + c4];
            float4 vv = *(const float4*)&Vb[(size_t)(kt * 64 + r) * Dd + c4];
            *(__half2*)&Ks[r][c4]     = __floats2half2_rn(kv.x, kv.y);
            *(__half2*)&Ks[r][c4 + 2] = __floats2half2_rn(kv.z, kv.w);
            *(__half2*)&Vs[r][c4]     = __floats2half2_rn(vv.x, vv.y);
            *(__half2*)&Vs[r][c4 + 2] = __floats2half2_rn(vv.z, vv.w);
        }
        __syncthreads();

        // ---- S = Q @ K^T : 8 n-tiles x 4 k16 steps ----
        float S[8][4];
#pragma unroll
        for (int n = 0; n < 8; n++)
#pragma unroll
            for (int j = 0; j < 4; j++) S[n][j] = 0.f;

#pragma unroll
        for (int s = 0; s < 4; s++) {
#pragma unroll
            for (int n = 0; n < 8; n++) {
                uint32_t bq[2];
                bq[0] = *(const uint32_t*)&Ks[n * 8 + g][s * 16 + 2 * t];
                bq[1] = *(const uint32_t*)&Ks[n * 8 + g][s * 16 + 2 * t + 8];
                mma_f16(S[n], qf[s], bq);
            }
        }

        // ---- causal mask (diagonal tile only) ----
        if (kt == qb) {
#pragma unroll
            for (int n = 0; n < 8; n++) {
                const int kc = n * 8 + 2 * t;
                if (kc     > lq0) S[n][0] = -1e30f;
                if (kc + 1 > lq0) S[n][1] = -1e30f;
                if (kc     > lq1) S[n][2] = -1e30f;
                if (kc + 1 > lq1) S[n][3] = -1e30f;
            }
        }

        // ---- online softmax (rows lq0, lq1; quad reduction) ----
        float mx0 = -1e30f, mx1 = -1e30f;
#pragma unroll
        for (int n = 0; n < 8; n++) {
            mx0 = fmaxf(mx0, fmaxf(S[n][0], S[n][1]));
            mx1 = fmaxf(mx1, fmaxf(S[n][2], S[n][3]));
        }
        mx0 = fmaxf(mx0, __shfl_xor_sync(0xffffffffu, mx0, 1));
        mx0 = fmaxf(mx0, __shfl_xor_sync(0xffffffffu, mx0, 2));
        mx1 = fmaxf(mx1, __shfl_xor_sync(0xffffffffu, mx1, 1));
        mx1 = fmaxf(mx1, __shfl_xor_sync(0xffffffffu, mx1, 2));

        const float mn0 = fmaxf(m0, mx0), mn1 = fmaxf(m1, mx1);
        const float fac0 = __expf(m0 - mn0), fac1 = __expf(m1 - mn1);

        float s0 = 0.f, s1 = 0.f;
#pragma unroll
        for (int n = 0; n < 8; n++) {
            S[n][0] = __expf(S[n][0] - mn0);
            S[n][1] = __expf(S[n][1] - mn0);
            S[n][2] = __expf(S[n][2] - mn1);
            S[n][3] = __expf(S[n][3] - mn1);
            s0 += S[n][0] + S[n][1];
            s1 += S[n][2] + S[n][3];
        }
        s0 += __shfl_xor_sync(0xffffffffu, s0, 1);
        s0 += __shfl_xor_sync(0xffffffffu, s0, 2);
        s1 += __shfl_xor_sync(0xffffffffu, s1, 1);
        s1 += __shfl_xor_sync(0xffffffffu, s1, 2);

        l0 = l0 * fac0 + s0;
        l1 = l1 * fac1 + s1;
        m0 = mn0; m1 = mn1;

#pragma unroll
        for (int n = 0; n < 8; n++) {
            O[n][0] *= fac0; O[n][1] *= fac0;
            O[n][2] *= fac1; O[n][3] *= fac1;
        }

        // ---- O += P @ V : P packed from S fragments in registers ----
#pragma unroll
        for (int kk = 0; kk < 4; kk++) {
            uint32_t pa[4];
            pa[0] = packh2(S[2 * kk][0],     S[2 * kk][1]);
            pa[1] = packh2(S[2 * kk][2],     S[2 * kk][3]);
            pa[2] = packh2(S[2 * kk + 1][0], S[2 * kk + 1][1]);
            pa[3] = packh2(S[2 * kk + 1][2], S[2 * kk + 1][3]);
#pragma unroll
            for (int nd = 0; nd < 8; nd++) {
                uint32_t bv[2];
                ldsm_x2t(bv, sptr(&Vs[kk * 16 + lrow][nd * 8]));
                mma_f16(O[nd], pa, bv);
            }
        }
    }

    // ---- epilogue ----
    const float inv0 = 1.f / l0, inv1 = 1.f / l1;
    const int q0 = qb * 64 + lq0;
    float* o0 = Og + (size_t)(b * Ss + q0) * Dd + h * HDd;
    float* o1 = o0 + 8 * Dd;
#pragma unroll
    for (int nd = 0; nd < 8; nd++) {
        const int c0 = nd * 8 + 2 * t;
        float2 v0, v1;
        v0.x = O[nd][0] * inv0; v0.y = O[nd][1] * inv0;
        v1.x = O[nd][2] * inv1; v1.y = O[nd][3] * inv1;
        *(float2*)&o0[c0] = v0;
        *(float2*)&o1[c0] = v1;
    }
}

// ---------------- residual add + LayerNorm ----------------
__global__ __launch_bounds__(256)
void add_ln_kernel(const float* __restrict__ a, const float* __restrict__ r,
                   const float* __restrict__ gamma, const float* __restrict__ beta,
                   float* __restrict__ out)
{
    const int t = blockIdx.x;
    const int tid = threadIdx.x;
    __shared__ float buf[Dd];
    __shared__ float red[20];

    float s = 0.f, sq = 0.f;
    for (int i = tid; i < Dd; i += 256) {
        float v = a[(size_t)t * Dd + i] + r[(size_t)t * Dd + i];
        buf[i] = v;
        s += v; sq += v * v;
    }
#pragma unroll
    for (int o = 16; o; o >>= 1) {
        s  += __shfl_xor_sync(0xffffffffu, s, o);
        sq += __shfl_xor_sync(0xffffffffu, sq, o);
    }
    if ((tid & 31) == 0) { red[tid >> 5] = s; red[8 + (tid >> 5)] = sq; }
    __syncthreads();
    if (tid == 0) {
        float ts = 0.f, tq = 0.f;
        for (int i = 0; i < 8; i++) { ts += red[i]; tq += red[8 + i]; }
        const float mu  = ts * (1.0f / Dd);
        const float var = tq * (1.0f / Dd) - mu * mu;
        red[16] = mu;
        red[17] = rsqrtf(var + 1e-6f);
    }
    __syncthreads();
    const float mu = red[16], rstd = red[17];
    for (int i = tid; i < Dd; i += 256)
        out[(size_t)t * Dd + i] = (buf[i] - mu) * rstd * gamma[i] + beta[i];
}

// ---------------- launch ----------------
extern "C" void kernel_launch(void* const* d_in, const int* in_sizes, int n_in,
                              void* d_out, int out_size)
{
    const float* x   = (const float*)d_in[0];
    const float* Wq  = (const float*)d_in[1];
    const float* bq  = (const float*)d_in[2];
    const float* Wk  = (const float*)d_in[3];
    const float* bk  = (const float*)d_in[4];
    const float* Wv  = (const float*)d_in[5];
    const float* bv  = (const float*)d_in[6];
    const float* Wo  = (const float*)d_in[7];
    const float* bo  = (const float*)d_in[8];
    const float* g1  = (const float*)d_in[9];
    const float* b1  = (const float*)d_in[10];
    const float* Wup = (const float*)d_in[11];
    const float* bup = (const float*)d_in[12];
    const float* Wdn = (const float*)d_in[13];
    const float* bdn = (const float*)d_in[14];
    const float* g2  = (const float*)d_in[15];
    const float* b2  = (const float*)d_in[16];
    float* out = (float*)d_out;

    float *q, *k, *v, *mid, *proj, *x1, *up;
    cudaGetSymbolAddress((void**)&q,    g_q);
    cudaGetSymbolAddress((void**)&k,    g_k);
    cudaGetSymbolAddress((void**)&v,    g_v);
    cudaGetSymbolAddress((void**)&mid,  g_mid);
    cudaGetSymbolAddress((void**)&proj, g_proj);
    cudaGetSymbolAddress((void**)&x1,   g_x1);
    cudaGetSymbolAddress((void**)&up,   g_up);

    const dim3 blk(256);
    const dim3 gridD(Dd / 128, Tt / 128);
    const dim3 gridF(DFF / 128, Tt / 128);

    gemm_f16<0><<<gridD, blk>>>(x, Wq, bq, q, Tt, Dd, Dd);
    gemm_f16<0><<<gridD, blk>>>(x, Wk, bk, k, Tt, Dd, Dd);
    gemm_f16<0><<<gridD, blk>>>(x, Wv, bv, v, Tt, Dd, Dd);

    attn_f16<<<dim3(Ss / 64, Bt * Hh), dim3(128)>>>(q, k, v, mid);

    gemm_f16<0><<<gridD, blk>>>(mid, Wo, bo, proj, Tt, Dd, Dd);
    add_ln_kernel<<<Tt, blk>>>(x, proj, g1, b1, x1);

    gemm_f16<1><<<gridF, blk>>>(x1, Wup, bup, up, Tt, DFF, Dd);
    gemm_f16<0><<<gridD, blk>>>(up, Wdn, bdn, proj, Tt, Dd, DFF);
    add_ln_kernel<<<Tt, blk>>>(x1, proj, g2, b2, out);
}

// round 7
// speedup vs baseline: 5.9812x; 1.2767x over previous
#include <cuda_runtime.h>
#include <cuda_fp16.h>
#include <cstdint>

#define Bt  2
#define Ss  2048
#define Dd  1024
#define Hh  16
#define HDd 64
#define Tt  (Bt * Ss)      // 4096 tokens
#define DFF (4 * Dd)       // 4096

// ---------------- scratch (device globals; no allocation allowed) ----------------
__device__ float  g_proj[Tt * Dd];
__device__ float  g_x1[Tt * Dd];
__device__ __half g_xh[Tt * Dd];
__device__ __half g_wqh[Dd * Dd];
__device__ __half g_wkh[Dd * Dd];
__device__ __half g_wvh[Dd * Dd];
__device__ __half g_woh[Dd * Dd];
__device__ __half g_wuph[(size_t)Dd * DFF];
__device__ __half g_wdnh[(size_t)DFF * Dd];
__device__ __half g_qh[Tt * Dd];
__device__ __half g_kh[Tt * Dd];
__device__ __half g_vh[Tt * Dd];
__device__ __half g_midh[Tt * Dd];
__device__ __half g_x1h[Tt * Dd];
__device__ __half g_uph[(size_t)Tt * DFF];

// ---------------- helpers ----------------
__device__ __forceinline__ void mma_f16(float* d, const uint32_t* a, const uint32_t* b) {
    asm volatile(
        "mma.sync.aligned.m16n8k16.row.col.f32.f16.f16.f32 "
        "{%0,%1,%2,%3}, {%4,%5,%6,%7}, {%8,%9}, {%0,%1,%2,%3};"
        : "+f"(d[0]), "+f"(d[1]), "+f"(d[2]), "+f"(d[3])
        : "r"(a[0]), "r"(a[1]), "r"(a[2]), "r"(a[3]), "r"(b[0]), "r"(b[1]));
}
__device__ __forceinline__ uint32_t sptr(const void* p) {
    return (uint32_t)__cvta_generic_to_shared(p);
}
__device__ __forceinline__ void ldsm_x4(uint32_t* r, uint32_t addr) {
    asm volatile("ldmatrix.sync.aligned.m8n8.x4.shared.b16 {%0,%1,%2,%3}, [%4];"
                 : "=r"(r[0]), "=r"(r[1]), "=r"(r[2]), "=r"(r[3]) : "r"(addr));
}
__device__ __forceinline__ void ldsm_x2t(uint32_t* r, uint32_t addr) {
    asm volatile("ldmatrix.sync.aligned.m8n8.x2.trans.shared.b16 {%0,%1}, [%2];"
                 : "=r"(r[0]), "=r"(r[1]) : "r"(addr));
}
__device__ __forceinline__ uint32_t packh2(float x, float y) {
    __half2 h = __floats2half2_rn(x, y);
    return *reinterpret_cast<uint32_t*>(&h);
}
__device__ __forceinline__ void cp_async16(uint32_t dst, const void* src) {
    asm volatile("cp.async.cg.shared.global [%0], [%1], 16;" :: "r"(dst), "l"(src));
}
__device__ __forceinline__ void cp_commit() {
    asm volatile("cp.async.commit_group;" ::: "memory");
}
template <int N>
__device__ __forceinline__ void cp_wait() {
    asm volatile("cp.async.wait_group %0;" :: "n"(N) : "memory");
}

// ---------------- fp32 -> fp16 converter ----------------
__global__ __launch_bounds__(256)
void f2h_kernel(const float* __restrict__ in, __half* __restrict__ out, int n)
{
    const int i = (blockIdx.x * 256 + threadIdx.x) * 4;
    if (i < n) {
        float4 v = *(const float4*)&in[i];
        *(__half2*)&out[i]     = __floats2half2_rn(v.x, v.y);
        *(__half2*)&out[i + 2] = __floats2half2_rn(v.z, v.w);
    }
}

// ---------------- FP16 GEMM, cp.async double-buffered ----------------
// C[M,N] = A[M,K] @ W[K,N] + bias (+ReLU). A, W fp16; acc fp32; out fp16 or fp32.
// Block 128x128, K-chunk 32 (2 x k16), 256 threads = 8 warps (2m x 4n).
template <int RELU, int OUTH>
__global__ __launch_bounds__(256)
void gemm_h(const __half* __restrict__ A, const __half* __restrict__ W,
            const float* __restrict__ bias, void* __restrict__ Cout,
            int M, int N, int K)
{
    __shared__ __half As[2][128][40];    // 80B stride: conflict-free ldsm
    __shared__ __half Bs[2][32][136];    // 272B stride: conflict-free ldsm.trans

    const int tid  = threadIdx.x;
    const int lane = tid & 31;
    const int wid  = tid >> 5;
    const int wm   = (wid & 1) * 64;
    const int wn   = (wid >> 1) * 32;
    const int m0   = blockIdx.y << 7;
    const int n0   = blockIdx.x << 7;

    const int row  = lane >> 2;
    const int col  = lane & 3;
    const int lrow = lane & 15;
    const int lcol = (lane >> 4) * 8;

    // cp.async chunk assignment (2 A-chunks + 2 B-chunks per thread per tile)
    const int a_r = tid >> 2;            // 0..63  (A rows; +64 for second)
    const int a_e = (tid & 3) * 8;       // A elem offset within 32-k row
    const int b_r = tid >> 4;            // 0..15  (B k-rows; +16 for second)
    const int b_e = (tid & 15) * 8;      // B elem offset within 128-n row

    float acc[4][4][4];
#pragma unroll
    for (int mi = 0; mi < 4; mi++)
#pragma unroll
        for (int ni = 0; ni < 4; ni++)
#pragma unroll
            for (int j = 0; j < 4; j++) acc[mi][ni][j] = 0.f;

    const int nk = K >> 5;

    auto load_stage = [&](int c, int st) {
        const __half* Ab = A + (size_t)(m0 + a_r) * K + (c << 5) + a_e;
        cp_async16(sptr(&As[st][a_r][a_e]),      Ab);
        cp_async16(sptr(&As[st][a_r + 64][a_e]), Ab + (size_t)64 * K);
        const __half* Bb = W + (size_t)((c << 5) + b_r) * N + n0 + b_e;
        cp_async16(sptr(&Bs[st][b_r][b_e]),      Bb);
        cp_async16(sptr(&Bs[st][b_r + 16][b_e]), Bb + (size_t)16 * N);
    };

    load_stage(0, 0);
    cp_commit();

    for (int c = 0; c < nk; c++) {
        const int st = c & 1;
        if (c + 1 < nk) {
            load_stage(c + 1, st ^ 1);
            cp_commit();
            cp_wait<1>();
        } else {
            cp_wait<0>();
        }
        __syncthreads();

#pragma unroll
        for (int ks = 0; ks < 32; ks += 16) {
            uint32_t a[4][4], b[4][2];
#pragma unroll
            for (int mi = 0; mi < 4; mi++)
                ldsm_x4(a[mi], sptr(&As[st][wm + mi * 16 + lrow][ks + lcol]));
#pragma unroll
            for (int ni = 0; ni < 4; ni++)
                ldsm_x2t(b[ni], sptr(&Bs[st][ks + lrow][wn + ni * 8]));
#pragma unroll
            for (int mi = 0; mi < 4; mi++)
#pragma unroll
                for (int ni = 0; ni < 4; ni++)
                    mma_f16(acc[mi][ni], a[mi], b[ni]);
        }
        __syncthreads();
    }

    // epilogue
#pragma unroll
    for (int mi = 0; mi < 4; mi++) {
        const int r0 = m0 + wm + mi * 16 + row;
#pragma unroll
        for (int ni = 0; ni < 4; ni++) {
            const int c0 = n0 + wn + ni * 8 + 2 * col;
            const float b0 = bias[c0], b1 = bias[c0 + 1];
            float v00 = acc[mi][ni][0] + b0, v01 = acc[mi][ni][1] + b1;
            float v10 = acc[mi][ni][2] + b0, v11 = acc[mi][ni][3] + b1;
            if (RELU) {
                v00 = fmaxf(v00, 0.f); v01 = fmaxf(v01, 0.f);
                v10 = fmaxf(v10, 0.f); v11 = fmaxf(v11, 0.f);
            }
            if (OUTH) {
                __half* Ch = (__half*)Cout;
                *(__half2*)&Ch[(size_t)r0 * N + c0]       = __floats2half2_rn(v00, v01);
                *(__half2*)&Ch[(size_t)(r0 + 8) * N + c0] = __floats2half2_rn(v10, v11);
            } else {
                float* Cf = (float*)Cout;
                *(float2*)&Cf[(size_t)r0 * N + c0]       = make_float2(v00, v01);
                *(float2*)&Cf[(size_t)(r0 + 8) * N + c0] = make_float2(v10, v11);
            }
        }
    }
}

// ---------------- FP16 causal flash attention (fp16 in/out) ----------------
__global__ __launch_bounds__(128)
void attn_f16(const __half* __restrict__ Qg, const __half* __restrict__ Kg,
              const __half* __restrict__ Vg, __half* __restrict__ Og)
{
    __shared__ __half Ks[64][72];   // [key][dim]; doubles as Q staging in prologue
    __shared__ __half Vs[64][72];

    const int tid  = threadIdx.x;
    const int lane = tid & 31;
    const int wid  = tid >> 5;
    const int g    = lane >> 2;
    const int t    = lane & 3;
    const int lrow = lane & 15;
    const int qb   = blockIdx.x;
    const int bh   = blockIdx.y;
    const int b    = bh >> 4, h = bh & 15;

    const __half* Qb = Qg + (size_t)b * Ss * Dd + h * HDd;
    const __half* Kb = Kg + (size_t)b * Ss * Dd + h * HDd;
    const __half* Vb = Vg + (size_t)b * Ss * Dd + h * HDd;

    // ---- prologue: stage Q (scaled) through Ks, build A fragments ----
    const __half2 hs = __floats2half2_rn(0.125f, 0.125f);
    for (int i = tid; i < 64 * 8; i += 128) {
        const int r = i >> 3, c8 = (i & 7) * 8;
        uint4 q4 = *(const uint4*)&Qb[(size_t)(qb * 64 + r) * Dd + c8];
        __half2* p = (__half2*)&q4;
        p[0] = __hmul2(p[0], hs); p[1] = __hmul2(p[1], hs);
        p[2] = __hmul2(p[2], hs); p[3] = __hmul2(p[3], hs);
        *(uint4*)&Ks[r][c8] = q4;
    }
    __syncthreads();

    uint32_t qf[4][4];
    {
        const int qr = wid * 16 + g;
#pragma unroll
        for (int s = 0; s < 4; s++) {
            qf[s][0] = *(const uint32_t*)&Ks[qr][s * 16 + 2 * t];
            qf[s][1] = *(const uint32_t*)&Ks[qr + 8][s * 16 + 2 * t];
            qf[s][2] = *(const uint32_t*)&Ks[qr][s * 16 + 2 * t + 8];
            qf[s][3] = *(const uint32_t*)&Ks[qr + 8][s * 16 + 2 * t + 8];
        }
    }

    float m0 = -1e30f, m1 = -1e30f, l0 = 0.f, l1 = 0.f;
    float O[8][4];
#pragma unroll
    for (int n = 0; n < 8; n++)
#pragma unroll
        for (int j = 0; j < 4; j++) O[n][j] = 0.f;

    const int lq0 = wid * 16 + g;
    const int lq1 = lq0 + 8;

    const int nkt = qb + 1;
    for (int kt = 0; kt < nkt; kt++) {
        __syncthreads();
        for (int i = tid; i < 64 * 8; i += 128) {
            const int r = i >> 3, c8 = (i & 7) * 8;
            const size_t off = (size_t)(kt * 64 + r) * Dd + c8;
            *(uint4*)&Ks[r][c8] = *(const uint4*)&Kb[off];
            *(uint4*)&Vs[r][c8] = *(const uint4*)&Vb[off];
        }
        __syncthreads();

        // ---- S = Q @ K^T ----
        float S[8][4];
#pragma unroll
        for (int n = 0; n < 8; n++)
#pragma unroll
            for (int j = 0; j < 4; j++) S[n][j] = 0.f;

#pragma unroll
        for (int s = 0; s < 4; s++) {
#pragma unroll
            for (int n = 0; n < 8; n++) {
                uint32_t bq[2];
                bq[0] = *(const uint32_t*)&Ks[n * 8 + g][s * 16 + 2 * t];
                bq[1] = *(const uint32_t*)&Ks[n * 8 + g][s * 16 + 2 * t + 8];
                mma_f16(S[n], qf[s], bq);
            }
        }

        // ---- causal mask (diagonal tile only) ----
        if (kt == qb) {
#pragma unroll
            for (int n = 0; n < 8; n++) {
                const int kc = n * 8 + 2 * t;
                if (kc     > lq0) S[n][0] = -1e30f;
                if (kc + 1 > lq0) S[n][1] = -1e30f;
                if (kc     > lq1) S[n][2] = -1e30f;
                if (kc + 1 > lq1) S[n][3] = -1e30f;
            }
        }

        // ---- online softmax ----
        float mx0 = -1e30f, mx1 = -1e30f;
#pragma unroll
        for (int n = 0; n < 8; n++) {
            mx0 = fmaxf(mx0, fmaxf(S[n][0], S[n][1]));
            mx1 = fmaxf(mx1, fmaxf(S[n][2], S[n][3]));
        }
        mx0 = fmaxf(mx0, __shfl_xor_sync(0xffffffffu, mx0, 1));
        mx0 = fmaxf(mx0, __shfl_xor_sync(0xffffffffu, mx0, 2));
        mx1 = fmaxf(mx1, __shfl_xor_sync(0xffffffffu, mx1, 1));
        mx1 = fmaxf(mx1, __shfl_xor_sync(0xffffffffu, mx1, 2));

        const float mn0 = fmaxf(m0, mx0), mn1 = fmaxf(m1, mx1);
        const float fac0 = __expf(m0 - mn0), fac1 = __expf(m1 - mn1);

        float s0 = 0.f, s1 = 0.f;
#pragma unroll
        for (int n = 0; n < 8; n++) {
            S[n][0] = __expf(S[n][0] - mn0);
            S[n][1] = __expf(S[n][1] - mn0);
            S[n][2] = __expf(S[n][2] - mn1);
            S[n][3] = __expf(S[n][3] - mn1);
            s0 += S[n][0] + S[n][1];
            s1 += S[n][2] + S[n][3];
        }
        s0 += __shfl_xor_sync(0xffffffffu, s0, 1);
        s0 += __shfl_xor_sync(0xffffffffu, s0, 2);
        s1 += __shfl_xor_sync(0xffffffffu, s1, 1);
        s1 += __shfl_xor_sync(0xffffffffu, s1, 2);

        l0 = l0 * fac0 + s0;
        l1 = l1 * fac1 + s1;
        m0 = mn0; m1 = mn1;

#pragma unroll
        for (int n = 0; n < 8; n++) {
            O[n][0] *= fac0; O[n][1] *= fac0;
            O[n][2] *= fac1; O[n][3] *= fac1;
        }

        // ---- O += P @ V (P packed in registers) ----
#pragma unroll
        for (int kk = 0; kk < 4; kk++) {
            uint32_t pa[4];
            pa[0] = packh2(S[2 * kk][0],     S[2 * kk][1]);
            pa[1] = packh2(S[2 * kk][2],     S[2 * kk][3]);
            pa[2] = packh2(S[2 * kk + 1][0], S[2 * kk + 1][1]);
            pa[3] = packh2(S[2 * kk + 1][2], S[2 * kk + 1][3]);
#pragma unroll
            for (int nd = 0; nd < 8; nd++) {
                uint32_t bv[2];
                ldsm_x2t(bv, sptr(&Vs[kk * 16 + lrow][nd * 8]));
                mma_f16(O[nd], pa, bv);
            }
        }
    }

    // ---- epilogue (fp16 out) ----
    const float inv0 = 1.f / l0, inv1 = 1.f / l1;
    const int q0 = qb * 64 + lq0;
    __half* o0 = Og + (size_t)(b * Ss + q0) * Dd + h * HDd;
    __half* o1 = o0 + 8 * Dd;
#pragma unroll
    for (int nd = 0; nd < 8; nd++) {
        const int c0 = nd * 8 + 2 * t;
        *(__half2*)&o0[c0] = __floats2half2_rn(O[nd][0] * inv0, O[nd][1] * inv0);
        *(__half2*)&o1[c0] = __floats2half2_rn(O[nd][2] * inv1, O[nd][3] * inv1);
    }
}

// ---------------- residual add + LayerNorm (optional fp16 mirror) ----------------
template <int DUAL>
__global__ __launch_bounds__(256)
void add_ln_kernel(const float* __restrict__ a, const float* __restrict__ r,
                   const float* __restrict__ gamma, const float* __restrict__ beta,
                   float* __restrict__ out, __half* __restrict__ outh)
{
    const int t = blockIdx.x;
    const int tid = threadIdx.x;
    __shared__ float buf[Dd];
    __shared__ float red[20];

    float s = 0.f, sq = 0.f;
    for (int i = tid; i < Dd; i += 256) {
        float v = a[(size_t)t * Dd + i] + r[(size_t)t * Dd + i];
        buf[i] = v;
        s += v; sq += v * v;
    }
#pragma unroll
    for (int o = 16; o; o >>= 1) {
        s  += __shfl_xor_sync(0xffffffffu, s, o);
        sq += __shfl_xor_sync(0xffffffffu, sq, o);
    }
    if ((tid & 31) == 0) { red[tid >> 5] = s; red[8 + (tid >> 5)] = sq; }
    __syncthreads();
    if (tid == 0) {
        float ts = 0.f, tq = 0.f;
        for (int i = 0; i < 8; i++) { ts += red[i]; tq += red[8 + i]; }
        const float mu  = ts * (1.0f / Dd);
        const float var = tq * (1.0f / Dd) - mu * mu;
        red[16] = mu;
        red[17] = rsqrtf(var + 1e-6f);
    }
    __syncthreads();
    const float mu = red[16], rstd = red[17];
    for (int i = tid; i < Dd; i += 256) {
        const float v = (buf[i] - mu) * rstd * gamma[i] + beta[i];
        out[(size_t)t * Dd + i] = v;
        if (DUAL) outh[(size_t)t * Dd + i] = __float2half_rn(v);
    }
}

// ---------------- launch ----------------
extern "C" void kernel_launch(void* const* d_in, const int* in_sizes, int n_in,
                              void* d_out, int out_size)
{
    const float* x   = (const float*)d_in[0];
    const float* Wq  = (const float*)d_in[1];
    const float* bq  = (const float*)d_in[2];
    const float* Wk  = (const float*)d_in[3];
    const float* bk  = (const float*)d_in[4];
    const float* Wv  = (const float*)d_in[5];
    const float* bv  = (const float*)d_in[6];
    const float* Wo  = (const float*)d_in[7];
    const float* bo  = (const float*)d_in[8];
    const float* g1  = (const float*)d_in[9];
    const float* b1  = (const float*)d_in[10];
    const float* Wup = (const float*)d_in[11];
    const float* bup = (const float*)d_in[12];
    const float* Wdn = (const float*)d_in[13];
    const float* bdn = (const float*)d_in[14];
    const float* g2  = (const float*)d_in[15];
    const float* b2  = (const float*)d_in[16];
    float* out = (float*)d_out;

    float *proj, *x1;
    __half *xh, *wqh, *wkh, *wvh, *woh, *wuph, *wdnh;
    __half *qh, *kh, *vh, *midh, *x1h, *uph;
    cudaGetSymbolAddress((void**)&proj, g_proj);
    cudaGetSymbolAddress((void**)&x1,   g_x1);
    cudaGetSymbolAddress((void**)&xh,   g_xh);
    cudaGetSymbolAddress((void**)&wqh,  g_wqh);
    cudaGetSymbolAddress((void**)&wkh,  g_wkh);
    cudaGetSymbolAddress((void**)&wvh,  g_wvh);
    cudaGetSymbolAddress((void**)&woh,  g_woh);
    cudaGetSymbolAddress((void**)&wuph, g_wuph);
    cudaGetSymbolAddress((void**)&wdnh, g_wdnh);
    cudaGetSymbolAddress((void**)&qh,   g_qh);
    cudaGetSymbolAddress((void**)&kh,   g_kh);
    cudaGetSymbolAddress((void**)&vh,   g_vh);
    cudaGetSymbolAddress((void**)&midh, g_midh);
    cudaGetSymbolAddress((void**)&x1h,  g_x1h);
    cudaGetSymbolAddress((void**)&uph,  g_uph);

    const dim3 blk(256);
    const dim3 gridD(Dd / 128, Tt / 128);
    const dim3 gridF(DFF / 128, Tt / 128);

    // fp32 -> fp16 conversions (weights + x)
    f2h_kernel<<<Tt * Dd / 1024, blk>>>(x,   xh,   Tt * Dd);
    f2h_kernel<<<Dd * Dd / 1024, blk>>>(Wq,  wqh,  Dd * Dd);
    f2h_kernel<<<Dd * Dd / 1024, blk>>>(Wk,  wkh,  Dd * Dd);
    f2h_kernel<<<Dd * Dd / 1024, blk>>>(Wv,  wvh,  Dd * Dd);
    f2h_kernel<<<Dd * Dd / 1024, blk>>>(Wo,  woh,  Dd * Dd);
    f2h_kernel<<<Dd * DFF / 1024, blk>>>(Wup, wuph, Dd * DFF);
    f2h_kernel<<<DFF * Dd / 1024, blk>>>(Wdn, wdnh, DFF * Dd);

    // QKV projections (fp16 out)
    gemm_h<0, 1><<<gridD, blk>>>(xh, wqh, bq, qh, Tt, Dd, Dd);
    gemm_h<0, 1><<<gridD, blk>>>(xh, wkh, bk, kh, Tt, Dd, Dd);
    gemm_h<0, 1><<<gridD, blk>>>(xh, wvh, bv, vh, Tt, Dd, Dd);

    // causal attention (fp16 in/out)
    attn_f16<<<dim3(Ss / 64, Bt * Hh), dim3(128)>>>(qh, kh, vh, midh);

    // output projection (fp32 out) + residual LN1 (dual out)
    gemm_h<0, 0><<<gridD, blk>>>(midh, woh, bo, proj, Tt, Dd, Dd);
    add_ln_kernel<1><<<Tt, blk>>>(x, proj, g1, b1, x1, x1h);

    // FFN
    gemm_h<1, 1><<<gridF, blk>>>(x1h, wuph, bup, uph, Tt, DFF, Dd);
    gemm_h<0, 0><<<gridD, blk>>>(uph, wdnh, bdn, proj, Tt, Dd, DFF);
    add_ln_kernel<0><<<Tt, blk>>>(x1, proj, g2, b2, out, nullptr);
}

// round 8
// speedup vs baseline: 6.2452x; 1.0441x over previous
#include <cuda_runtime.h>
#include <cuda_fp16.h>
#include <cstdint>

#define Bt  2
#define Ss  2048
#define Dd  1024
#define Hh  16
#define HDd 64
#define Tt  (Bt * Ss)      // 4096 tokens
#define DFF (4 * Dd)       // 4096
#define QKVS (3 * Dd)      // 3072: row stride of fused qkv output

// ---------------- scratch (device globals; no allocation allowed) ----------------
__device__ float  g_proj[Tt * Dd];
__device__ float  g_x1[Tt * Dd];
__device__ float  g_bqkv[QKVS];
__device__ __half g_xh[Tt * Dd];
__device__ __half g_wqkvh[(size_t)Dd * QKVS];
__device__ __half g_woh[Dd * Dd];
__device__ __half g_wuph[(size_t)Dd * DFF];
__device__ __half g_wdnh[(size_t)DFF * Dd];
__device__ __half g_qkvh[(size_t)Tt * QKVS];
__device__ __half g_midh[Tt * Dd];
__device__ __half g_x1h[Tt * Dd];
__device__ __half g_uph[(size_t)Tt * DFF];

// ---------------- helpers ----------------
__device__ __forceinline__ void mma_f16(float* d, const uint32_t* a, const uint32_t* b) {
    asm volatile(
        "mma.sync.aligned.m16n8k16.row.col.f32.f16.f16.f32 "
        "{%0,%1,%2,%3}, {%4,%5,%6,%7}, {%8,%9}, {%0,%1,%2,%3};"
        : "+f"(d[0]), "+f"(d[1]), "+f"(d[2]), "+f"(d[3])
        : "r"(a[0]), "r"(a[1]), "r"(a[2]), "r"(a[3]), "r"(b[0]), "r"(b[1]));
}
__device__ __forceinline__ uint32_t sptr(const void* p) {
    return (uint32_t)__cvta_generic_to_shared(p);
}
__device__ __forceinline__ void ldsm_x4(uint32_t* r, uint32_t addr) {
    asm volatile("ldmatrix.sync.aligned.m8n8.x4.shared.b16 {%0,%1,%2,%3}, [%4];"
                 : "=r"(r[0]), "=r"(r[1]), "=r"(r[2]), "=r"(r[3]) : "r"(addr));
}
__device__ __forceinline__ void ldsm_x2t(uint32_t* r, uint32_t addr) {
    asm volatile("ldmatrix.sync.aligned.m8n8.x2.trans.shared.b16 {%0,%1}, [%2];"
                 : "=r"(r[0]), "=r"(r[1]) : "r"(addr));
}
__device__ __forceinline__ uint32_t packh2(float x, float y) {
    __half2 h = __floats2half2_rn(x, y);
    return *reinterpret_cast<uint32_t*>(&h);
}
__device__ __forceinline__ void cp_async16(uint32_t dst, const void* src) {
    asm volatile("cp.async.cg.shared.global [%0], [%1], 16;" :: "r"(dst), "l"(src));
}
__device__ __forceinline__ void cp_commit() {
    asm volatile("cp.async.commit_group;" ::: "memory");
}
template <int N>
__device__ __forceinline__ void cp_wait() {
    asm volatile("cp.async.wait_group %0;" :: "n"(N) : "memory");
}

// ---------------- fp32 -> fp16 converters ----------------
__global__ __launch_bounds__(256)
void f2h_kernel(const float* __restrict__ in, __half* __restrict__ out, int n)
{
    const int i = (blockIdx.x * 256 + threadIdx.x) * 4;
    if (i < n) {
        float4 v = *(const float4*)&in[i];
        *(__half2*)&out[i]     = __floats2half2_rn(v.x, v.y);
        *(__half2*)&out[i + 2] = __floats2half2_rn(v.z, v.w);
    }
}
// convert W[Dd rows x Dd cols] into columns [base, base+Dd) of Wcat[Dd x QKVS]
__global__ __launch_bounds__(256)
void f2h_concat_kernel(const float* __restrict__ in, __half* __restrict__ out, int base)
{
    const int i = (blockIdx.x * 256 + threadIdx.x) * 4;
    const int r = i >> 10, c = i & 1023;   // Dd = 1024
    float4 v = *(const float4*)&in[i];
    __half* o = out + (size_t)r * QKVS + base + c;
    *(__half2*)&o[0] = __floats2half2_rn(v.x, v.y);
    *(__half2*)&o[2] = __floats2half2_rn(v.z, v.w);
}
__global__ __launch_bounds__(256)
void bias_concat_kernel(const float* __restrict__ bq, const float* __restrict__ bk,
                        const float* __restrict__ bv, float* __restrict__ out)
{
    const int i = blockIdx.x * 256 + threadIdx.x;
    if (i < Dd)            out[i] = bq[i];
    else if (i < 2 * Dd)   out[i] = bk[i - Dd];
    else if (i < 3 * Dd)   out[i] = bv[i - 2 * Dd];
}

// ---------------- FP16 GEMM, cp.async double-buffered (unchanged from R7) ----------------
template <int RELU, int OUTH>
__global__ __launch_bounds__(256)
void gemm_h(const __half* __restrict__ A, const __half* __restrict__ W,
            const float* __restrict__ bias, void* __restrict__ Cout,
            int M, int N, int K)
{
    __shared__ __half As[2][128][40];
    __shared__ __half Bs[2][32][136];

    const int tid  = threadIdx.x;
    const int lane = tid & 31;
    const int wid  = tid >> 5;
    const int wm   = (wid & 1) * 64;
    const int wn   = (wid >> 1) * 32;
    const int m0   = blockIdx.y << 7;
    const int n0   = blockIdx.x << 7;

    const int row  = lane >> 2;
    const int col  = lane & 3;
    const int lrow = lane & 15;
    const int lcol = (lane >> 4) * 8;

    const int a_r = tid >> 2;
    const int a_e = (tid & 3) * 8;
    const int b_r = tid >> 4;
    const int b_e = (tid & 15) * 8;

    float acc[4][4][4];
#pragma unroll
    for (int mi = 0; mi < 4; mi++)
#pragma unroll
        for (int ni = 0; ni < 4; ni++)
#pragma unroll
            for (int j = 0; j < 4; j++) acc[mi][ni][j] = 0.f;

    const int nk = K >> 5;

    auto load_stage = [&](int c, int st) {
        const __half* Ab = A + (size_t)(m0 + a_r) * K + (c << 5) + a_e;
        cp_async16(sptr(&As[st][a_r][a_e]),      Ab);
        cp_async16(sptr(&As[st][a_r + 64][a_e]), Ab + (size_t)64 * K);
        const __half* Bb = W + (size_t)((c << 5) + b_r) * N + n0 + b_e;
        cp_async16(sptr(&Bs[st][b_r][b_e]),      Bb);
        cp_async16(sptr(&Bs[st][b_r + 16][b_e]), Bb + (size_t)16 * N);
    };

    load_stage(0, 0);
    cp_commit();

    for (int c = 0; c < nk; c++) {
        const int st = c & 1;
        if (c + 1 < nk) {
            load_stage(c + 1, st ^ 1);
            cp_commit();
            cp_wait<1>();
        } else {
            cp_wait<0>();
        }
        __syncthreads();

#pragma unroll
        for (int ks = 0; ks < 32; ks += 16) {
            uint32_t a[4][4], b[4][2];
#pragma unroll
            for (int mi = 0; mi < 4; mi++)
                ldsm_x4(a[mi], sptr(&As[st][wm + mi * 16 + lrow][ks + lcol]));
#pragma unroll
            for (int ni = 0; ni < 4; ni++)
                ldsm_x2t(b[ni], sptr(&Bs[st][ks + lrow][wn + ni * 8]));
#pragma unroll
            for (int mi = 0; mi < 4; mi++)
#pragma unroll
                for (int ni = 0; ni < 4; ni++)
                    mma_f16(acc[mi][ni], a[mi], b[ni]);
        }
        __syncthreads();
    }

#pragma unroll
    for (int mi = 0; mi < 4; mi++) {
        const int r0 = m0 + wm + mi * 16 + row;
#pragma unroll
        for (int ni = 0; ni < 4; ni++) {
            const int c0 = n0 + wn + ni * 8 + 2 * col;
            const float b0 = bias[c0], b1 = bias[c0 + 1];
            float v00 = acc[mi][ni][0] + b0, v01 = acc[mi][ni][1] + b1;
            float v10 = acc[mi][ni][2] + b0, v11 = acc[mi][ni][3] + b1;
            if (RELU) {
                v00 = fmaxf(v00, 0.f); v01 = fmaxf(v01, 0.f);
                v10 = fmaxf(v10, 0.f); v11 = fmaxf(v11, 0.f);
            }
            if (OUTH) {
                __half* Ch = (__half*)Cout;
                *(__half2*)&Ch[(size_t)r0 * N + c0]       = __floats2half2_rn(v00, v01);
                *(__half2*)&Ch[(size_t)(r0 + 8) * N + c0] = __floats2half2_rn(v10, v11);
            } else {
                float* Cf = (float*)Cout;
                *(float2*)&Cf[(size_t)r0 * N + c0]       = make_float2(v00, v01);
                *(float2*)&Cf[(size_t)(r0 + 8) * N + c0] = make_float2(v10, v11);
            }
        }
    }
}

// ---------------- FP16 causal flash attention, cp.async double-buffered ----------------
// Reads q/k/v from fused qkv buffer (row stride QKVS). Heaviest q-blocks first.
__global__ __launch_bounds__(128)
void attn_f16(const __half* __restrict__ QKV, __half* __restrict__ Og)
{
    __shared__ __half Ks[2][64][72];
    __shared__ __half Vs[2][64][72];

    const int tid  = threadIdx.x;
    const int lane = tid & 31;
    const int wid  = tid >> 5;
    const int g    = lane >> 2;
    const int t    = lane & 3;
    const int lrow = lane & 15;
    const int qb   = (int)gridDim.x - 1 - (int)blockIdx.x;   // heavy blocks first
    const int bh   = blockIdx.y;
    const int b    = bh >> 4, h = bh & 15;

    const __half* Qb = QKV + (size_t)b * Ss * QKVS + h * HDd;
    const __half* Kb = Qb + Dd;
    const __half* Vb = Qb + 2 * Dd;

    // ---- prologue: stage Q (scaled) through Ks[0], build A fragments ----
    const __half2 hs = __floats2half2_rn(0.125f, 0.125f);
    for (int i = tid; i < 64 * 8; i += 128) {
        const int r = i >> 3, c8 = (i & 7) * 8;
        uint4 q4 = *(const uint4*)&Qb[(size_t)(qb * 64 + r) * QKVS + c8];
        __half2* p = (__half2*)&q4;
        p[0] = __hmul2(p[0], hs); p[1] = __hmul2(p[1], hs);
        p[2] = __hmul2(p[2], hs); p[3] = __hmul2(p[3], hs);
        *(uint4*)&Ks[0][r][c8] = q4;
    }
    __syncthreads();

    uint32_t qf[4][4];
    {
        const int qr = wid * 16 + g;
#pragma unroll
        for (int s = 0; s < 4; s++) {
            qf[s][0] = *(const uint32_t*)&Ks[0][qr][s * 16 + 2 * t];
            qf[s][1] = *(const uint32_t*)&Ks[0][qr + 8][s * 16 + 2 * t];
            qf[s][2] = *(const uint32_t*)&Ks[0][qr][s * 16 + 2 * t + 8];
            qf[s][3] = *(const uint32_t*)&Ks[0][qr + 8][s * 16 + 2 * t + 8];
        }
    }
    __syncthreads();   // all warps done reading Q staging before tile 0 overwrites

    // per-thread cp.async slice: 4 rows x 1 chunk for K and V each
    const int kv_r = tid >> 3;          // 0..15 (+16 steps)
    const int kv_c = (tid & 7) * 8;     // halves offset

    auto load_kv = [&](int kt, int st) {
#pragma unroll
        for (int j = 0; j < 4; j++) {
            const int r = kv_r + j * 16;
            const size_t off = (size_t)(kt * 64 + r) * QKVS + kv_c;
            cp_async16(sptr(&Ks[st][r][kv_c]), Kb + off);
            cp_async16(sptr(&Vs[st][r][kv_c]), Vb + off);
        }
    };

    load_kv(0, 0);
    cp_commit();

    float m0 = -1e30f, m1 = -1e30f, l0 = 0.f, l1 = 0.f;
    float O[8][4];
#pragma unroll
    for (int n = 0; n < 8; n++)
#pragma unroll
        for (int j = 0; j < 4; j++) O[n][j] = 0.f;

    const int lq0 = wid * 16 + g;
    const int lq1 = lq0 + 8;

    const int nkt = qb + 1;
    for (int kt = 0; kt < nkt; kt++) {
        const int st = kt & 1;
        __syncthreads();   // all warps finished reading buffer st^1 (iter kt-1)
        if (kt + 1 < nkt) {
            load_kv(kt + 1, st ^ 1);
            cp_commit();
            cp_wait<1>();
        } else {
            cp_wait<0>();
        }
        __syncthreads();   // tile kt visible to all warps

        // ---- S = Q @ K^T ----
        float S[8][4];
#pragma unroll
        for (int n = 0; n < 8; n++)
#pragma unroll
            for (int j = 0; j < 4; j++) S[n][j] = 0.f;

#pragma unroll
        for (int s = 0; s < 4; s++) {
#pragma unroll
            for (int n = 0; n < 8; n++) {
                uint32_t bq[2];
                bq[0] = *(const uint32_t*)&Ks[st][n * 8 + g][s * 16 + 2 * t];
                bq[1] = *(const uint32_t*)&Ks[st][n * 8 + g][s * 16 + 2 * t + 8];
                mma_f16(S[n], qf[s], bq);
            }
        }

        // ---- causal mask (diagonal tile only) ----
        if (kt == qb) {
#pragma unroll
            for (int n = 0; n < 8; n++) {
                const int kc = n * 8 + 2 * t;
                if (kc     > lq0) S[n][0] = -1e30f;
                if (kc + 1 > lq0) S[n][1] = -1e30f;
                if (kc     > lq1) S[n][2] = -1e30f;
                if (kc + 1 > lq1) S[n][3] = -1e30f;
            }
        }

        // ---- online softmax ----
        float mx0 = -1e30f, mx1 = -1e30f;
#pragma unroll
        for (int n = 0; n < 8; n++) {
            mx0 = fmaxf(mx0, fmaxf(S[n][0], S[n][1]));
            mx1 = fmaxf(mx1, fmaxf(S[n][2], S[n][3]));
        }
        mx0 = fmaxf(mx0, __shfl_xor_sync(0xffffffffu, mx0, 1));
        mx0 = fmaxf(mx0, __shfl_xor_sync(0xffffffffu, mx0, 2));
        mx1 = fmaxf(mx1, __shfl_xor_sync(0xffffffffu, mx1, 1));
        mx1 = fmaxf(mx1, __shfl_xor_sync(0xffffffffu, mx1, 2));

        const float mn0 = fmaxf(m0, mx0), mn1 = fmaxf(m1, mx1);
        const float fac0 = __expf(m0 - mn0), fac1 = __expf(m1 - mn1);

        float s0 = 0.f, s1 = 0.f;
#pragma unroll
        for (int n = 0; n < 8; n++) {
            S[n][0] = __expf(S[n][0] - mn0);
            S[n][1] = __expf(S[n][1] - mn0);
            S[n][2] = __expf(S[n][2] - mn1);
            S[n][3] = __expf(S[n][3] - mn1);
            s0 += S[n][0] + S[n][1];
            s1 += S[n][2] + S[n][3];
        }
        s0 += __shfl_xor_sync(0xffffffffu, s0, 1);
        s0 += __shfl_xor_sync(0xffffffffu, s0, 2);
        s1 += __shfl_xor_sync(0xffffffffu, s1, 1);
        s1 += __shfl_xor_sync(0xffffffffu, s1, 2);

        l0 = l0 * fac0 + s0;
        l1 = l1 * fac1 + s1;
        m0 = mn0; m1 = mn1;

#pragma unroll
        for (int n = 0; n < 8; n++) {
            O[n][0] *= fac0; O[n][1] *= fac0;
            O[n][2] *= fac1; O[n][3] *= fac1;
        }

        // ---- O += P @ V (P packed in registers) ----
#pragma unroll
        for (int kk = 0; kk < 4; kk++) {
            uint32_t pa[4];
            pa[0] = packh2(S[2 * kk][0],     S[2 * kk][1]);
            pa[1] = packh2(S[2 * kk][2],     S[2 * kk][3]);
            pa[2] = packh2(S[2 * kk + 1][0], S[2 * kk + 1][1]);
            pa[3] = packh2(S[2 * kk + 1][2], S[2 * kk + 1][3]);
#pragma unroll
            for (int nd = 0; nd < 8; nd++) {
                uint32_t bv[2];
                ldsm_x2t(bv, sptr(&Vs[st][kk * 16 + lrow][nd * 8]));
                mma_f16(O[nd], pa, bv);
            }
        }
    }

    // ---- epilogue (fp16 out, stride Dd) ----
    const float inv0 = 1.f / l0, inv1 = 1.f / l1;
    const int q0 = qb * 64 + lq0;
    __half* o0 = Og + (size_t)(b * Ss + q0) * Dd + h * HDd;
    __half* o1 = o0 + 8 * Dd;
#pragma unroll
    for (int nd = 0; nd < 8; nd++) {
        const int c0 = nd * 8 + 2 * t;
        *(__half2*)&o0[c0] = __floats2half2_rn(O[nd][0] * inv0, O[nd][1] * inv0);
        *(__half2*)&o1[c0] = __floats2half2_rn(O[nd][2] * inv1, O[nd][3] * inv1);
    }
}

// ---------------- residual add + LayerNorm (optional fp16 mirror) ----------------
template <int DUAL>
__global__ __launch_bounds__(256)
void add_ln_kernel(const float* __restrict__ a, const float* __restrict__ r,
                   const float* __restrict__ gamma, const float* __restrict__ beta,
                   float* __restrict__ out, __half* __restrict__ outh)
{
    const int t = blockIdx.x;
    const int tid = threadIdx.x;
    __shared__ float buf[Dd];
    __shared__ float red[20];

    float s = 0.f, sq = 0.f;
    for (int i = tid; i < Dd; i += 256) {
        float v = a[(size_t)t * Dd + i] + r[(size_t)t * Dd + i];
        buf[i] = v;
        s += v; sq += v * v;
    }
#pragma unroll
    for (int o = 16; o; o >>= 1) {
        s  += __shfl_xor_sync(0xffffffffu, s, o);
        sq += __shfl_xor_sync(0xffffffffu, sq, o);
    }
    if ((tid & 31) == 0) { red[tid >> 5] = s; red[8 + (tid >> 5)] = sq; }
    __syncthreads();
    if (tid == 0) {
        float ts = 0.f, tq = 0.f;
        for (int i = 0; i < 8; i++) { ts += red[i]; tq += red[8 + i]; }
        const float mu  = ts * (1.0f / Dd);
        const float var = tq * (1.0f / Dd) - mu * mu;
        red[16] = mu;
        red[17] = rsqrtf(var + 1e-6f);
    }
    __syncthreads();
    const float mu = red[16], rstd = red[17];
    for (int i = tid; i < Dd; i += 256) {
        const float v = (buf[i] - mu) * rstd * gamma[i] + beta[i];
        out[(size_t)t * Dd + i] = v;
        if (DUAL) outh[(size_t)t * Dd + i] = __float2half_rn(v);
    }
}

// ---------------- launch ----------------
extern "C" void kernel_launch(void* const* d_in, const int* in_sizes, int n_in,
                              void* d_out, int out_size)
{
    const float* x   = (const float*)d_in[0];
    const float* Wq  = (const float*)d_in[1];
    const float* bq  = (const float*)d_in[2];
    const float* Wk  = (const float*)d_in[3];
    const float* bk  = (const float*)d_in[4];
    const float* Wv  = (const float*)d_in[5];
    const float* bv  = (const float*)d_in[6];
    const float* Wo  = (const float*)d_in[7];
    const float* bo  = (const float*)d_in[8];
    const float* g1  = (const float*)d_in[9];
    const float* b1  = (const float*)d_in[10];
    const float* Wup = (const float*)d_in[11];
    const float* bup = (const float*)d_in[12];
    const float* Wdn = (const float*)d_in[13];
    const float* bdn = (const float*)d_in[14];
    const float* g2  = (const float*)d_in[15];
    const float* b2  = (const float*)d_in[16];
    float* out = (float*)d_out;

    float *proj, *x1, *bqkv;
    __half *xh, *wqkvh, *woh, *wuph, *wdnh;
    __half *qkvh, *midh, *x1h, *uph;
    cudaGetSymbolAddress((void**)&proj,  g_proj);
    cudaGetSymbolAddress((void**)&x1,    g_x1);
    cudaGetSymbolAddress((void**)&bqkv,  g_bqkv);
    cudaGetSymbolAddress((void**)&xh,    g_xh);
    cudaGetSymbolAddress((void**)&wqkvh, g_wqkvh);
    cudaGetSymbolAddress((void**)&woh,   g_woh);
    cudaGetSymbolAddress((void**)&wuph,  g_wuph);
    cudaGetSymbolAddress((void**)&wdnh,  g_wdnh);
    cudaGetSymbolAddress((void**)&qkvh,  g_qkvh);
    cudaGetSymbolAddress((void**)&midh,  g_midh);
    cudaGetSymbolAddress((void**)&x1h,   g_x1h);
    cudaGetSymbolAddress((void**)&uph,   g_uph);

    const dim3 blk(256);

    // fp32 -> fp16 conversions (weights + x); QKV weights interleave into one matrix
    f2h_kernel<<<Tt * Dd / 1024, blk>>>(x, xh, Tt * Dd);
    f2h_concat_kernel<<<Dd * Dd / 1024, blk>>>(Wq, wqkvh, 0);
    f2h_concat_kernel<<<Dd * Dd / 1024, blk>>>(Wk, wqkvh, Dd);
    f2h_concat_kernel<<<Dd * Dd / 1024, blk>>>(Wv, wqkvh, 2 * Dd);
    bias_concat_kernel<<<QKVS / 256, blk>>>(bq, bk, bv, bqkv);
    f2h_kernel<<<Dd * Dd / 1024, blk>>>(Wo, woh, Dd * Dd);
    f2h_kernel<<<Dd * DFF / 1024, blk>>>(Wup, wuph, Dd * DFF);
    f2h_kernel<<<DFF * Dd / 1024, blk>>>(Wdn, wdnh, DFF * Dd);

    // fused QKV projection (fp16 out, [Tt, 3072])
    gemm_h<0, 1><<<dim3(QKVS / 128, Tt / 128), blk>>>(xh, wqkvh, bqkv, qkvh, Tt, QKVS, Dd);

    // causal attention (fp16 in/out, strided qkv read)
    attn_f16<<<dim3(Ss / 64, Bt * Hh), dim3(128)>>>(qkvh, midh);

    // output projection (fp32 out) + residual LN1 (dual out)
    gemm_h<0, 0><<<dim3(Dd / 128, Tt / 128), blk>>>(midh, woh, bo, proj, Tt, Dd, Dd);
    add_ln_kernel<1><<<Tt, blk>>>(x, proj, g1, b1, x1, x1h);

    // FFN
    gemm_h<1, 1><<<dim3(DFF / 128, Tt / 128), blk>>>(x1h, wuph, bup, uph, Tt, DFF, Dd);
    gemm_h<0, 0><<<dim3(Dd / 128, Tt / 128), blk>>>(uph, wdnh, bdn, proj, Tt, Dd, DFF);
    add_ln_kernel<0><<<Tt, blk>>>(x1, proj, g2, b2, out, nullptr);
}

// round 9
// speedup vs baseline: 6.3225x; 1.0124x over previous
#include <cuda_runtime.h>
#include <cuda_fp16.h>
#include <cstdint>

#define Bt  2
#define Ss  2048
#define Dd  1024
#define Hh  16
#define HDd 64
#define Tt  (Bt * Ss)      // 4096 tokens
#define DFF (4 * Dd)       // 4096
#define QKVS (3 * Dd)      // 3072: row stride of fused qkv output

// ---------------- scratch (device globals; no allocation allowed) ----------------
__device__ float  g_proj[Tt * Dd];
__device__ float  g_x1[Tt * Dd];
__device__ float  g_bqkv[QKVS];
__device__ __half g_xh[Tt * Dd];
__device__ __half g_wqkvh[(size_t)Dd * QKVS];
__device__ __half g_woh[Dd * Dd];
__device__ __half g_wuph[(size_t)Dd * DFF];
__device__ __half g_wdnh[(size_t)DFF * Dd];
__device__ __half g_qkvh[(size_t)Tt * QKVS];
__device__ __half g_midh[Tt * Dd];
__device__ __half g_x1h[Tt * Dd];
__device__ __half g_uph[(size_t)Tt * DFF];

// ---------------- helpers ----------------
__device__ __forceinline__ void mma_f16(float* d, const uint32_t* a, const uint32_t* b) {
    asm volatile(
        "mma.sync.aligned.m16n8k16.row.col.f32.f16.f16.f32 "
        "{%0,%1,%2,%3}, {%4,%5,%6,%7}, {%8,%9}, {%0,%1,%2,%3};"
        : "+f"(d[0]), "+f"(d[1]), "+f"(d[2]), "+f"(d[3])
        : "r"(a[0]), "r"(a[1]), "r"(a[2]), "r"(a[3]), "r"(b[0]), "r"(b[1]));
}
__device__ __forceinline__ uint32_t sptr(const void* p) {
    return (uint32_t)__cvta_generic_to_shared(p);
}
__device__ __forceinline__ void ldsm_x4(uint32_t* r, uint32_t addr) {
    asm volatile("ldmatrix.sync.aligned.m8n8.x4.shared.b16 {%0,%1,%2,%3}, [%4];"
                 : "=r"(r[0]), "=r"(r[1]), "=r"(r[2]), "=r"(r[3]) : "r"(addr));
}
__device__ __forceinline__ void ldsm_x2t(uint32_t* r, uint32_t addr) {
    asm volatile("ldmatrix.sync.aligned.m8n8.x2.trans.shared.b16 {%0,%1}, [%2];"
                 : "=r"(r[0]), "=r"(r[1]) : "r"(addr));
}
__device__ __forceinline__ uint32_t packh2(float x, float y) {
    __half2 h = __floats2half2_rn(x, y);
    return *reinterpret_cast<uint32_t*>(&h);
}
__device__ __forceinline__ void cp_async16(uint32_t dst, const void* src) {
    asm volatile("cp.async.cg.shared.global [%0], [%1], 16;" :: "r"(dst), "l"(src));
}
__device__ __forceinline__ void cp_commit() {
    asm volatile("cp.async.commit_group;" ::: "memory");
}
template <int N>
__device__ __forceinline__ void cp_wait() {
    asm volatile("cp.async.wait_group %0;" :: "n"(N) : "memory");
}

// ---------------- fp32 -> fp16 converters (consolidated) ----------------
#define DD4 (Dd * Dd / 4)   // float4 chunks per Dd x Dd matrix
// Wq|Wk|Wv -> interleaved wqkvh[Dd][QKVS]
__global__ __launch_bounds__(256)
void f2h_qkv(const float* __restrict__ Wq, const float* __restrict__ Wk,
             const float* __restrict__ Wv, __half* __restrict__ out)
{
    const int idx = blockIdx.x * 256 + threadIdx.x;   // 0 .. 3*DD4-1
    const int seg = idx / DD4;
    const int j = (idx - seg * DD4) * 4;
    const float* W = (seg == 0) ? Wq : (seg == 1) ? Wk : Wv;
    const int r = j >> 10, c = j & 1023;
    float4 v = *(const float4*)&W[j];
    __half* o = out + (size_t)r * QKVS + seg * Dd + c;
    *(__half2*)&o[0] = __floats2half2_rn(v.x, v.y);
    *(__half2*)&o[2] = __floats2half2_rn(v.z, v.w);
}
// x, Wo, Wup, Wdn -> fp16 mirrors, one launch
__global__ __launch_bounds__(256)
void f2h_misc(const float* __restrict__ x,   const float* __restrict__ Wo,
              const float* __restrict__ Wup, const float* __restrict__ Wdn,
              __half* __restrict__ xh,   __half* __restrict__ woh,
              __half* __restrict__ wuph, __half* __restrict__ wdnh)
{
    const int c0 = Tt * Dd / 4, c1 = Dd * Dd / 4, c2 = Dd * DFF / 4;
    int idx = blockIdx.x * 256 + threadIdx.x;
    const float* in; __half* out;
    if (idx < c0)                 { in = x;   out = xh; }
    else if ((idx -= c0) < c1)    { in = Wo;  out = woh; }
    else if ((idx -= c1) < c2)    { in = Wup; out = wuph; }
    else { idx -= c2;               in = Wdn; out = wdnh; }
    const int j = idx * 4;
    float4 v = *(const float4*)&in[j];
    *(__half2*)&out[j]     = __floats2half2_rn(v.x, v.y);
    *(__half2*)&out[j + 2] = __floats2half2_rn(v.z, v.w);
}
__global__ __launch_bounds__(256)
void bias_concat_kernel(const float* __restrict__ bq, const float* __restrict__ bk,
                        const float* __restrict__ bv, float* __restrict__ out)
{
    const int i = blockIdx.x * 256 + threadIdx.x;
    if (i < Dd)            out[i] = bq[i];
    else if (i < 2 * Dd)   out[i] = bk[i - Dd];
    else if (i < 3 * Dd)   out[i] = bv[i - 2 * Dd];
}

// ---------------- FP16 GEMM, cp.async double-buffered (unchanged) ----------------
template <int RELU, int OUTH>
__global__ __launch_bounds__(256)
void gemm_h(const __half* __restrict__ A, const __half* __restrict__ W,
            const float* __restrict__ bias, void* __restrict__ Cout,
            int M, int N, int K)
{
    __shared__ __half As[2][128][40];
    __shared__ __half Bs[2][32][136];

    const int tid  = threadIdx.x;
    const int lane = tid & 31;
    const int wid  = tid >> 5;
    const int wm   = (wid & 1) * 64;
    const int wn   = (wid >> 1) * 32;
    const int m0   = blockIdx.y << 7;
    const int n0   = blockIdx.x << 7;

    const int row  = lane >> 2;
    const int col  = lane & 3;
    const int lrow = lane & 15;
    const int lcol = (lane >> 4) * 8;

    const int a_r = tid >> 2;
    const int a_e = (tid & 3) * 8;
    const int b_r = tid >> 4;
    const int b_e = (tid & 15) * 8;

    float acc[4][4][4];
#pragma unroll
    for (int mi = 0; mi < 4; mi++)
#pragma unroll
        for (int ni = 0; ni < 4; ni++)
#pragma unroll
            for (int j = 0; j < 4; j++) acc[mi][ni][j] = 0.f;

    const int nk = K >> 5;

    auto load_stage = [&](int c, int st) {
        const __half* Ab = A + (size_t)(m0 + a_r) * K + (c << 5) + a_e;
        cp_async16(sptr(&As[st][a_r][a_e]),      Ab);
        cp_async16(sptr(&As[st][a_r + 64][a_e]), Ab + (size_t)64 * K);
        const __half* Bb = W + (size_t)((c << 5) + b_r) * N + n0 + b_e;
        cp_async16(sptr(&Bs[st][b_r][b_e]),      Bb);
        cp_async16(sptr(&Bs[st][b_r + 16][b_e]), Bb + (size_t)16 * N);
    };

    load_stage(0, 0);
    cp_commit();

    for (int c = 0; c < nk; c++) {
        const int st = c & 1;
        if (c + 1 < nk) {
            load_stage(c + 1, st ^ 1);
            cp_commit();
            cp_wait<1>();
        } else {
            cp_wait<0>();
        }
        __syncthreads();

#pragma unroll
        for (int ks = 0; ks < 32; ks += 16) {
            uint32_t a[4][4], b[4][2];
#pragma unroll
            for (int mi = 0; mi < 4; mi++)
                ldsm_x4(a[mi], sptr(&As[st][wm + mi * 16 + lrow][ks + lcol]));
#pragma unroll
            for (int ni = 0; ni < 4; ni++)
                ldsm_x2t(b[ni], sptr(&Bs[st][ks + lrow][wn + ni * 8]));
#pragma unroll
            for (int mi = 0; mi < 4; mi++)
#pragma unroll
                for (int ni = 0; ni < 4; ni++)
                    mma_f16(acc[mi][ni], a[mi], b[ni]);
        }
        __syncthreads();
    }

#pragma unroll
    for (int mi = 0; mi < 4; mi++) {
        const int r0 = m0 + wm + mi * 16 + row;
#pragma unroll
        for (int ni = 0; ni < 4; ni++) {
            const int c0 = n0 + wn + ni * 8 + 2 * col;
            const float b0 = bias[c0], b1 = bias[c0 + 1];
            float v00 = acc[mi][ni][0] + b0, v01 = acc[mi][ni][1] + b1;
            float v10 = acc[mi][ni][2] + b0, v11 = acc[mi][ni][3] + b1;
            if (RELU) {
                v00 = fmaxf(v00, 0.f); v01 = fmaxf(v01, 0.f);
                v10 = fmaxf(v10, 0.f); v11 = fmaxf(v11, 0.f);
            }
            if (OUTH) {
                __half* Ch = (__half*)Cout;
                *(__half2*)&Ch[(size_t)r0 * N + c0]       = __floats2half2_rn(v00, v01);
                *(__half2*)&Ch[(size_t)(r0 + 8) * N + c0] = __floats2half2_rn(v10, v11);
            } else {
                float* Cf = (float*)Cout;
                *(float2*)&Cf[(size_t)r0 * N + c0]       = make_float2(v00, v01);
                *(float2*)&Cf[(size_t)(r0 + 8) * N + c0] = make_float2(v10, v11);
            }
        }
    }
}

// ---------------- FP16 causal flash attention: 128 queries/CTA, 8 warps ----------------
// K/V tiles cp.async double-buffered; Q stages through stage-0 buffers; per-warp
// fully-masked-tile skip. Heaviest q-blocks scheduled first.
__global__ __launch_bounds__(256)
void attn_f16(const __half* __restrict__ QKV, __half* __restrict__ Og)
{
    __shared__ __half Ks[2][64][72];
    __shared__ __half Vs[2][64][72];

    const int tid  = threadIdx.x;
    const int lane = tid & 31;
    const int wid  = tid >> 5;            // 0..7
    const int g    = lane >> 2;           // 0..7
    const int t    = lane & 3;            // 0..3
    const int lrow = lane & 15;
    const int qb   = (int)gridDim.x - 1 - (int)blockIdx.x;   // heavy first
    const int bh   = blockIdx.y;
    const int b    = bh >> 4, h = bh & 15;

    const __half* Qb = QKV + (size_t)b * Ss * QKVS + h * HDd;
    const __half* Kb = Qb + Dd;
    const __half* Vb = Qb + 2 * Dd;

    // ---- prologue: stage 128 Q rows (scaled): rows 0-63 -> Ks[0], 64-127 -> Vs[0] ----
    const __half2 hs = __floats2half2_rn(0.125f, 0.125f);
    for (int i = tid; i < 128 * 8; i += 256) {
        const int r = i >> 3, c8 = (i & 7) * 8;
        uint4 q4 = *(const uint4*)&Qb[(size_t)(qb * 128 + r) * QKVS + c8];
        __half2* p = (__half2*)&q4;
        p[0] = __hmul2(p[0], hs); p[1] = __hmul2(p[1], hs);
        p[2] = __hmul2(p[2], hs); p[3] = __hmul2(p[3], hs);
        if (r < 64) *(uint4*)&Ks[0][r][c8]      = q4;
        else        *(uint4*)&Vs[0][r - 64][c8] = q4;
    }
    __syncthreads();

    uint32_t qf[4][4];
    {
        const __half (*Qs)[72] = (wid < 4) ? Ks[0] : Vs[0];
        const int qr = (wid * 16) % 64 + g;
#pragma unroll
        for (int s = 0; s < 4; s++) {
            qf[s][0] = *(const uint32_t*)&Qs[qr][s * 16 + 2 * t];
            qf[s][1] = *(const uint32_t*)&Qs[qr + 8][s * 16 + 2 * t];
            qf[s][2] = *(const uint32_t*)&Qs[qr][s * 16 + 2 * t + 8];
            qf[s][3] = *(const uint32_t*)&Qs[qr + 8][s * 16 + 2 * t + 8];
        }
    }
    __syncthreads();   // Q staging fully consumed before tile 0 overwrites

    // per-thread cp.async slice: 2 rows x 1 chunk for K and V each
    const int kv_r = tid >> 3;          // 0..31 (+32 step)
    const int kv_c = (tid & 7) * 8;

    auto load_kv = [&](int kt, int st) {
#pragma unroll
        for (int j = 0; j < 2; j++) {
            const int r = kv_r + j * 32;
            const size_t off = (size_t)(kt * 64 + r) * QKVS + kv_c;
            cp_async16(sptr(&Ks[st][r][kv_c]), Kb + off);
            cp_async16(sptr(&Vs[st][r][kv_c]), Vb + off);
        }
    };

    load_kv(0, 0);
    cp_commit();

    float m0 = -1e30f, m1 = -1e30f, l0 = 0.f, l1 = 0.f;
    float O[8][4];
#pragma unroll
    for (int n = 0; n < 8; n++)
#pragma unroll
        for (int j = 0; j < 4; j++) O[n][j] = 0.f;

    const int lq0 = wid * 16 + g;        // 0..127
    const int qg0 = qb * 128 + lq0;      // global q rows
    const int qg1 = qg0 + 8;
    const int wmax = qb * 128 + wid * 16 + 15;   // warp's max q row

    const int nkt = 2 * qb + 2;
    for (int kt = 0; kt < nkt; kt++) {
        const int st = kt & 1;
        __syncthreads();   // all warps done with buffer st (iter kt-2)
        if (kt + 1 < nkt) {
            load_kv(kt + 1, st ^ 1);
            cp_commit();
            cp_wait<1>();
        } else {
            cp_wait<0>();
        }
        __syncthreads();   // tile kt visible

        if (kt * 64 > wmax) continue;   // warp fully masked: no body syncs, safe

        // ---- S = Q @ K^T ----
        float S[8][4];
#pragma unroll
        for (int n = 0; n < 8; n++)
#pragma unroll
            for (int j = 0; j < 4; j++) S[n][j] = 0.f;

#pragma unroll
        for (int s = 0; s < 4; s++) {
#pragma unroll
            for (int n = 0; n < 8; n++) {
                uint32_t bq[2];
                bq[0] = *(const uint32_t*)&Ks[st][n * 8 + g][s * 16 + 2 * t];
                bq[1] = *(const uint32_t*)&Ks[st][n * 8 + g][s * 16 + 2 * t + 8];
                mma_f16(S[n], qf[s], bq);
            }
        }

        // ---- causal mask (only the last two tiles can touch the diagonal) ----
        if (kt >= 2 * qb) {
#pragma unroll
            for (int n = 0; n < 8; n++) {
                const int kg = kt * 64 + n * 8 + 2 * t;
                if (kg     > qg0) S[n][0] = -1e30f;
                if (kg + 1 > qg0) S[n][1] = -1e30f;
                if (kg     > qg1) S[n][2] = -1e30f;
                if (kg + 1 > qg1) S[n][3] = -1e30f;
            }
        }

        // ---- online softmax ----
        float mx0 = -1e30f, mx1 = -1e30f;
#pragma unroll
        for (int n = 0; n < 8; n++) {
            mx0 = fmaxf(mx0, fmaxf(S[n][0], S[n][1]));
            mx1 = fmaxf(mx1, fmaxf(S[n][2], S[n][3]));
        }
        mx0 = fmaxf(mx0, __shfl_xor_sync(0xffffffffu, mx0, 1));
        mx0 = fmaxf(mx0, __shfl_xor_sync(0xffffffffu, mx0, 2));
        mx1 = fmaxf(mx1, __shfl_xor_sync(0xffffffffu, mx1, 1));
        mx1 = fmaxf(mx1, __shfl_xor_sync(0xffffffffu, mx1, 2));

        const float mn0 = fmaxf(m0, mx0), mn1 = fmaxf(m1, mx1);
        const float fac0 = __expf(m0 - mn0), fac1 = __expf(m1 - mn1);

        float s0 = 0.f, s1 = 0.f;
#pragma unroll
        for (int n = 0; n < 8; n++) {
            S[n][0] = __expf(S[n][0] - mn0);
            S[n][1] = __expf(S[n][1] - mn0);
            S[n][2] = __expf(S[n][2] - mn1);
            S[n][3] = __expf(S[n][3] - mn1);
            s0 += S[n][0] + S[n][1];
            s1 += S[n][2] + S[n][3];
        }
        s0 += __shfl_xor_sync(0xffffffffu, s0, 1);
        s0 += __shfl_xor_sync(0xffffffffu, s0, 2);
        s1 += __shfl_xor_sync(0xffffffffu, s1, 1);
        s1 += __shfl_xor_sync(0xffffffffu, s1, 2);

        l0 = l0 * fac0 + s0;
        l1 = l1 * fac1 + s1;
        m0 = mn0; m1 = mn1;

#pragma unroll
        for (int n = 0; n < 8; n++) {
            O[n][0] *= fac0; O[n][1] *= fac0;
            O[n][2] *= fac1; O[n][3] *= fac1;
        }

        // ---- O += P @ V (P packed in registers) ----
#pragma unroll
        for (int kk = 0; kk < 4; kk++) {
            uint32_t pa[4];
            pa[0] = packh2(S[2 * kk][0],     S[2 * kk][1]);
            pa[1] = packh2(S[2 * kk][2],     S[2 * kk][3]);
            pa[2] = packh2(S[2 * kk + 1][0], S[2 * kk + 1][1]);
            pa[3] = packh2(S[2 * kk + 1][2], S[2 * kk + 1][3]);
#pragma unroll
            for (int nd = 0; nd < 8; nd++) {
                uint32_t bv[2];
                ldsm_x2t(bv, sptr(&Vs[st][kk * 16 + lrow][nd * 8]));
                mma_f16(O[nd], pa, bv);
            }
        }
    }

    // ---- epilogue (fp16 out, stride Dd) ----
    const float inv0 = 1.f / l0, inv1 = 1.f / l1;
    __half* o0 = Og + (size_t)(b * Ss + qb * 128 + lq0) * Dd + h * HDd;
    __half* o1 = o0 + 8 * Dd;
#pragma unroll
    for (int nd = 0; nd < 8; nd++) {
        const int c0 = nd * 8 + 2 * t;
        *(__half2*)&o0[c0] = __floats2half2_rn(O[nd][0] * inv0, O[nd][1] * inv0);
        *(__half2*)&o1[c0] = __floats2half2_rn(O[nd][2] * inv1, O[nd][3] * inv1);
    }
}

// ---------------- residual add + LayerNorm (optional fp16 mirror) ----------------
template <int DUAL>
__global__ __launch_bounds__(256)
void add_ln_kernel(const float* __restrict__ a, const float* __restrict__ r,
                   const float* __restrict__ gamma, const float* __restrict__ beta,
                   float* __restrict__ out, __half* __restrict__ outh)
{
    const int t = blockIdx.x;
    const int tid = threadIdx.x;
    __shared__ float buf[Dd];
    __shared__ float red[20];

    float s = 0.f, sq = 0.f;
    for (int i = tid; i < Dd; i += 256) {
        float v = a[(size_t)t * Dd + i] + r[(size_t)t * Dd + i];
        buf[i] = v;
        s += v; sq += v * v;
    }
#pragma unroll
    for (int o = 16; o; o >>= 1) {
        s  += __shfl_xor_sync(0xffffffffu, s, o);
        sq += __shfl_xor_sync(0xffffffffu, sq, o);
    }
    if ((tid & 31) == 0) { red[tid >> 5] = s; red[8 + (tid >> 5)] = sq; }
    __syncthreads();
    if (tid == 0) {
        float ts = 0.f, tq = 0.f;
        for (int i = 0; i < 8; i++) { ts += red[i]; tq += red[8 + i]; }
        const float mu  = ts * (1.0f / Dd);
        const float var = tq * (1.0f / Dd) - mu * mu;
        red[16] = mu;
        red[17] = rsqrtf(var + 1e-6f);
    }
    __syncthreads();
    const float mu = red[16], rstd = red[17];
    for (int i = tid; i < Dd; i += 256) {
        const float v = (buf[i] - mu) * rstd * gamma[i] + beta[i];
        out[(size_t)t * Dd + i] = v;
        if (DUAL) outh[(size_t)t * Dd + i] = __float2half_rn(v);
    }
}

// ---------------- launch ----------------
extern "C" void kernel_launch(void* const* d_in, const int* in_sizes, int n_in,
                              void* d_out, int out_size)
{
    const float* x   = (const float*)d_in[0];
    const float* Wq  = (const float*)d_in[1];
    const float* bq  = (const float*)d_in[2];
    const float* Wk  = (const float*)d_in[3];
    const float* bk  = (const float*)d_in[4];
    const float* Wv  = (const float*)d_in[5];
    const float* bv  = (const float*)d_in[6];
    const float* Wo  = (const float*)d_in[7];
    const float* bo  = (const float*)d_in[8];
    const float* g1  = (const float*)d_in[9];
    const float* b1  = (const float*)d_in[10];
    const float* Wup = (const float*)d_in[11];
    const float* bup = (const float*)d_in[12];
    const float* Wdn = (const float*)d_in[13];
    const float* bdn = (const float*)d_in[14];
    const float* g2  = (const float*)d_in[15];
    const float* b2  = (const float*)d_in[16];
    float* out = (float*)d_out;

    float *proj, *x1, *bqkv;
    __half *xh, *wqkvh, *woh, *wuph, *wdnh;
    __half *qkvh, *midh, *x1h, *uph;
    cudaGetSymbolAddress((void**)&proj,  g_proj);
    cudaGetSymbolAddress((void**)&x1,    g_x1);
    cudaGetSymbolAddress((void**)&bqkv,  g_bqkv);
    cudaGetSymbolAddress((void**)&xh,    g_xh);
    cudaGetSymbolAddress((void**)&wqkvh, g_wqkvh);
    cudaGetSymbolAddress((void**)&woh,   g_woh);
    cudaGetSymbolAddress((void**)&wuph,  g_wuph);
    cudaGetSymbolAddress((void**)&wdnh,  g_wdnh);
    cudaGetSymbolAddress((void**)&qkvh,  g_qkvh);
    cudaGetSymbolAddress((void**)&midh,  g_midh);
    cudaGetSymbolAddress((void**)&x1h,   g_x1h);
    cudaGetSymbolAddress((void**)&uph,   g_uph);

    const dim3 blk(256);

    // fp32 -> fp16 conversions: 3 launches total
    f2h_qkv<<<3 * (Dd * Dd / 4) / 256, blk>>>(Wq, Wk, Wv, wqkvh);
    {
        const int chunks = (Tt * Dd + Dd * Dd + Dd * DFF + DFF * Dd) / 4;
        f2h_misc<<<chunks / 256, blk>>>(x, Wo, Wup, Wdn, xh, woh, wuph, wdnh);
    }
    bias_concat_kernel<<<QKVS / 256, blk>>>(bq, bk, bv, bqkv);

    // fused QKV projection (fp16 out, [Tt, 3072])
    gemm_h<0, 1><<<dim3(QKVS / 128, Tt / 128), blk>>>(xh, wqkvh, bqkv, qkvh, Tt, QKVS, Dd);

    // causal attention (fp16 in/out, 128 queries per CTA)
    attn_f16<<<dim3(Ss / 128, Bt * Hh), blk>>>(qkvh, midh);

    // output projection (fp32 out) + residual LN1 (dual out)
    gemm_h<0, 0><<<dim3(Dd / 128, Tt / 128), blk>>>(midh, woh, bo, proj, Tt, Dd, Dd);
    add_ln_kernel<1><<<Tt, blk>>>(x, proj, g1, b1, x1, x1h);

    // FFN
    gemm_h<1, 1><<<dim3(DFF / 128, Tt / 128), blk>>>(x1h, wuph, bup, uph, Tt, DFF, Dd);
    gemm_h<0, 0><<<dim3(Dd / 128, Tt / 128), blk>>>(uph, wdnh, bdn, proj, Tt, Dd, DFF);
    add_ln_kernel<0><<<Tt, blk>>>(x1, proj, g2, b2, out, nullptr);
}

// round 10
// speedup vs baseline: 7.3123x; 1.1566x over previous
#include <cuda_runtime.h>
#include <cuda_fp16.h>
#include <cstdint>

#define Bt  2
#define Ss  2048
#define Dd  1024
#define Hh  16
#define HDd 64
#define Tt  (Bt * Ss)      // 4096 tokens
#define DFF (4 * Dd)       // 4096
#define QKVS (3 * Dd)      // 3072: row stride of fused qkv output

// ---------------- scratch (device globals; no allocation allowed) ----------------
__device__ float  g_proj[Tt * Dd];
__device__ float  g_x1[Tt * Dd];
__device__ float  g_bqkv[QKVS];
__device__ __half g_xh[Tt * Dd];
__device__ __half g_wqkvh[(size_t)Dd * QKVS];
__device__ __half g_woh[Dd * Dd];
__device__ __half g_wuph[(size_t)Dd * DFF];
__device__ __half g_wdnh[(size_t)DFF * Dd];
__device__ __half g_qkvh[(size_t)Tt * QKVS];
__device__ __half g_midh[Tt * Dd];
__device__ __half g_x1h[Tt * Dd];
__device__ __half g_uph[(size_t)Tt * DFF];

// ---------------- helpers ----------------
__device__ __forceinline__ void mma_f16(float* d, const uint32_t* a, const uint32_t* b) {
    asm volatile(
        "mma.sync.aligned.m16n8k16.row.col.f32.f16.f16.f32 "
        "{%0,%1,%2,%3}, {%4,%5,%6,%7}, {%8,%9}, {%0,%1,%2,%3};"
        : "+f"(d[0]), "+f"(d[1]), "+f"(d[2]), "+f"(d[3])
        : "r"(a[0]), "r"(a[1]), "r"(a[2]), "r"(a[3]), "r"(b[0]), "r"(b[1]));
}
__device__ __forceinline__ uint32_t sptr(const void* p) {
    return (uint32_t)__cvta_generic_to_shared(p);
}
__device__ __forceinline__ void ldsm_x4(uint32_t* r, uint32_t addr) {
    asm volatile("ldmatrix.sync.aligned.m8n8.x4.shared.b16 {%0,%1,%2,%3}, [%4];"
                 : "=r"(r[0]), "=r"(r[1]), "=r"(r[2]), "=r"(r[3]) : "r"(addr));
}
__device__ __forceinline__ void ldsm_x2t(uint32_t* r, uint32_t addr) {
    asm volatile("ldmatrix.sync.aligned.m8n8.x2.trans.shared.b16 {%0,%1}, [%2];"
                 : "=r"(r[0]), "=r"(r[1]) : "r"(addr));
}
__device__ __forceinline__ uint32_t packh2(float x, float y) {
    __half2 h = __floats2half2_rn(x, y);
    return *reinterpret_cast<uint32_t*>(&h);
}
__device__ __forceinline__ void cp_async16(uint32_t dst, const void* src) {
    asm volatile("cp.async.cg.shared.global [%0], [%1], 16;" :: "r"(dst), "l"(src));
}
__device__ __forceinline__ void cp_commit() {
    asm volatile("cp.async.commit_group;" ::: "memory");
}
template <int N>
__device__ __forceinline__ void cp_wait() {
    asm volatile("cp.async.wait_group %0;" :: "n"(N) : "memory");
}

// ---------------- fp32 -> fp16 converters (consolidated) ----------------
#define DD4 (Dd * Dd / 4)
__global__ __launch_bounds__(256)
void f2h_qkv(const float* __restrict__ Wq, const float* __restrict__ Wk,
             const float* __restrict__ Wv, __half* __restrict__ out)
{
    const int idx = blockIdx.x * 256 + threadIdx.x;
    const int seg = idx / DD4;
    const int j = (idx - seg * DD4) * 4;
    const float* W = (seg == 0) ? Wq : (seg == 1) ? Wk : Wv;
    const int r = j >> 10, c = j & 1023;
    float4 v = *(const float4*)&W[j];
    __half* o = out + (size_t)r * QKVS + seg * Dd + c;
    *(__half2*)&o[0] = __floats2half2_rn(v.x, v.y);
    *(__half2*)&o[2] = __floats2half2_rn(v.z, v.w);
}
__global__ __launch_bounds__(256)
void f2h_misc(const float* __restrict__ x,   const float* __restrict__ Wo,
              const float* __restrict__ Wup, const float* __restrict__ Wdn,
              __half* __restrict__ xh,   __half* __restrict__ woh,
              __half* __restrict__ wuph, __half* __restrict__ wdnh)
{
    const int c0 = Tt * Dd / 4, c1 = Dd * Dd / 4, c2 = Dd * DFF / 4;
    int idx = blockIdx.x * 256 + threadIdx.x;
    const float* in; __half* out;
    if (idx < c0)                 { in = x;   out = xh; }
    else if ((idx -= c0) < c1)    { in = Wo;  out = woh; }
    else if ((idx -= c1) < c2)    { in = Wup; out = wuph; }
    else { idx -= c2;               in = Wdn; out = wdnh; }
    const int j = idx * 4;
    float4 v = *(const float4*)&in[j];
    *(__half2*)&out[j]     = __floats2half2_rn(v.x, v.y);
    *(__half2*)&out[j + 2] = __floats2half2_rn(v.z, v.w);
}
__global__ __launch_bounds__(256)
void bias_concat_kernel(const float* __restrict__ bq, const float* __restrict__ bk,
                        const float* __restrict__ bv, float* __restrict__ out)
{
    const int i = blockIdx.x * 256 + threadIdx.x;
    if (i < Dd)            out[i] = bq[i];
    else if (i < 2 * Dd)   out[i] = bk[i - Dd];
    else if (i < 3 * Dd)   out[i] = bv[i - 2 * Dd];
}

// ---------------- FP16 GEMM: 3-stage cp.async, XOR-swizzled smem ----------------
// C[M,N] = A[M,K] @ W[K,N] + bias (+ReLU). Block 128x128, K-chunk 32, 256 thr.
// A stage: 128 rows x 64B, phys16Bchunk = c ^ ((r>>1)&3). 8192B/stage.
// B stage: 32 rows x 256B,  phys16Bchunk = c ^ (r&7).     8192B/stage.
// 3 stages x 16KB = 48KB. One __syncthreads per chunk.
template <int RELU, int OUTH>
__global__ __launch_bounds__(256, 2)
void gemm_h(const __half* __restrict__ A, const __half* __restrict__ W,
            const float* __restrict__ bias, void* __restrict__ Cout,
            int M, int N, int K)
{
    __shared__ __align__(128) __half sm[24576];   // 49152 B

    const int tid  = threadIdx.x;
    const int lane = tid & 31;
    const int wid  = tid >> 5;
    const int wm   = (wid & 1) * 64;
    const int wn   = (wid >> 1) * 32;
    const int m0   = blockIdx.y << 7;
    const int n0   = blockIdx.x << 7;

    const int row  = lane >> 2;
    const int col  = lane & 3;
    const int lrow = lane & 15;
    const int lc0  = lane >> 4;          // A logical 16B-chunk (0/1) for ks=0

    const uint32_t SA0 = sptr(sm);           // A stages: [0, 24576)B
    const uint32_t SB0 = SA0 + 24576;        // B stages: [24576, 49152)B

    // cp.async assignments
    const int a_r  = tid >> 2;           // A rows 0..63 (+64)
    const int a_cc = tid & 3;            // A 16B chunk
    const int b_r  = tid >> 4;           // B rows 0..15 (+16)
    const int b_cc = tid & 15;           // B 16B chunk

    float acc[4][4][4];
#pragma unroll
    for (int mi = 0; mi < 4; mi++)
#pragma unroll
        for (int ni = 0; ni < 4; ni++)
#pragma unroll
            for (int j = 0; j < 4; j++) acc[mi][ni][j] = 0.f;

    const int nk = K >> 5;

    // swizzled dst offsets are stage-invariant; rows r and r+64 (A), r and r+16 (B)
    // share the same swizzle term, so second copy = first + 4096B.
    const uint32_t dA = a_r * 64 + ((uint32_t)(a_cc ^ ((a_r >> 1) & 3)) << 4);
    const uint32_t dB = b_r * 256 + ((uint32_t)(b_cc ^ (b_r & 7)) << 4);

    auto load_stage = [&](int c, int st) {
        const __half* Ab = A + (size_t)(m0 + a_r) * K + (c << 5) + a_cc * 8;
        const uint32_t da = SA0 + st * 8192 + dA;
        cp_async16(da,        Ab);
        cp_async16(da + 4096, Ab + (size_t)64 * K);
        const __half* Bb = W + (size_t)((c << 5) + b_r) * N + n0 + b_cc * 8;
        const uint32_t db = SB0 + st * 8192 + dB;
        cp_async16(db,        Bb);
        cp_async16(db + 4096, Bb + (size_t)16 * N);
    };

    load_stage(0, 0); cp_commit();
    load_stage(1, 1); cp_commit();

    int st = 0, stL = 2;
    for (int c = 0; c < nk; c++) {
        if (c + 1 < nk) cp_wait<1>(); else cp_wait<0>();
        __syncthreads();   // stage st data visible; stage stL consumers (iter c-1) done
        if (c + 2 < nk) { load_stage(c + 2, stL); cp_commit(); }

        const uint32_t SA = SA0 + st * 8192;
        const uint32_t SB = SB0 + st * 8192;

        // all fragments up-front for maximal LDSM overlap
        uint32_t a0[4][4], a1[4][4], b0[4][2], b1[4][2];
#pragma unroll
        for (int mi = 0; mi < 4; mi++) {
            const int rr = wm + mi * 16 + lrow;
            const uint32_t rb = SA + rr * 64;
            const uint32_t sw = (uint32_t)((rr >> 1) & 3) << 4;
            ldsm_x4(a0[mi], rb + (((uint32_t)lc0 << 4) ^ sw));
            ldsm_x4(a1[mi], rb + (((uint32_t)(lc0 + 2) << 4) ^ sw));
        }
#pragma unroll
        for (int ni = 0; ni < 4; ni++) {
            const uint32_t lcb = (uint32_t)((wn + ni * 8) >> 3) << 4;
            const uint32_t swb = (uint32_t)(lrow & 7) << 4;
            ldsm_x2t(b0[ni], SB + lrow * 256        + (lcb ^ swb));
            ldsm_x2t(b1[ni], SB + (16 + lrow) * 256 + (lcb ^ swb));
        }
#pragma unroll
        for (int mi = 0; mi < 4; mi++)
#pragma unroll
            for (int ni = 0; ni < 4; ni++)
                mma_f16(acc[mi][ni], a0[mi], b0[ni]);
#pragma unroll
        for (int mi = 0; mi < 4; mi++)
#pragma unroll
            for (int ni = 0; ni < 4; ni++)
                mma_f16(acc[mi][ni], a1[mi], b1[ni]);

        st = (st == 2) ? 0 : st + 1;
        stL = (stL == 2) ? 0 : stL + 1;
    }

    // epilogue: direct stores
#pragma unroll
    for (int mi = 0; mi < 4; mi++) {
        const int r0 = m0 + wm + mi * 16 + row;
#pragma unroll
        for (int ni = 0; ni < 4; ni++) {
            const int c0 = n0 + wn + ni * 8 + 2 * col;
            const float bb0 = bias[c0], bb1 = bias[c0 + 1];
            float v00 = acc[mi][ni][0] + bb0, v01 = acc[mi][ni][1] + bb1;
            float v10 = acc[mi][ni][2] + bb0, v11 = acc[mi][ni][3] + bb1;
            if (RELU) {
                v00 = fmaxf(v00, 0.f); v01 = fmaxf(v01, 0.f);
                v10 = fmaxf(v10, 0.f); v11 = fmaxf(v11, 0.f);
            }
            if (OUTH) {
                __half* Ch = (__half*)Cout;
                *(__half2*)&Ch[(size_t)r0 * N + c0]       = __floats2half2_rn(v00, v01);
                *(__half2*)&Ch[(size_t)(r0 + 8) * N + c0] = __floats2half2_rn(v10, v11);
            } else {
                float* Cf = (float*)Cout;
                *(float2*)&Cf[(size_t)r0 * N + c0]       = make_float2(v00, v01);
                *(float2*)&Cf[(size_t)(r0 + 8) * N + c0] = make_float2(v10, v11);
            }
        }
    }
}

// ---------------- FP16 causal flash attention (unchanged from R9) ----------------
__global__ __launch_bounds__(256)
void attn_f16(const __half* __restrict__ QKV, __half* __restrict__ Og)
{
    __shared__ __half Ks[2][64][72];
    __shared__ __half Vs[2][64][72];

    const int tid  = threadIdx.x;
    const int lane = tid & 31;
    const int wid  = tid >> 5;
    const int g    = lane >> 2;
    const int t    = lane & 3;
    const int lrow = lane & 15;
    const int qb   = (int)gridDim.x - 1 - (int)blockIdx.x;
    const int bh   = blockIdx.y;
    const int b    = bh >> 4, h = bh & 15;

    const __half* Qb = QKV + (size_t)b * Ss * QKVS + h * HDd;
    const __half* Kb = Qb + Dd;
    const __half* Vb = Qb + 2 * Dd;

    const __half2 hs = __floats2half2_rn(0.125f, 0.125f);
    for (int i = tid; i < 128 * 8; i += 256) {
        const int r = i >> 3, c8 = (i & 7) * 8;
        uint4 q4 = *(const uint4*)&Qb[(size_t)(qb * 128 + r) * QKVS + c8];
        __half2* p = (__half2*)&q4;
        p[0] = __hmul2(p[0], hs); p[1] = __hmul2(p[1], hs);
        p[2] = __hmul2(p[2], hs); p[3] = __hmul2(p[3], hs);
        if (r < 64) *(uint4*)&Ks[0][r][c8]      = q4;
        else        *(uint4*)&Vs[0][r - 64][c8] = q4;
    }
    __syncthreads();

    uint32_t qf[4][4];
    {
        const __half (*Qs)[72] = (wid < 4) ? Ks[0] : Vs[0];
        const int qr = (wid * 16) % 64 + g;
#pragma unroll
        for (int s = 0; s < 4; s++) {
            qf[s][0] = *(const uint32_t*)&Qs[qr][s * 16 + 2 * t];
            qf[s][1] = *(const uint32_t*)&Qs[qr + 8][s * 16 + 2 * t];
            qf[s][2] = *(const uint32_t*)&Qs[qr][s * 16 + 2 * t + 8];
            qf[s][3] = *(const uint32_t*)&Qs[qr + 8][s * 16 + 2 * t + 8];
        }
    }
    __syncthreads();

    const int kv_r = tid >> 3;
    const int kv_c = (tid & 7) * 8;

    auto load_kv = [&](int kt, int st) {
#pragma unroll
        for (int j = 0; j < 2; j++) {
            const int r = kv_r + j * 32;
            const size_t off = (size_t)(kt * 64 + r) * QKVS + kv_c;
            cp_async16(sptr(&Ks[st][r][kv_c]), Kb + off);
            cp_async16(sptr(&Vs[st][r][kv_c]), Vb + off);
        }
    };

    load_kv(0, 0);
    cp_commit();

    float m0 = -1e30f, m1 = -1e30f, l0 = 0.f, l1 = 0.f;
    float O[8][4];
#pragma unroll
    for (int n = 0; n < 8; n++)
#pragma unroll
        for (int j = 0; j < 4; j++) O[n][j] = 0.f;

    const int lq0 = wid * 16 + g;
    const int qg0 = qb * 128 + lq0;
    const int qg1 = qg0 + 8;
    const int wmax = qb * 128 + wid * 16 + 15;

    const int nkt = 2 * qb + 2;
    for (int kt = 0; kt < nkt; kt++) {
        const int st = kt & 1;
        __syncthreads();
        if (kt + 1 < nkt) {
            load_kv(kt + 1, st ^ 1);
            cp_commit();
            cp_wait<1>();
        } else {
            cp_wait<0>();
        }
        __syncthreads();

        if (kt * 64 > wmax) continue;

        float S[8][4];
#pragma unroll
        for (int n = 0; n < 8; n++)
#pragma unroll
            for (int j = 0; j < 4; j++) S[n][j] = 0.f;

#pragma unroll
        for (int s = 0; s < 4; s++) {
#pragma unroll
            for (int n = 0; n < 8; n++) {
                uint32_t bq[2];
                bq[0] = *(const uint32_t*)&Ks[st][n * 8 + g][s * 16 + 2 * t];
                bq[1] = *(const uint32_t*)&Ks[st][n * 8 + g][s * 16 + 2 * t + 8];
                mma_f16(S[n], qf[s], bq);
            }
        }

        if (kt >= 2 * qb) {
#pragma unroll
            for (int n = 0; n < 8; n++) {
                const int kg = kt * 64 + n * 8 + 2 * t;
                if (kg     > qg0) S[n][0] = -1e30f;
                if (kg + 1 > qg0) S[n][1] = -1e30f;
                if (kg     > qg1) S[n][2] = -1e30f;
                if (kg + 1 > qg1) S[n][3] = -1e30f;
            }
        }

        float mx0 = -1e30f, mx1 = -1e30f;
#pragma unroll
        for (int n = 0; n < 8; n++) {
            mx0 = fmaxf(mx0, fmaxf(S[n][0], S[n][1]));
            mx1 = fmaxf(mx1, fmaxf(S[n][2], S[n][3]));
        }
        mx0 = fmaxf(mx0, __shfl_xor_sync(0xffffffffu, mx0, 1));
        mx0 = fmaxf(mx0, __shfl_xor_sync(0xffffffffu, mx0, 2));
        mx1 = fmaxf(mx1, __shfl_xor_sync(0xffffffffu, mx1, 1));
        mx1 = fmaxf(mx1, __shfl_xor_sync(0xffffffffu, mx1, 2));

        const float mn0 = fmaxf(m0, mx0), mn1 = fmaxf(m1, mx1);
        const float fac0 = __expf(m0 - mn0), fac1 = __expf(m1 - mn1);

        float s0 = 0.f, s1 = 0.f;
#pragma unroll
        for (int n = 0; n < 8; n++) {
            S[n][0] = __expf(S[n][0] - mn0);
            S[n][1] = __expf(S[n][1] - mn0);
            S[n][2] = __expf(S[n][2] - mn1);
            S[n][3] = __expf(S[n][3] - mn1);
            s0 += S[n][0] + S[n][1];
            s1 += S[n][2] + S[n][3];
        }
        s0 += __shfl_xor_sync(0xffffffffu, s0, 1);
        s0 += __shfl_xor_sync(0xffffffffu, s0, 2);
        s1 += __shfl_xor_sync(0xffffffffu, s1, 1);
        s1 += __shfl_xor_sync(0xffffffffu, s1, 2);

        l0 = l0 * fac0 + s0;
        l1 = l1 * fac1 + s1;
        m0 = mn0; m1 = mn1;

#pragma unroll
        for (int n = 0; n < 8; n++) {
            O[n][0] *= fac0; O[n][1] *= fac0;
            O[n][2] *= fac1; O[n][3] *= fac1;
        }

#pragma unroll
        for (int kk = 0; kk < 4; kk++) {
            uint32_t pa[4];
            pa[0] = packh2(S[2 * kk][0],     S[2 * kk][1]);
            pa[1] = packh2(S[2 * kk][2],     S[2 * kk][3]);
            pa[2] = packh2(S[2 * kk + 1][0], S[2 * kk + 1][1]);
            pa[3] = packh2(S[2 * kk + 1][2], S[2 * kk + 1][3]);
#pragma unroll
            for (int nd = 0; nd < 8; nd++) {
                uint32_t bv[2];
                ldsm_x2t(bv, sptr(&Vs[st][kk * 16 + lrow][nd * 8]));
                mma_f16(O[nd], pa, bv);
            }
        }
    }

    const float inv0 = 1.f / l0, inv1 = 1.f / l1;
    __half* o0 = Og + (size_t)(b * Ss + qb * 128 + lq0) * Dd + h * HDd;
    __half* o1 = o0 + 8 * Dd;
#pragma unroll
    for (int nd = 0; nd < 8; nd++) {
        const int c0 = nd * 8 + 2 * t;
        *(__half2*)&o0[c0] = __floats2half2_rn(O[nd][0] * inv0, O[nd][1] * inv0);
        *(__half2*)&o1[c0] = __floats2half2_rn(O[nd][2] * inv1, O[nd][3] * inv1);
    }
}

// ---------------- residual add + LayerNorm (optional fp16 mirror) ----------------
template <int DUAL>
__global__ __launch_bounds__(256)
void add_ln_kernel(const float* __restrict__ a, const float* __restrict__ r,
                   const float* __restrict__ gamma, const float* __restrict__ beta,
                   float* __restrict__ out, __half* __restrict__ outh)
{
    const int t = blockIdx.x;
    const int tid = threadIdx.x;
    __shared__ float buf[Dd];
    __shared__ float red[20];

    float s = 0.f, sq = 0.f;
    for (int i = tid; i < Dd; i += 256) {
        float v = a[(size_t)t * Dd + i] + r[(size_t)t * Dd + i];
        buf[i] = v;
        s += v; sq += v * v;
    }
#pragma unroll
    for (int o = 16; o; o >>= 1) {
        s  += __shfl_xor_sync(0xffffffffu, s, o);
        sq += __shfl_xor_sync(0xffffffffu, sq, o);
    }
    if ((tid & 31) == 0) { red[tid >> 5] = s; red[8 + (tid >> 5)] = sq; }
    __syncthreads();
    if (tid == 0) {
        float ts = 0.f, tq = 0.f;
        for (int i = 0; i < 8; i++) { ts += red[i]; tq += red[8 + i]; }
        const float mu  = ts * (1.0f / Dd);
        const float var = tq * (1.0f / Dd) - mu * mu;
        red[16] = mu;
        red[17] = rsqrtf(var + 1e-6f);
    }
    __syncthreads();
    const float mu = red[16], rstd = red[17];
    for (int i = tid; i < Dd; i += 256) {
        const float v = (buf[i] - mu) * rstd * gamma[i] + beta[i];
        out[(size_t)t * Dd + i] = v;
        if (DUAL) outh[(size_t)t * Dd + i] = __float2half_rn(v);
    }
}

// ---------------- launch ----------------
extern "C" void kernel_launch(void* const* d_in, const int* in_sizes, int n_in,
                              void* d_out, int out_size)
{
    const float* x   = (const float*)d_in[0];
    const float* Wq  = (const float*)d_in[1];
    const float* bq  = (const float*)d_in[2];
    const float* Wk  = (const float*)d_in[3];
    const float* bk  = (const float*)d_in[4];
    const float* Wv  = (const float*)d_in[5];
    const float* bv  = (const float*)d_in[6];
    const float* Wo  = (const float*)d_in[7];
    const float* bo  = (const float*)d_in[8];
    const float* g1  = (const float*)d_in[9];
    const float* b1  = (const float*)d_in[10];
    const float* Wup = (const float*)d_in[11];
    const float* bup = (const float*)d_in[12];
    const float* Wdn = (const float*)d_in[13];
    const float* bdn = (const float*)d_in[14];
    const float* g2  = (const float*)d_in[15];
    const float* b2  = (const float*)d_in[16];
    float* out = (float*)d_out;

    float *proj, *x1, *bqkv;
    __half *xh, *wqkvh, *woh, *wuph, *wdnh;
    __half *qkvh, *midh, *x1h, *uph;
    cudaGetSymbolAddress((void**)&proj,  g_proj);
    cudaGetSymbolAddress((void**)&x1,    g_x1);
    cudaGetSymbolAddress((void**)&bqkv,  g_bqkv);
    cudaGetSymbolAddress((void**)&xh,    g_xh);
    cudaGetSymbolAddress((void**)&wqkvh, g_wqkvh);
    cudaGetSymbolAddress((void**)&woh,   g_woh);
    cudaGetSymbolAddress((void**)&wuph,  g_wuph);
    cudaGetSymbolAddress((void**)&wdnh,  g_wdnh);
    cudaGetSymbolAddress((void**)&qkvh,  g_qkvh);
    cudaGetSymbolAddress((void**)&midh,  g_midh);
    cudaGetSymbolAddress((void**)&x1h,   g_x1h);
    cudaGetSymbolAddress((void**)&uph,   g_uph);

    const dim3 blk(256);

    f2h_qkv<<<3 * (Dd * Dd / 4) / 256, blk>>>(Wq, Wk, Wv, wqkvh);
    {
        const int chunks = (Tt * Dd + Dd * Dd + Dd * DFF + DFF * Dd) / 4;
        f2h_misc<<<chunks / 256, blk>>>(x, Wo, Wup, Wdn, xh, woh, wuph, wdnh);
    }
    bias_concat_kernel<<<QKVS / 256, blk>>>(bq, bk, bv, bqkv);

    gemm_h<0, 1><<<dim3(QKVS / 128, Tt / 128), blk>>>(xh, wqkvh, bqkv, qkvh, Tt, QKVS, Dd);

    attn_f16<<<dim3(Ss / 128, Bt * Hh), blk>>>(qkvh, midh);

    gemm_h<0, 0><<<dim3(Dd / 128, Tt / 128), blk>>>(midh, woh, bo, proj, Tt, Dd, Dd);
    add_ln_kernel<1><<<Tt, blk>>>(x, proj, g1, b1, x1, x1h);

    gemm_h<1, 1><<<dim3(DFF / 128, Tt / 128), blk>>>(x1h, wuph, bup, uph, Tt, DFF, Dd);
    gemm_h<0, 0><<<dim3(Dd / 128, Tt / 128), blk>>>(uph, wdnh, bdn, proj, Tt, Dd, DFF);
    add_ln_kernel<0><<<Tt, blk>>>(x1, proj, g2, b2, out, nullptr);
}

// round 11
// speedup vs baseline: 7.8937x; 1.0795x over previous
#include <cuda_runtime.h>
#include <cuda_fp16.h>
#include <cstdint>

#define Bt  2
#define Ss  2048
#define Dd  1024
#define Hh  16
#define HDd 64
#define Tt  (Bt * Ss)      // 4096 tokens
#define DFF (4 * Dd)       // 4096
#define QKVS (3 * Dd)      // 3072

// ---------------- scratch (device globals; no allocation allowed) ----------------
__device__ float  g_proj[Tt * Dd];
__device__ float  g_x1[Tt * Dd];
__device__ float  g_bqkv[QKVS];
__device__ __half g_xh[Tt * Dd];
__device__ __half g_wqkvh[(size_t)Dd * QKVS];
__device__ __half g_woh[Dd * Dd];
__device__ __half g_wuph[(size_t)Dd * DFF];
__device__ __half g_wdnh[(size_t)DFF * Dd];
__device__ __half g_qkvh[(size_t)Tt * QKVS];
__device__ __half g_midh[Tt * Dd];
__device__ __half g_x1h[Tt * Dd];
__device__ __half g_uph[(size_t)Tt * DFF];

// ---------------- helpers ----------------
__device__ __forceinline__ void mma_f16(float* d, const uint32_t* a, const uint32_t* b) {
    asm volatile(
        "mma.sync.aligned.m16n8k16.row.col.f32.f16.f16.f32 "
        "{%0,%1,%2,%3}, {%4,%5,%6,%7}, {%8,%9}, {%0,%1,%2,%3};"
        : "+f"(d[0]), "+f"(d[1]), "+f"(d[2]), "+f"(d[3])
        : "r"(a[0]), "r"(a[1]), "r"(a[2]), "r"(a[3]), "r"(b[0]), "r"(b[1]));
}
__device__ __forceinline__ uint32_t sptr(const void* p) {
    return (uint32_t)__cvta_generic_to_shared(p);
}
__device__ __forceinline__ void ldsm_x4(uint32_t* r, uint32_t addr) {
    asm volatile("ldmatrix.sync.aligned.m8n8.x4.shared.b16 {%0,%1,%2,%3}, [%4];"
                 : "=r"(r[0]), "=r"(r[1]), "=r"(r[2]), "=r"(r[3]) : "r"(addr));
}
__device__ __forceinline__ void ldsm_x2t(uint32_t* r, uint32_t addr) {
    asm volatile("ldmatrix.sync.aligned.m8n8.x2.trans.shared.b16 {%0,%1}, [%2];"
                 : "=r"(r[0]), "=r"(r[1]) : "r"(addr));
}
__device__ __forceinline__ uint32_t packh2(float x, float y) {
    __half2 h = __floats2half2_rn(x, y);
    return *reinterpret_cast<uint32_t*>(&h);
}
__device__ __forceinline__ void cp_async16(uint32_t dst, const void* src) {
    asm volatile("cp.async.cg.shared.global [%0], [%1], 16;" :: "r"(dst), "l"(src));
}
__device__ __forceinline__ void cp_commit() {
    asm volatile("cp.async.commit_group;" ::: "memory");
}
template <int N>
__device__ __forceinline__ void cp_wait() {
    asm volatile("cp.async.wait_group %0;" :: "n"(N) : "memory");
}

// ---------------- fp32 -> fp16 converters (consolidated) ----------------
#define DD4 (Dd * Dd / 4)
__global__ __launch_bounds__(256)
void f2h_qkv(const float* __restrict__ Wq, const float* __restrict__ Wk,
             const float* __restrict__ Wv, __half* __restrict__ out)
{
    const int idx = blockIdx.x * 256 + threadIdx.x;
    const int seg = idx / DD4;
    const int j = (idx - seg * DD4) * 4;
    const float* W = (seg == 0) ? Wq : (seg == 1) ? Wk : Wv;
    const int r = j >> 10, c = j & 1023;
    float4 v = *(const float4*)&W[j];
    __half* o = out + (size_t)r * QKVS + seg * Dd + c;
    *(__half2*)&o[0] = __floats2half2_rn(v.x, v.y);
    *(__half2*)&o[2] = __floats2half2_rn(v.z, v.w);
}
__global__ __launch_bounds__(256)
void f2h_misc(const float* __restrict__ x,   const float* __restrict__ Wo,
              const float* __restrict__ Wup, const float* __restrict__ Wdn,
              __half* __restrict__ xh,   __half* __restrict__ woh,
              __half* __restrict__ wuph, __half* __restrict__ wdnh)
{
    const int c0 = Tt * Dd / 4, c1 = Dd * Dd / 4, c2 = Dd * DFF / 4;
    int idx = blockIdx.x * 256 + threadIdx.x;
    const float* in; __half* out;
    if (idx < c0)                 { in = x;   out = xh; }
    else if ((idx -= c0) < c1)    { in = Wo;  out = woh; }
    else if ((idx -= c1) < c2)    { in = Wup; out = wuph; }
    else { idx -= c2;               in = Wdn; out = wdnh; }
    const int j = idx * 4;
    float4 v = *(const float4*)&in[j];
    *(__half2*)&out[j]     = __floats2half2_rn(v.x, v.y);
    *(__half2*)&out[j + 2] = __floats2half2_rn(v.z, v.w);
}
__global__ __launch_bounds__(256)
void bias_concat_kernel(const float* __restrict__ bq, const float* __restrict__ bk,
                        const float* __restrict__ bv, float* __restrict__ out)
{
    const int i = blockIdx.x * 256 + threadIdx.x;
    if (i < Dd)            out[i] = bq[i];
    else if (i < 2 * Dd)   out[i] = bk[i - Dd];
    else if (i < 3 * Dd)   out[i] = bv[i - 2 * Dd];
}

// ---------------- FP16 GEMM: K-chunk 64, 2-stage cp.async, 64KB dynamic smem ----------------
// A stage: 128 rows x 128B, phys16Bchunk = c ^ (r&7). 16KB.
// B stage: 64 rows x 256B,  phys16Bchunk = c ^ (r&7). 16KB.
// Stages: A at 0/16384, B at 32768/49152. One __syncthreads per chunk.
template <int RELU, int OUTH>
__global__ __launch_bounds__(256, 2)
void gemm_h(const __half* __restrict__ A, const __half* __restrict__ W,
            const float* __restrict__ bias, void* __restrict__ Cout,
            int M, int N, int K)
{
    extern __shared__ __align__(128) __half sm[];

    const int tid  = threadIdx.x;
    const int lane = tid & 31;
    const int wid  = tid >> 5;
    const int wm   = (wid & 1) * 64;
    const int wn   = (wid >> 1) * 32;
    const int m0   = blockIdx.y << 7;
    const int n0   = blockIdx.x << 7;

    const int row  = lane >> 2;
    const int col  = lane & 3;
    const int lrow = lane & 15;
    const int lc0  = lane >> 4;          // 0/1: A 16B chunk within k16

    const uint32_t SA0 = sptr(sm);          // A: [0, 32768)
    const uint32_t SB0 = SA0 + 32768;       // B: [32768, 65536)

    // cp.async assignment: A rows tid>>3 (+32 x4), chunk tid&7; B rows tid>>4 (+16 x4), chunk tid&15
    const int a_r  = tid >> 3;
    const int a_cc = tid & 7;
    const int b_r  = tid >> 4;
    const int b_cc = tid & 15;

    const uint32_t dA = a_r * 128 + ((uint32_t)(a_cc ^ (a_r & 7)) << 4);
    const uint32_t dB = b_r * 256 + ((uint32_t)(b_cc ^ (b_r & 7)) << 4);

    float acc[4][4][4];
#pragma unroll
    for (int mi = 0; mi < 4; mi++)
#pragma unroll
        for (int ni = 0; ni < 4; ni++)
#pragma unroll
            for (int j = 0; j < 4; j++) acc[mi][ni][j] = 0.f;

    const int nk = K >> 6;

    auto load_stage = [&](int c, int st) {
        const __half* Ab = A + (size_t)(m0 + a_r) * K + (c << 6) + a_cc * 8;
        const uint32_t da = SA0 + st * 16384 + dA;
#pragma unroll
        for (int j = 0; j < 4; j++)
            cp_async16(da + j * 4096, Ab + (size_t)(32 * j) * K);
        const __half* Bb = W + (size_t)((c << 6) + b_r) * N + n0 + b_cc * 8;
        const uint32_t db = SB0 + st * 16384 + dB;
#pragma unroll
        for (int j = 0; j < 4; j++)
            cp_async16(db + j * 4096, Bb + (size_t)(16 * j) * N);
    };

    load_stage(0, 0);
    cp_commit();

    for (int c = 0; c < nk; c++) {
        const int st = c & 1;
        cp_wait<0>();        // chunk c resident
        __syncthreads();     // all warps done reading stage st (iter c-1's other stage)
        if (c + 1 < nk) { load_stage(c + 1, st ^ 1); cp_commit(); }

        const uint32_t SA = SA0 + st * 16384;
        const uint32_t SB = SB0 + st * 16384;

#pragma unroll
        for (int ks = 0; ks < 4; ks++) {
            uint32_t a[4][4], b[4][2];
#pragma unroll
            for (int mi = 0; mi < 4; mi++) {
                const int rr = wm + mi * 16 + lrow;
                ldsm_x4(a[mi], SA + rr * 128 +
                        ((uint32_t)((2 * ks + lc0) ^ (rr & 7)) << 4));
            }
#pragma unroll
            for (int ni = 0; ni < 4; ni++) {
                const int kr = ks * 16 + lrow;
                ldsm_x2t(b[ni], SB + kr * 256 +
                         ((uint32_t)((((wn >> 3) + ni)) ^ (kr & 7)) << 4));
            }
#pragma unroll
            for (int mi = 0; mi < 4; mi++)
#pragma unroll
                for (int ni = 0; ni < 4; ni++)
                    mma_f16(acc[mi][ni], a[mi], b[ni]);
        }
    }

    // epilogue: direct stores
#pragma unroll
    for (int mi = 0; mi < 4; mi++) {
        const int r0 = m0 + wm + mi * 16 + row;
#pragma unroll
        for (int ni = 0; ni < 4; ni++) {
            const int c0 = n0 + wn + ni * 8 + 2 * col;
            const float bb0 = bias[c0], bb1 = bias[c0 + 1];
            float v00 = acc[mi][ni][0] + bb0, v01 = acc[mi][ni][1] + bb1;
            float v10 = acc[mi][ni][2] + bb0, v11 = acc[mi][ni][3] + bb1;
            if (RELU) {
                v00 = fmaxf(v00, 0.f); v01 = fmaxf(v01, 0.f);
                v10 = fmaxf(v10, 0.f); v11 = fmaxf(v11, 0.f);
            }
            if (OUTH) {
                __half* Ch = (__half*)Cout;
                *(__half2*)&Ch[(size_t)r0 * N + c0]       = __floats2half2_rn(v00, v01);
                *(__half2*)&Ch[(size_t)(r0 + 8) * N + c0] = __floats2half2_rn(v10, v11);
            } else {
                float* Cf = (float*)Cout;
                *(float2*)&Cf[(size_t)r0 * N + c0]       = make_float2(v00, v01);
                *(float2*)&Cf[(size_t)(r0 + 8) * N + c0] = make_float2(v10, v11);
            }
        }
    }
}

// ---------------- FP16 causal flash attention (unchanged from R10) ----------------
__global__ __launch_bounds__(256)
void attn_f16(const __half* __restrict__ QKV, __half* __restrict__ Og)
{
    __shared__ __half Ks[2][64][72];
    __shared__ __half Vs[2][64][72];

    const int tid  = threadIdx.x;
    const int lane = tid & 31;
    const int wid  = tid >> 5;
    const int g    = lane >> 2;
    const int t    = lane & 3;
    const int lrow = lane & 15;
    const int qb   = (int)gridDim.x - 1 - (int)blockIdx.x;
    const int bh   = blockIdx.y;
    const int b    = bh >> 4, h = bh & 15;

    const __half* Qb = QKV + (size_t)b * Ss * QKVS + h * HDd;
    const __half* Kb = Qb + Dd;
    const __half* Vb = Qb + 2 * Dd;

    const __half2 hs = __floats2half2_rn(0.125f, 0.125f);
    for (int i = tid; i < 128 * 8; i += 256) {
        const int r = i >> 3, c8 = (i & 7) * 8;
        uint4 q4 = *(const uint4*)&Qb[(size_t)(qb * 128 + r) * QKVS + c8];
        __half2* p = (__half2*)&q4;
        p[0] = __hmul2(p[0], hs); p[1] = __hmul2(p[1], hs);
        p[2] = __hmul2(p[2], hs); p[3] = __hmul2(p[3], hs);
        if (r < 64) *(uint4*)&Ks[0][r][c8]      = q4;
        else        *(uint4*)&Vs[0][r - 64][c8] = q4;
    }
    __syncthreads();

    uint32_t qf[4][4];
    {
        const __half (*Qs)[72] = (wid < 4) ? Ks[0] : Vs[0];
        const int qr = (wid * 16) % 64 + g;
#pragma unroll
        for (int s = 0; s < 4; s++) {
            qf[s][0] = *(const uint32_t*)&Qs[qr][s * 16 + 2 * t];
            qf[s][1] = *(const uint32_t*)&Qs[qr + 8][s * 16 + 2 * t];
            qf[s][2] = *(const uint32_t*)&Qs[qr][s * 16 + 2 * t + 8];
            qf[s][3] = *(const uint32_t*)&Qs[qr + 8][s * 16 + 2 * t + 8];
        }
    }
    __syncthreads();

    const int kv_r = tid >> 3;
    const int kv_c = (tid & 7) * 8;

    auto load_kv = [&](int kt, int st) {
#pragma unroll
        for (int j = 0; j < 2; j++) {
            const int r = kv_r + j * 32;
            const size_t off = (size_t)(kt * 64 + r) * QKVS + kv_c;
            cp_async16(sptr(&Ks[st][r][kv_c]), Kb + off);
            cp_async16(sptr(&Vs[st][r][kv_c]), Vb + off);
        }
    };

    load_kv(0, 0);
    cp_commit();

    float m0 = -1e30f, m1 = -1e30f, l0 = 0.f, l1 = 0.f;
    float O[8][4];
#pragma unroll
    for (int n = 0; n < 8; n++)
#pragma unroll
        for (int j = 0; j < 4; j++) O[n][j] = 0.f;

    const int lq0 = wid * 16 + g;
    const int qg0 = qb * 128 + lq0;
    const int qg1 = qg0 + 8;
    const int wmax = qb * 128 + wid * 16 + 15;

    const int nkt = 2 * qb + 2;
    for (int kt = 0; kt < nkt; kt++) {
        const int st = kt & 1;
        __syncthreads();
        if (kt + 1 < nkt) {
            load_kv(kt + 1, st ^ 1);
            cp_commit();
            cp_wait<1>();
        } else {
            cp_wait<0>();
        }
        __syncthreads();

        if (kt * 64 > wmax) continue;

        float S[8][4];
#pragma unroll
        for (int n = 0; n < 8; n++)
#pragma unroll
            for (int j = 0; j < 4; j++) S[n][j] = 0.f;

#pragma unroll
        for (int s = 0; s < 4; s++) {
#pragma unroll
            for (int n = 0; n < 8; n++) {
                uint32_t bq[2];
                bq[0] = *(const uint32_t*)&Ks[st][n * 8 + g][s * 16 + 2 * t];
                bq[1] = *(const uint32_t*)&Ks[st][n * 8 + g][s * 16 + 2 * t + 8];
                mma_f16(S[n], qf[s], bq);
            }
        }

        if (kt >= 2 * qb) {
#pragma unroll
            for (int n = 0; n < 8; n++) {
                const int kg = kt * 64 + n * 8 + 2 * t;
                if (kg     > qg0) S[n][0] = -1e30f;
                if (kg + 1 > qg0) S[n][1] = -1e30f;
                if (kg     > qg1) S[n][2] = -1e30f;
                if (kg + 1 > qg1) S[n][3] = -1e30f;
            }
        }

        float mx0 = -1e30f, mx1 = -1e30f;
#pragma unroll
        for (int n = 0; n < 8; n++) {
            mx0 = fmaxf(mx0, fmaxf(S[n][0], S[n][1]));
            mx1 = fmaxf(mx1, fmaxf(S[n][2], S[n][3]));
        }
        mx0 = fmaxf(mx0, __shfl_xor_sync(0xffffffffu, mx0, 1));
        mx0 = fmaxf(mx0, __shfl_xor_sync(0xffffffffu, mx0, 2));
        mx1 = fmaxf(mx1, __shfl_xor_sync(0xffffffffu, mx1, 1));
        mx1 = fmaxf(mx1, __shfl_xor_sync(0xffffffffu, mx1, 2));

        const float mn0 = fmaxf(m0, mx0), mn1 = fmaxf(m1, mx1);
        const float fac0 = __expf(m0 - mn0), fac1 = __expf(m1 - mn1);

        float s0 = 0.f, s1 = 0.f;
#pragma unroll
        for (int n = 0; n < 8; n++) {
            S[n][0] = __expf(S[n][0] - mn0);
            S[n][1] = __expf(S[n][1] - mn0);
            S[n][2] = __expf(S[n][2] - mn1);
            S[n][3] = __expf(S[n][3] - mn1);
            s0 += S[n][0] + S[n][1];
            s1 += S[n][2] + S[n][3];
        }
        s0 += __shfl_xor_sync(0xffffffffu, s0, 1);
        s0 += __shfl_xor_sync(0xffffffffu, s0, 2);
        s1 += __shfl_xor_sync(0xffffffffu, s1, 1);
        s1 += __shfl_xor_sync(0xffffffffu, s1, 2);

        l0 = l0 * fac0 + s0;
        l1 = l1 * fac1 + s1;
        m0 = mn0; m1 = mn1;

#pragma unroll
        for (int n = 0; n < 8; n++) {
            O[n][0] *= fac0; O[n][1] *= fac0;
            O[n][2] *= fac1; O[n][3] *= fac1;
        }

#pragma unroll
        for (int kk = 0; kk < 4; kk++) {
            uint32_t pa[4];
            pa[0] = packh2(S[2 * kk][0],     S[2 * kk][1]);
            pa[1] = packh2(S[2 * kk][2],     S[2 * kk][3]);
            pa[2] = packh2(S[2 * kk + 1][0], S[2 * kk + 1][1]);
            pa[3] = packh2(S[2 * kk + 1][2], S[2 * kk + 1][3]);
#pragma unroll
            for (int nd = 0; nd < 8; nd++) {
                uint32_t bv[2];
                ldsm_x2t(bv, sptr(&Vs[st][kk * 16 + lrow][nd * 8]));
                mma_f16(O[nd], pa, bv);
            }
        }
    }

    const float inv0 = 1.f / l0, inv1 = 1.f / l1;
    __half* o0 = Og + (size_t)(b * Ss + qb * 128 + lq0) * Dd + h * HDd;
    __half* o1 = o0 + 8 * Dd;
#pragma unroll
    for (int nd = 0; nd < 8; nd++) {
        const int c0 = nd * 8 + 2 * t;
        *(__half2*)&o0[c0] = __floats2half2_rn(O[nd][0] * inv0, O[nd][1] * inv0);
        *(__half2*)&o1[c0] = __floats2half2_rn(O[nd][2] * inv1, O[nd][3] * inv1);
    }
}

// ---------------- residual add + LayerNorm (optional fp16 mirror) ----------------
template <int DUAL>
__global__ __launch_bounds__(256)
void add_ln_kernel(const float* __restrict__ a, const float* __restrict__ r,
                   const float* __restrict__ gamma, const float* __restrict__ beta,
                   float* __restrict__ out, __half* __restrict__ outh)
{
    const int t = blockIdx.x;
    const int tid = threadIdx.x;
    __shared__ float buf[Dd];
    __shared__ float red[20];

    float s = 0.f, sq = 0.f;
    for (int i = tid; i < Dd; i += 256) {
        float v = a[(size_t)t * Dd + i] + r[(size_t)t * Dd + i];
        buf[i] = v;
        s += v; sq += v * v;
    }
#pragma unroll
    for (int o = 16; o; o >>= 1) {
        s  += __shfl_xor_sync(0xffffffffu, s, o);
        sq += __shfl_xor_sync(0xffffffffu, sq, o);
    }
    if ((tid & 31) == 0) { red[tid >> 5] = s; red[8 + (tid >> 5)] = sq; }
    __syncthreads();
    if (tid == 0) {
        float ts = 0.f, tq = 0.f;
        for (int i = 0; i < 8; i++) { ts += red[i]; tq += red[8 + i]; }
        const float mu  = ts * (1.0f / Dd);
        const float var = tq * (1.0f / Dd) - mu * mu;
        red[16] = mu;
        red[17] = rsqrtf(var + 1e-6f);
    }
    __syncthreads();
    const float mu = red[16], rstd = red[17];
    for (int i = tid; i < Dd; i += 256) {
        const float v = (buf[i] - mu) * rstd * gamma[i] + beta[i];
        out[(size_t)t * Dd + i] = v;
        if (DUAL) outh[(size_t)t * Dd + i] = __float2half_rn(v);
    }
}

// ---------------- launch ----------------
extern "C" void kernel_launch(void* const* d_in, const int* in_sizes, int n_in,
                              void* d_out, int out_size)
{
    const float* x   = (const float*)d_in[0];
    const float* Wq  = (const float*)d_in[1];
    const float* bq  = (const float*)d_in[2];
    const float* Wk  = (const float*)d_in[3];
    const float* bk  = (const float*)d_in[4];
    const float* Wv  = (const float*)d_in[5];
    const float* bv  = (const float*)d_in[6];
    const float* Wo  = (const float*)d_in[7];
    const float* bo  = (const float*)d_in[8];
    const float* g1  = (const float*)d_in[9];
    const float* b1  = (const float*)d_in[10];
    const float* Wup = (const float*)d_in[11];
    const float* bup = (const float*)d_in[12];
    const float* Wdn = (const float*)d_in[13];
    const float* bdn = (const float*)d_in[14];
    const float* g2  = (const float*)d_in[15];
    const float* b2  = (const float*)d_in[16];
    float* out = (float*)d_out;

    float *proj, *x1, *bqkv;
    __half *xh, *wqkvh, *woh, *wuph, *wdnh;
    __half *qkvh, *midh, *x1h, *uph;
    cudaGetSymbolAddress((void**)&proj,  g_proj);
    cudaGetSymbolAddress((void**)&x1,    g_x1);
    cudaGetSymbolAddress((void**)&bqkv,  g_bqkv);
    cudaGetSymbolAddress((void**)&xh,    g_xh);
    cudaGetSymbolAddress((void**)&wqkvh, g_wqkvh);
    cudaGetSymbolAddress((void**)&woh,   g_woh);
    cudaGetSymbolAddress((void**)&wuph,  g_wuph);
    cudaGetSymbolAddress((void**)&wdnh,  g_wdnh);
    cudaGetSymbolAddress((void**)&qkvh,  g_qkvh);
    cudaGetSymbolAddress((void**)&midh,  g_midh);
    cudaGetSymbolAddress((void**)&x1h,   g_x1h);
    cudaGetSymbolAddress((void**)&uph,   g_uph);

    const dim3 blk(256);
    const int SMEM = 65536;

    // opt-in to 64KB dynamic smem (idempotent; not an allocation)
    cudaFuncSetAttribute(gemm_h<0, 1>, cudaFuncAttributeMaxDynamicSharedMemorySize, SMEM);
    cudaFuncSetAttribute(gemm_h<0, 0>, cudaFuncAttributeMaxDynamicSharedMemorySize, SMEM);
    cudaFuncSetAttribute(gemm_h<1, 1>, cudaFuncAttributeMaxDynamicSharedMemorySize, SMEM);

    f2h_qkv<<<3 * (Dd * Dd / 4) / 256, blk>>>(Wq, Wk, Wv, wqkvh);
    {
        const int chunks = (Tt * Dd + Dd * Dd + Dd * DFF + DFF * Dd) / 4;
        f2h_misc<<<chunks / 256, blk>>>(x, Wo, Wup, Wdn, xh, woh, wuph, wdnh);
    }
    bias_concat_kernel<<<QKVS / 256, blk>>>(bq, bk, bv, bqkv);

    gemm_h<0, 1><<<dim3(QKVS / 128, Tt / 128), blk, SMEM>>>(xh, wqkvh, bqkv, qkvh, Tt, QKVS, Dd);

    attn_f16<<<dim3(Ss / 128, Bt * Hh), blk>>>(qkvh, midh);

    gemm_h<0, 0><<<dim3(Dd / 128, Tt / 128), blk, SMEM>>>(midh, woh, bo, proj, Tt, Dd, Dd);
    add_ln_kernel<1><<<Tt, blk>>>(x, proj, g1, b1, x1, x1h);

    gemm_h<1, 1><<<dim3(DFF / 128, Tt / 128), blk, SMEM>>>(x1h, wuph, bup, uph, Tt, DFF, Dd);
    gemm_h<0, 0><<<dim3(Dd / 128, Tt / 128), blk, SMEM>>>(uph, wdnh, bdn, proj, Tt, Dd, DFF);
    add_ln_kernel<0><<<Tt, blk>>>(x1, proj, g2, b2, out, nullptr);
}